// round 5
// baseline (speedup 1.0000x reference)
#include <cuda_runtime.h>
#include <math.h>

// Problem constants
#define BATCH 16
#define SEQ   1024
#define NTOK  (BATCH*SEQ)        // 16384
#define DMODEL 512
#define NHEAD  4
#define HDIM   128
#define DMLP   1024
#define NBH    (BATCH*NHEAD)     // 64

#define BM 128
#define BN 128
#define BK 16
#define APITCH 20                // [m][k] pitch: conflict-free frag loads
#define BPITCH 136               // [k][n] pitch: conflict-free frag loads

// flash kernel smem pitches
#define QP 132
#define KP 132
#define VP 136
#define PP 68
// smem float offsets
#define FS_Q   0
#define FS_K   16896              // 128*132
#define FS_V   25344              // + 64*132
#define FS_P   34048              // + 64*136
#define FS_R1  42752              // + 128*68
#define FS_R2  43264
#define FS_TOT 43776
#define FLASH_SMEM (FS_TOT*4)     // 175104 bytes

// -------- scratch (no cudaMalloc allowed) --------
__device__ float g_x1n[NTOK*DMODEL];
__device__ float g_x2n[NTOK*DMODEL];
__device__ float g_q  [NTOK*DMODEL];
__device__ float g_qkv[NTOK*3*DMODEL];     // fused qkv / kv projections
__device__ float g_ctx[NTOK*DMODEL];
__device__ float g_src1[NTOK*DMODEL];
__device__ float g_src2[NTOK*DMODEL];
__device__ float g_x  [NTOK*DMODEL];
__device__ float g_h1 [NTOK*DMLP];
// rounded weights (concatenated): s1 qkv 512x1536, s2 qkv 512x1536,
// cross q 512x512, cross kv 512x1024, Wo 512x512, W1 512x1024, W2 1024x512
__device__ float g_w  [3670016];
__device__ float g_bc [4096];              // bias concats: s1(1536), s2(1536), ckv(1024)

// fp32 -> tf32 (round to nearest) kept in float container
__device__ __forceinline__ float tf32r(float x) {
    unsigned r;
    asm("cvt.rna.tf32.f32 %0, %1;" : "=r"(r) : "f"(x));
    return __uint_as_float(r);
}

// ============================================================
// Round-copy kernels (weights -> tf32-valued fp32 scratch)
// ============================================================
__global__ void round_copy(const float* __restrict__ in, float* __restrict__ out, int n) {
    int i = (blockIdx.x * 256 + threadIdx.x) * 4;
    if (i < n) {
        float4 v = *(const float4*)&in[i];
        v.x = tf32r(v.x); v.y = tf32r(v.y); v.z = tf32r(v.z); v.w = tf32r(v.w);
        *(float4*)&out[i] = v;
    }
}

// strided: out[r*ldo + c] = round(in[r*ncols + c])  (for weight concat)
__global__ void round_copy_strided(const float* __restrict__ in, float* __restrict__ out,
                                   int total, int ncols, int ldo) {
    int i = (blockIdx.x * 256 + threadIdx.x) * 4;
    if (i < total) {
        int r = i / ncols, c = i % ncols;
        float4 v = *(const float4*)&in[i];
        v.x = tf32r(v.x); v.y = tf32r(v.y); v.z = tf32r(v.z); v.w = tf32r(v.w);
        *(float4*)&out[(size_t)r * ldo + c] = v;
    }
}

// ============================================================
// LayerNorm: one block per token row (D=512), 256 threads.
// Output is tf32-rounded (it only feeds GEMMs).
// ============================================================
__global__ void ln_kernel(const float* __restrict__ x,
                          const float* __restrict__ g,
                          const float* __restrict__ b,
                          float* __restrict__ out) {
    int row = blockIdx.x;
    const float* xr = x + (size_t)row * DMODEL;
    float* orow = out + (size_t)row * DMODEL;
    int tid = threadIdx.x;
    float v0 = xr[tid], v1 = xr[tid + 256];

    __shared__ float sm[8];
    float s = v0 + v1;
    #pragma unroll
    for (int o = 16; o; o >>= 1) s += __shfl_xor_sync(0xffffffffu, s, o);
    if ((tid & 31) == 0) sm[tid >> 5] = s;
    __syncthreads();
    if (tid == 0) {
        float t = 0.f;
        #pragma unroll
        for (int i = 0; i < 8; i++) t += sm[i];
        sm[0] = t * (1.0f / DMODEL);
    }
    __syncthreads();
    float mean = sm[0];
    __syncthreads();

    float d0 = v0 - mean, d1 = v1 - mean;
    float q = d0 * d0 + d1 * d1;
    #pragma unroll
    for (int o = 16; o; o >>= 1) q += __shfl_xor_sync(0xffffffffu, q, o);
    if ((tid & 31) == 0) sm[tid >> 5] = q;
    __syncthreads();
    if (tid == 0) {
        float t = 0.f;
        #pragma unroll
        for (int i = 0; i < 8; i++) t += sm[i];
        sm[0] = rsqrtf(t * (1.0f / DMODEL) + 1e-6f);
    }
    __syncthreads();
    float rstd = sm[0];

    orow[tid]       = tf32r(d0 * rstd * g[tid]       + b[tid]);
    orow[tid + 256] = tf32r(d1 * rstd * g[tid + 256] + b[tid + 256]);
}

// ============================================================
// TF32 tensor-core GEMM (dense projections). Operands pre-rounded.
// 128x128x16 tiles, 8 warps (2x4), warp tile 64x32, mma.m16n8k8.
// ============================================================
__global__ void __launch_bounds__(256, 2)
gemm_tc(const float* __restrict__ A, const float* __restrict__ B,
        const float* __restrict__ bias, const float* __restrict__ add,
        float* __restrict__ C,
        int M, int N, int K,
        int lda, int ldb, int ldc,
        int act, float cscale, int round_out)
{
    __shared__ float As[2][BM * APITCH];
    __shared__ float Bs[2][BK * BPITCH];

    int bm = blockIdx.y * BM, bn = blockIdx.x * BN;
    int tid = threadIdx.x;
    int warp = tid >> 5, lane = tid & 31;
    int wm = warp >> 2, wn = warp & 3;
    int gid = lane >> 2, tig = lane & 3;

    int arow = tid >> 1, acol = (tid & 1) * 8;
    const float* Aptr = A + (size_t)(bm + arow) * lda + acol;
    int asw = arow * APITCH + acol;

    int brow = tid >> 4, bcol = (tid & 15) * 8;
    const float* Bptr = B + (size_t)brow * ldb + bn + bcol;
    int bsw = brow * BPITCH + bcol;

    float4 a0 = *(const float4*)(Aptr);
    float4 a1 = *(const float4*)(Aptr + 4);
    float4 b0 = *(const float4*)(Bptr);
    float4 b1 = *(const float4*)(Bptr + 4);

    *(float4*)&As[0][asw]     = a0;
    *(float4*)&As[0][asw + 4] = a1;
    *(float4*)&Bs[0][bsw]     = b0;
    *(float4*)&Bs[0][bsw + 4] = b1;
    __syncthreads();

    float acc[4][4][4];
    #pragma unroll
    for (int i = 0; i < 4; i++)
        #pragma unroll
        for (int j = 0; j < 4; j++)
            #pragma unroll
            for (int c = 0; c < 4; c++) acc[i][j][c] = 0.f;

    int nk = K / BK;
    int buf = 0;
    for (int kt = 0; kt < nk; kt++) {
        if (kt + 1 < nk) {
            Aptr += BK;
            a0 = *(const float4*)(Aptr);
            a1 = *(const float4*)(Aptr + 4);
            Bptr += (size_t)BK * ldb;
            b0 = *(const float4*)(Bptr);
            b1 = *(const float4*)(Bptr + 4);
        }
        #pragma unroll
        for (int ks = 0; ks < 2; ks++) {
            int k0 = ks * 8;
            unsigned af[4][4], bf[4][2];
            #pragma unroll
            for (int ma = 0; ma < 4; ma++) {
                int mb = (wm * 64 + ma * 16 + gid) * APITCH + k0 + tig;
                af[ma][0] = __float_as_uint(As[buf][mb]);
                af[ma][1] = __float_as_uint(As[buf][mb + 8 * APITCH]);
                af[ma][2] = __float_as_uint(As[buf][mb + 4]);
                af[ma][3] = __float_as_uint(As[buf][mb + 8 * APITCH + 4]);
            }
            #pragma unroll
            for (int nb = 0; nb < 4; nb++) {
                int n0 = wn * 32 + nb * 8 + gid;
                int nbase = (k0 + tig) * BPITCH + n0;
                bf[nb][0] = __float_as_uint(Bs[buf][nbase]);
                bf[nb][1] = __float_as_uint(Bs[buf][nbase + 4 * BPITCH]);
            }
            #pragma unroll
            for (int ma = 0; ma < 4; ma++)
                #pragma unroll
                for (int nb = 0; nb < 4; nb++) {
                    asm volatile(
                        "mma.sync.aligned.m16n8k8.row.col.f32.tf32.tf32.f32 "
                        "{%0,%1,%2,%3}, {%4,%5,%6,%7}, {%8,%9}, {%0,%1,%2,%3};\n"
                        : "+f"(acc[ma][nb][0]), "+f"(acc[ma][nb][1]),
                          "+f"(acc[ma][nb][2]), "+f"(acc[ma][nb][3])
                        : "r"(af[ma][0]), "r"(af[ma][1]), "r"(af[ma][2]), "r"(af[ma][3]),
                          "r"(bf[nb][0]), "r"(bf[nb][1]));
                }
        }
        if (kt + 1 < nk) {
            int nb2 = buf ^ 1;
            __syncthreads();
            *(float4*)&As[nb2][asw]     = a0;
            *(float4*)&As[nb2][asw + 4] = a1;
            *(float4*)&Bs[nb2][bsw]     = b0;
            *(float4*)&Bs[nb2][bsw + 4] = b1;
            __syncthreads();
            buf = nb2;
        }
    }

    #pragma unroll
    for (int ma = 0; ma < 4; ma++) {
        int r0 = bm + wm * 64 + ma * 16 + gid;
        #pragma unroll
        for (int nb = 0; nb < 4; nb++) {
            int c = bn + wn * 32 + nb * 8 + tig * 2;
            float bv0 = bias ? bias[c] : 0.f;
            float bv1 = bias ? bias[c + 1] : 0.f;
            #pragma unroll
            for (int half = 0; half < 2; half++) {
                int r = r0 + half * 8;
                float t0 = acc[ma][nb][half * 2 + 0] * cscale + bv0;
                float t1 = acc[ma][nb][half * 2 + 1] * cscale + bv1;
                if (act) {
                    t0 = 0.5f * t0 * (1.0f + erff(t0 * 0.70710678118654752f));
                    t1 = 0.5f * t1 * (1.0f + erff(t1 * 0.70710678118654752f));
                }
                size_t off = (size_t)r * ldc + c;
                if (add) { t0 += add[off]; t1 += add[off + 1]; }
                if (round_out) { t0 = tf32r(t0); t1 = tf32r(t1); }
                *(float2*)&C[off] = make_float2(t0, t1);
            }
        }
    }
}

// ============================================================
// Flash attention: per CTA 128 Q rows of one (b,h); stream KV in
// chunks of 64 with online softmax. tf32 mma for S=QK^T and O=PV.
// Inputs Q/K/V already tf32-rounded by their producers.
// Output ctx tf32-rounded (feeds Wo GEMM).
// ============================================================
extern __shared__ float fs[];

__global__ void __launch_bounds__(256)
flash_kernel(const float* __restrict__ Qm, int qld,
             const float* __restrict__ Km, const float* __restrict__ Vm, int kvld,
             float* __restrict__ Om)
{
    float* sQ = fs + FS_Q;
    float* sK = fs + FS_K;
    float* sV = fs + FS_V;
    float* sP = fs + FS_P;
    float* sR1 = fs + FS_R1;
    float* sR2 = fs + FS_R2;

    int tid = threadIdx.x;
    int warp = tid >> 5, lane = tid & 31;
    int wm = warp >> 2, wn = warp & 3;
    int gid = lane >> 2, tig = lane & 3;

    int bh = blockIdx.y, b = bh >> 2, h = bh & 3;
    int q0 = blockIdx.x * 128, base = b * SEQ;
    int hoff = h * HDIM;

    // load Q tile 128x128
    {
        int r = tid >> 1, c0 = (tid & 1) * 64;
        const float* src = Qm + (size_t)(base + q0 + r) * qld + hoff + c0;
        float* dst = sQ + r * QP + c0;
        #pragma unroll
        for (int i = 0; i < 16; i++) *(float4*)(dst + 4 * i) = *(const float4*)(src + 4 * i);
    }

    float oacc[4][4][4];
    #pragma unroll
    for (int i = 0; i < 4; i++)
        #pragma unroll
        for (int j = 0; j < 4; j++)
            #pragma unroll
            for (int c = 0; c < 4; c++) oacc[i][j][c] = 0.f;
    float mrow[4][2], lrow[4][2];
    #pragma unroll
    for (int i = 0; i < 4; i++) { mrow[i][0] = -1e30f; mrow[i][1] = -1e30f;
                                  lrow[i][0] = 0.f;    lrow[i][1] = 0.f; }

    const float scale = 0.08838834764831845f;  // 1/sqrt(128)

    for (int ch = 0; ch < SEQ / 64; ch++) {
        int kv0 = ch * 64;
        __syncthreads();   // prev-iter consumers done (and Q staged on ch==0)
        // load K,V chunk (64 x 128 each)
        {
            int r = tid >> 2, c0 = (tid & 3) * 32;
            const float* ksrc = Km + (size_t)(base + kv0 + r) * kvld + hoff + c0;
            const float* vsrc = Vm + (size_t)(base + kv0 + r) * kvld + hoff + c0;
            float* kd = sK + r * KP + c0;
            float* vd = sV + r * VP + c0;
            #pragma unroll
            for (int i = 0; i < 8; i++) *(float4*)(kd + 4 * i) = *(const float4*)(ksrc + 4 * i);
            #pragma unroll
            for (int i = 0; i < 8; i++) *(float4*)(vd + 4 * i) = *(const float4*)(vsrc + 4 * i);
        }
        __syncthreads();

        // S = Q @ K^T : warp tile 64x16 (ma 4, nb 2), k over 128
        float s[4][2][4];
        #pragma unroll
        for (int i = 0; i < 4; i++)
            #pragma unroll
            for (int j = 0; j < 2; j++)
                #pragma unroll
                for (int c = 0; c < 4; c++) s[i][j][c] = 0.f;

        #pragma unroll
        for (int k8 = 0; k8 < 16; k8++) {
            int k0 = k8 * 8;
            unsigned af[4][4], bf[2][2];
            #pragma unroll
            for (int ma = 0; ma < 4; ma++) {
                int mb = (wm * 64 + ma * 16 + gid) * QP + k0 + tig;
                af[ma][0] = __float_as_uint(sQ[mb]);
                af[ma][1] = __float_as_uint(sQ[mb + 8 * QP]);
                af[ma][2] = __float_as_uint(sQ[mb + 4]);
                af[ma][3] = __float_as_uint(sQ[mb + 8 * QP + 4]);
            }
            #pragma unroll
            for (int nb = 0; nb < 2; nb++) {
                int nbase = (wn * 16 + nb * 8 + gid) * KP + k0 + tig;
                bf[nb][0] = __float_as_uint(sK[nbase]);
                bf[nb][1] = __float_as_uint(sK[nbase + 4]);
            }
            #pragma unroll
            for (int ma = 0; ma < 4; ma++)
                #pragma unroll
                for (int nb = 0; nb < 2; nb++) {
                    asm volatile(
                        "mma.sync.aligned.m16n8k8.row.col.f32.tf32.tf32.f32 "
                        "{%0,%1,%2,%3}, {%4,%5,%6,%7}, {%8,%9}, {%0,%1,%2,%3};\n"
                        : "+f"(s[ma][nb][0]), "+f"(s[ma][nb][1]),
                          "+f"(s[ma][nb][2]), "+f"(s[ma][nb][3])
                        : "r"(af[ma][0]), "r"(af[ma][1]), "r"(af[ma][2]), "r"(af[ma][3]),
                          "r"(bf[nb][0]), "r"(bf[nb][1]));
                }
        }

        // online softmax: pass 1 — per-row slice max, cross-warp via sR1
        #pragma unroll
        for (int ma = 0; ma < 4; ma++)
            #pragma unroll
            for (int hf = 0; hf < 2; hf++) {
                float mx = fmaxf(fmaxf(s[ma][0][hf*2] , s[ma][0][hf*2+1]),
                                 fmaxf(s[ma][1][hf*2] , s[ma][1][hf*2+1])) * scale;
                mx = fmaxf(mx, __shfl_xor_sync(0xffffffffu, mx, 1));
                mx = fmaxf(mx, __shfl_xor_sync(0xffffffffu, mx, 2));
                if (tig == 0) sR1[(wm*64 + ma*16 + hf*8 + gid) * 4 + wn] = mx;
            }
        __syncthreads();

        // pass 2 — new max, exp, slice sums, rescale O, store P
        #pragma unroll
        for (int ma = 0; ma < 4; ma++)
            #pragma unroll
            for (int hf = 0; hf < 2; hf++) {
                int r = wm*64 + ma*16 + hf*8 + gid;
                float cm = fmaxf(fmaxf(sR1[r*4+0], sR1[r*4+1]),
                                 fmaxf(sR1[r*4+2], sR1[r*4+3]));
                float nm = fmaxf(mrow[ma][hf], cm);
                float alpha = __expf(mrow[ma][hf] - nm);
                mrow[ma][hf] = nm;
                float p0 = __expf(s[ma][0][hf*2]   * scale - nm);
                float p1 = __expf(s[ma][0][hf*2+1] * scale - nm);
                float p2 = __expf(s[ma][1][hf*2]   * scale - nm);
                float p3 = __expf(s[ma][1][hf*2+1] * scale - nm);
                float sum = p0 + p1 + p2 + p3;
                sum += __shfl_xor_sync(0xffffffffu, sum, 1);
                sum += __shfl_xor_sync(0xffffffffu, sum, 2);
                if (tig == 0) sR2[r*4 + wn] = sum;
                lrow[ma][hf] *= alpha;
                #pragma unroll
                for (int nb = 0; nb < 4; nb++) {
                    oacc[ma][nb][hf*2]   *= alpha;
                    oacc[ma][nb][hf*2+1] *= alpha;
                }
                *(float2*)&sP[r*PP + wn*16 + tig*2]     = make_float2(tf32r(p0), tf32r(p1));
                *(float2*)&sP[r*PP + wn*16 + 8 + tig*2] = make_float2(tf32r(p2), tf32r(p3));
            }
        __syncthreads();   // P + sR2 visible

        #pragma unroll
        for (int ma = 0; ma < 4; ma++)
            #pragma unroll
            for (int hf = 0; hf < 2; hf++) {
                int r = wm*64 + ma*16 + hf*8 + gid;
                lrow[ma][hf] += sR2[r*4+0] + sR2[r*4+1] + sR2[r*4+2] + sR2[r*4+3];
            }

        // O += P @ V : warp tile 64x32 (ma 4, nb 4), k over 64
        #pragma unroll
        for (int k8 = 0; k8 < 8; k8++) {
            int k0 = k8 * 8;
            unsigned ap[4][4], bv[4][2];
            #pragma unroll
            for (int ma = 0; ma < 4; ma++) {
                int mb = (wm * 64 + ma * 16 + gid) * PP + k0 + tig;
                ap[ma][0] = __float_as_uint(sP[mb]);
                ap[ma][1] = __float_as_uint(sP[mb + 8 * PP]);
                ap[ma][2] = __float_as_uint(sP[mb + 4]);
                ap[ma][3] = __float_as_uint(sP[mb + 8 * PP + 4]);
            }
            #pragma unroll
            for (int nb = 0; nb < 4; nb++) {
                int n0 = wn * 32 + nb * 8 + gid;
                bv[nb][0] = __float_as_uint(sV[(k0 + tig) * VP + n0]);
                bv[nb][1] = __float_as_uint(sV[(k0 + tig + 4) * VP + n0]);
            }
            #pragma unroll
            for (int ma = 0; ma < 4; ma++)
                #pragma unroll
                for (int nb = 0; nb < 4; nb++) {
                    asm volatile(
                        "mma.sync.aligned.m16n8k8.row.col.f32.tf32.tf32.f32 "
                        "{%0,%1,%2,%3}, {%4,%5,%6,%7}, {%8,%9}, {%0,%1,%2,%3};\n"
                        : "+f"(oacc[ma][nb][0]), "+f"(oacc[ma][nb][1]),
                          "+f"(oacc[ma][nb][2]), "+f"(oacc[ma][nb][3])
                        : "r"(ap[ma][0]), "r"(ap[ma][1]), "r"(ap[ma][2]), "r"(ap[ma][3]),
                          "r"(bv[nb][0]), "r"(bv[nb][1]));
                }
        }
    }

    // epilogue: divide by l, round, store ctx
    #pragma unroll
    for (int ma = 0; ma < 4; ma++)
        #pragma unroll
        for (int hf = 0; hf < 2; hf++) {
            float inv = 1.0f / lrow[ma][hf];
            int gr = base + q0 + wm*64 + ma*16 + hf*8 + gid;
            #pragma unroll
            for (int nb = 0; nb < 4; nb++) {
                int c = hoff + wn*32 + nb*8 + tig*2;
                float t0 = tf32r(oacc[ma][nb][hf*2]   * inv);
                float t1 = tf32r(oacc[ma][nb][hf*2+1] * inv);
                *(float2*)&Om[(size_t)gr * DMODEL + c] = make_float2(t0, t1);
            }
        }
}

// ============================================================
// Host orchestration
// ============================================================
static inline void run_proj(const float* A, const float* W, const float* bias,
                            const float* add, float* C, int M, int Nc, int K,
                            int act, int round_out) {
    dim3 grid(Nc / BN, M / BM, 1);
    gemm_tc<<<grid, 256>>>(A, W, bias, add, C, M, Nc, K,
                           K, Nc, Nc, act, 1.0f, round_out);
}

static inline void run_flash(const float* Qm, int qld,
                             const float* Km, const float* Vm, int kvld,
                             float* Om) {
    cudaFuncSetAttribute(flash_kernel, cudaFuncAttributeMaxDynamicSharedMemorySize, FLASH_SMEM);
    dim3 grid(SEQ / 128, NBH);
    flash_kernel<<<grid, 256, FLASH_SMEM>>>(Qm, qld, Km, Vm, kvld, Om);
}

extern "C" void kernel_launch(void* const* d_in, const int* in_sizes, int n_in,
                              void* d_out, int out_size) {
    const float* x1    = (const float*)d_in[0];
    const float* x2    = (const float*)d_in[1];
    const float* ln1_g = (const float*)d_in[2];
    const float* ln1_b = (const float*)d_in[3];
    const float* ln2_g = (const float*)d_in[4];
    const float* ln2_b = (const float*)d_in[5];
    const float* lnf_g = (const float*)d_in[6];
    const float* lnf_b = (const float*)d_in[7];
    const float* Wq1 = (const float*)d_in[8],  *bq1 = (const float*)d_in[9];
    const float* Wk1 = (const float*)d_in[10], *bk1 = (const float*)d_in[11];
    const float* Wv1 = (const float*)d_in[12], *bv1 = (const float*)d_in[13];
    const float* Wq2 = (const float*)d_in[14], *bq2 = (const float*)d_in[15];
    const float* Wk2 = (const float*)d_in[16], *bk2 = (const float*)d_in[17];
    const float* Wv2 = (const float*)d_in[18], *bv2 = (const float*)d_in[19];
    const float* Wq12 = (const float*)d_in[20], *bq12 = (const float*)d_in[21];
    const float* Wk12 = (const float*)d_in[22], *bk12 = (const float*)d_in[23];
    const float* Wv12 = (const float*)d_in[24], *bv12 = (const float*)d_in[25];
    const float* Wo  = (const float*)d_in[26], *bo = (const float*)d_in[27];
    const float* W1  = (const float*)d_in[28], *b1 = (const float*)d_in[29];
    const float* W2  = (const float*)d_in[30], *b2 = (const float*)d_in[31];
    float* out = (float*)d_out;

    float *x1n, *x2n, *src1, *src2, *xres, *h1, *qs, *qkv, *ctxs, *wbuf, *bc;
    cudaGetSymbolAddress((void**)&x1n,  g_x1n);
    cudaGetSymbolAddress((void**)&x2n,  g_x2n);
    cudaGetSymbolAddress((void**)&src1, g_src1);
    cudaGetSymbolAddress((void**)&src2, g_src2);
    cudaGetSymbolAddress((void**)&xres, g_x);
    cudaGetSymbolAddress((void**)&h1,   g_h1);
    cudaGetSymbolAddress((void**)&qs,   g_q);
    cudaGetSymbolAddress((void**)&qkv,  g_qkv);
    cudaGetSymbolAddress((void**)&ctxs, g_ctx);
    cudaGetSymbolAddress((void**)&wbuf, g_w);
    cudaGetSymbolAddress((void**)&bc,   g_bc);
    float* xnorm = x1n;

    const int WSQ = DMODEL * DMODEL;      // 262144
    const int WML = DMODEL * DMLP;        // 524288
    // concatenated weight offsets in g_w
    float* wS1  = wbuf;                   // 512 x 1536
    float* wS2  = wbuf + 786432;          // 512 x 1536
    float* wCQ  = wbuf + 1572864;         // 512 x 512
    float* wCKV = wbuf + 1835008;         // 512 x 1024
    float* wWo  = wbuf + 2359296;
    float* wW1  = wbuf + 2621440;
    float* wW2  = wbuf + 3145728;

    // weight rounding / concat
    round_copy_strided<<<WSQ/1024, 256>>>(Wq1, wS1,         WSQ, DMODEL, 1536);
    round_copy_strided<<<WSQ/1024, 256>>>(Wk1, wS1 + 512,   WSQ, DMODEL, 1536);
    round_copy_strided<<<WSQ/1024, 256>>>(Wv1, wS1 + 1024,  WSQ, DMODEL, 1536);
    round_copy_strided<<<WSQ/1024, 256>>>(Wq2, wS2,         WSQ, DMODEL, 1536);
    round_copy_strided<<<WSQ/1024, 256>>>(Wk2, wS2 + 512,   WSQ, DMODEL, 1536);
    round_copy_strided<<<WSQ/1024, 256>>>(Wv2, wS2 + 1024,  WSQ, DMODEL, 1536);
    round_copy<<<WSQ/1024, 256>>>(Wq12, wCQ, WSQ);
    round_copy_strided<<<WSQ/1024, 256>>>(Wk12, wCKV,       WSQ, DMODEL, 1024);
    round_copy_strided<<<WSQ/1024, 256>>>(Wv12, wCKV + 512, WSQ, DMODEL, 1024);
    round_copy<<<WSQ/1024, 256>>>(Wo, wWo, WSQ);
    round_copy<<<WML/1024, 256>>>(W1, wW1, WML);
    round_copy<<<WML/1024, 256>>>(W2, wW2, WML);
    // bias concats (rounding harmless)
    float* bS1 = bc, *bS2 = bc + 1536, *bCKV = bc + 3072;
    round_copy<<<1, 256>>>(bq1, bS1,        DMODEL);
    round_copy<<<1, 256>>>(bk1, bS1 + 512,  DMODEL);
    round_copy<<<1, 256>>>(bv1, bS1 + 1024, DMODEL);
    round_copy<<<1, 256>>>(bq2, bS2,        DMODEL);
    round_copy<<<1, 256>>>(bk2, bS2 + 512,  DMODEL);
    round_copy<<<1, 256>>>(bv2, bS2 + 1024, DMODEL);
    round_copy<<<1, 256>>>(bk12, bCKV,       DMODEL);
    round_copy<<<1, 256>>>(bv12, bCKV + 512, DMODEL);

    // 1) pre-LN of both streams
    ln_kernel<<<NTOK, 256>>>(x1, ln1_g, ln1_b, x1n);
    ln_kernel<<<NTOK, 256>>>(x2, ln2_g, ln2_b, x2n);

    // 2) stream-1 self-attention
    run_proj(x1n, wS1, bS1, nullptr, qkv, NTOK, 1536, DMODEL, 0, 1);
    run_flash(qkv, 1536, qkv + 512, qkv + 1024, 1536, ctxs);
    run_proj(ctxs, wWo, bo, x1n, src1, NTOK, DMODEL, DMODEL, 0, 1);

    // 3) stream-2 self-attention
    run_proj(x2n, wS2, bS2, nullptr, qkv, NTOK, 1536, DMODEL, 0, 1);
    run_flash(qkv, 1536, qkv + 512, qkv + 1024, 1536, ctxs);
    run_proj(ctxs, wWo, bo, x2n, src2, NTOK, DMODEL, DMODEL, 0, 1);

    // 4) cross-attention: q from src1, k/v from src2; residual = x1
    run_proj(src1, wCQ, bq12, nullptr, qs, NTOK, DMODEL, DMODEL, 0, 1);
    run_proj(src2, wCKV, bCKV, nullptr, qkv, NTOK, 1024, DMODEL, 0, 1);
    run_flash(qs, DMODEL, qkv, qkv + 512, 1024, ctxs);
    run_proj(ctxs, wWo, bo, x1, xres, NTOK, DMODEL, DMODEL, 0, 0);

    // 5) final LN + MLP, residual onto xres
    ln_kernel<<<NTOK, 256>>>(xres, lnf_g, lnf_b, xnorm);
    run_proj(xnorm, wW1, b1, nullptr, h1, NTOK, DMLP, DMODEL, 1, 1);
    run_proj(h1, wW2, b2, xres, out, NTOK, DMODEL, DMLP, 0, 0);
    (void)in_sizes; (void)n_in; (void)out_size;
}

// round 7
// speedup vs baseline: 1.8990x; 1.8990x over previous
#include <cuda_runtime.h>
#include <cuda_bf16.h>
#include <math.h>
#include <stdint.h>

// Problem constants
#define BATCH 16
#define SEQ   1024
#define NTOK  (BATCH*SEQ)        // 16384
#define DMODEL 512
#define NHEAD  4
#define HDIM   128
#define DMLP   1024
#define NBH    (BATCH*NHEAD)     // 64

// -------- scratch (no cudaMalloc allowed). bf16 tensors stored as packed u32 pairs.
__device__ unsigned g_x1n[NTOK*256];
__device__ unsigned g_x2n[NTOK*256];
__device__ unsigned g_qv [NTOK*256];      // cross-attn Q
__device__ unsigned g_qkv[NTOK*768];      // fused qkv / kv projections
__device__ unsigned g_ctx[NTOK*256];
__device__ unsigned g_s1 [NTOK*256];
__device__ unsigned g_s2 [NTOK*256];
__device__ float    g_x  [NTOK*DMODEL];   // fp32 residual trunk
__device__ unsigned g_h1 [NTOK*512];
__device__ unsigned g_wb [1835008];       // transposed bf16 weights
__device__ float    g_bc [4096];          // fp32 bias concats

// ---------- helpers ----------
__device__ __forceinline__ unsigned packbf(float a, float b) {
    __nv_bfloat162 h = __floats2bfloat162_rn(a, b);
    return *reinterpret_cast<unsigned*>(&h);
}
__device__ __forceinline__ float2 unpackbf(unsigned u) {
    __nv_bfloat162 h = *reinterpret_cast<__nv_bfloat162*>(&u);
    return __bfloat1622float2(h);
}

#define MMA_BF16(acc, a, b) \
    asm volatile("mma.sync.aligned.m16n8k16.row.col.f32.bf16.bf16.f32 " \
        "{%0,%1,%2,%3}, {%4,%5,%6,%7}, {%8,%9}, {%0,%1,%2,%3};\n" \
        : "+f"((acc)[0]), "+f"((acc)[1]), "+f"((acc)[2]), "+f"((acc)[3]) \
        : "r"((a)[0]), "r"((a)[1]), "r"((a)[2]), "r"((a)[3]), "r"((b)[0]), "r"((b)[1]))

// ============================================================
// Weight prep: transpose fp32 [K,N] -> bf16 [N, K/2 u32]
// ============================================================
__global__ void wt_kernel(const float* __restrict__ in, unsigned* __restrict__ out,
                          int K, int N) {
    __shared__ float t[32][33];
    int k0 = blockIdx.x * 32, n0 = blockIdx.y * 32;
    int tx = threadIdx.x, ty = threadIdx.y;   // (32,8)
    #pragma unroll
    for (int i = 0; i < 4; i++)
        t[ty + i*8][tx] = in[(size_t)(k0 + ty + i*8) * N + n0 + tx];
    __syncthreads();
    #pragma unroll
    for (int i = 0; i < 2; i++) {
        int kp = ty + 8 * i;
        out[(size_t)(n0 + tx) * (K >> 1) + (k0 >> 1) + kp] =
            packbf(t[2*kp][tx], t[2*kp+1][tx]);
    }
}

struct Sq10 { const float* s[10]; unsigned* d[10]; };
__global__ void wt10_kernel(Sq10 p) {
    __shared__ float t[32][33];
    int m = blockIdx.z;
    const float* in = p.s[m];
    unsigned* out = p.d[m];
    int k0 = blockIdx.x * 32, n0 = blockIdx.y * 32;
    int tx = threadIdx.x, ty = threadIdx.y;
    #pragma unroll
    for (int i = 0; i < 4; i++)
        t[ty + i*8][tx] = in[(size_t)(k0 + ty + i*8) * 512 + n0 + tx];
    __syncthreads();
    #pragma unroll
    for (int i = 0; i < 2; i++) {
        int kp = ty + 8 * i;
        out[(size_t)(n0 + tx) * 256 + (k0 >> 1) + kp] =
            packbf(t[2*kp][tx], t[2*kp+1][tx]);
    }
}

struct B8 { const float* s[8]; };
__global__ void bias_concat(B8 p, float* __restrict__ dst) {
    int i = blockIdx.x * 256 + threadIdx.x;   // 4096
    dst[i] = p.s[i >> 9][i & 511];
}

// ============================================================
// LayerNorm: fp32 in, bf16 (packed) out. One block per row.
// ============================================================
__global__ void ln_kernel(const float* __restrict__ x,
                          const float* __restrict__ g,
                          const float* __restrict__ b,
                          unsigned* __restrict__ out) {
    int row = blockIdx.x;
    const float* xr = x + (size_t)row * DMODEL;
    unsigned* orow = out + (size_t)row * 256;
    int tid = threadIdx.x;
    float v0 = xr[2*tid], v1 = xr[2*tid + 1];

    __shared__ float sm[8];
    float s = v0 + v1;
    #pragma unroll
    for (int o = 16; o; o >>= 1) s += __shfl_xor_sync(0xffffffffu, s, o);
    if ((tid & 31) == 0) sm[tid >> 5] = s;
    __syncthreads();
    if (tid == 0) {
        float t = 0.f;
        #pragma unroll
        for (int i = 0; i < 8; i++) t += sm[i];
        sm[0] = t * (1.0f / DMODEL);
    }
    __syncthreads();
    float mean = sm[0];
    __syncthreads();

    float d0 = v0 - mean, d1 = v1 - mean;
    float q = d0 * d0 + d1 * d1;
    #pragma unroll
    for (int o = 16; o; o >>= 1) q += __shfl_xor_sync(0xffffffffu, q, o);
    if ((tid & 31) == 0) sm[tid >> 5] = q;
    __syncthreads();
    if (tid == 0) {
        float t = 0.f;
        #pragma unroll
        for (int i = 0; i < 8; i++) t += sm[i];
        sm[0] = rsqrtf(t * (1.0f / DMODEL) + 1e-6f);
    }
    __syncthreads();
    float rstd = sm[0];

    float y0 = d0 * rstd * g[2*tid]     + b[2*tid];
    float y1 = d1 * rstd * g[2*tid + 1] + b[2*tid + 1];
    orow[tid] = packbf(y0, y1);
}

// ============================================================
// bf16 tensor-core GEMM: C[M,N] = A[M,K] @ W[K,N], BT = W^T bf16 [N][K/2].
// 128x128x32 tiles, 8 warps (2x4), warp tile 64x32, mma.m16n8k16.
// Conflict-free packed-pair smem (pitch 20 u32). Reg-staged double buffer.
// Epilogue: +bias(fp32), gelu, +addf(fp32) or +addb(bf16); out fp32 and/or bf16.
// ============================================================
__global__ void __launch_bounds__(256, 2)
gemm_bf(const unsigned* __restrict__ A, const unsigned* __restrict__ BT,
        const float* __restrict__ bias,
        const float* __restrict__ addf, const unsigned* __restrict__ addb,
        float* __restrict__ Cf, unsigned* __restrict__ Cb,
        int N, int K, int act)
{
    __shared__ unsigned As[2][2560];   // 128 rows * pitch 20
    __shared__ unsigned Bs[2][2560];

    int bm = blockIdx.y * 128, bn = blockIdx.x * 128;
    int tid = threadIdx.x;
    int warp = tid >> 5, lane = tid & 31;
    int wm = warp >> 2, wn = warp & 3;
    int gid = lane >> 2, tig = lane & 3;
    int lda2 = K >> 1;

    int arow = tid >> 1, ug = (tid & 1) * 8;
    const unsigned* Ap = A + (size_t)(bm + arow) * lda2 + ug;
    const unsigned* Bp = BT + (size_t)(bn + arow) * lda2 + ug;
    int sw = arow * 20 + ug;

    uint4 a0 = *(const uint4*)Ap,       a1 = *(const uint4*)(Ap + 4);
    uint4 b0 = *(const uint4*)Bp,       b1 = *(const uint4*)(Bp + 4);
    *(uint4*)&As[0][sw] = a0; *(uint4*)&As[0][sw + 4] = a1;
    *(uint4*)&Bs[0][sw] = b0; *(uint4*)&Bs[0][sw + 4] = b1;
    __syncthreads();

    float acc[4][4][4];
    #pragma unroll
    for (int i = 0; i < 4; i++)
        #pragma unroll
        for (int j = 0; j < 4; j++)
            #pragma unroll
            for (int c = 0; c < 4; c++) acc[i][j][c] = 0.f;

    int nk = K >> 5;   // chunks of 32 K-elems = 16 u32
    int buf = 0;
    for (int kt = 0; kt < nk; kt++) {
        if (kt + 1 < nk) {
            Ap += 16; Bp += 16;
            a0 = *(const uint4*)Ap; a1 = *(const uint4*)(Ap + 4);
            b0 = *(const uint4*)Bp; b1 = *(const uint4*)(Bp + 4);
        }
        #pragma unroll
        for (int ks = 0; ks < 2; ks++) {
            int kb = ks * 8;
            unsigned af[4][4], bf2[4][2];
            #pragma unroll
            for (int ma = 0; ma < 4; ma++) {
                int mb = (wm * 64 + ma * 16 + gid) * 20 + kb + tig;
                af[ma][0] = As[buf][mb];
                af[ma][1] = As[buf][mb + 160];
                af[ma][2] = As[buf][mb + 4];
                af[ma][3] = As[buf][mb + 164];
            }
            #pragma unroll
            for (int nb = 0; nb < 4; nb++) {
                int nbase = (wn * 32 + nb * 8 + gid) * 20 + kb + tig;
                bf2[nb][0] = Bs[buf][nbase];
                bf2[nb][1] = Bs[buf][nbase + 4];
            }
            #pragma unroll
            for (int ma = 0; ma < 4; ma++)
                #pragma unroll
                for (int nb = 0; nb < 4; nb++)
                    MMA_BF16(acc[ma][nb], af[ma], bf2[nb]);
        }
        if (kt + 1 < nk) {
            int nb2 = buf ^ 1;
            __syncthreads();
            *(uint4*)&As[nb2][sw] = a0; *(uint4*)&As[nb2][sw + 4] = a1;
            *(uint4*)&Bs[nb2][sw] = b0; *(uint4*)&Bs[nb2][sw + 4] = b1;
            __syncthreads();
            buf = nb2;
        }
    }

    // epilogue
    #pragma unroll
    for (int ma = 0; ma < 4; ma++) {
        #pragma unroll
        for (int nb = 0; nb < 4; nb++) {
            int c = bn + wn * 32 + nb * 8 + tig * 2;
            float bv0 = bias ? bias[c] : 0.f;
            float bv1 = bias ? bias[c + 1] : 0.f;
            #pragma unroll
            for (int half = 0; half < 2; half++) {
                int r = bm + wm * 64 + ma * 16 + gid + half * 8;
                float t0 = acc[ma][nb][half * 2 + 0] + bv0;
                float t1 = acc[ma][nb][half * 2 + 1] + bv1;
                if (act) {
                    t0 = 0.5f * t0 * (1.0f + erff(t0 * 0.70710678118654752f));
                    t1 = 0.5f * t1 * (1.0f + erff(t1 * 0.70710678118654752f));
                }
                size_t off = (size_t)r * N + c;
                if (addf) { t0 += addf[off]; t1 += addf[off + 1]; }
                if (addb) {
                    float2 av = unpackbf(addb[(size_t)r * (N >> 1) + (c >> 1)]);
                    t0 += av.x; t1 += av.y;
                }
                if (Cf) *(float2*)&Cf[off] = make_float2(t0, t1);
                if (Cb) Cb[(size_t)r * (N >> 1) + (c >> 1)] = packbf(t0, t1);
            }
        }
    }
}

// ============================================================
// bf16 flash attention: 128 Q rows per CTA, KV chunks of 64,
// online softmax, bf16 m16n8k16 for S=QK^T and O=PV. 2 CTAs/SM.
// Pointers are u32 (bf16 pair) based; l*2 params are u32 strides.
// ============================================================
// smem u32 offsets
#define SQ_O 0        // 128 x 68
#define SK_O 8704     // 64 x 68
#define SV_O 13056    // 32 x 136 (token-pair packed)
#define SP_O 17408    // 128 x 36
#define R1_O 22016    // 512 floats
#define R2_O 22528    // 512 floats
#define FL_SMEM_BYTES (23040 * 4)

extern __shared__ unsigned fsu[];

__global__ void __launch_bounds__(256, 2)
flash_bf(const unsigned* __restrict__ Qm, int qld2,
         const unsigned* __restrict__ Km, const unsigned* __restrict__ Vm, int kvld2,
         unsigned* __restrict__ Om)
{
    float* sR1 = (float*)(fsu + R1_O);
    float* sR2 = (float*)(fsu + R2_O);

    int tid = threadIdx.x;
    int warp = tid >> 5, lane = tid & 31;
    int wm = warp >> 2, wn = warp & 3;
    int gid = lane >> 2, tig = lane & 3;

    int bh = blockIdx.y, b = bh >> 2, h = bh & 3;
    int q0 = blockIdx.x * 128, base = b * SEQ;
    int hoff2 = h * 64;   // u32 offset of head within row

    // load Q tile (128 x 64 u32), pitch 68
    {
        int r = tid >> 1, hq = tid & 1;
        const unsigned* src = Qm + (size_t)(base + q0 + r) * qld2 + hoff2 + hq * 32;
        unsigned* dst = fsu + SQ_O + r * 68 + hq * 32;
        #pragma unroll
        for (int i = 0; i < 8; i++) *(uint4*)(dst + 4*i) = *(const uint4*)(src + 4*i);
    }

    float oacc[4][4][4];
    #pragma unroll
    for (int i = 0; i < 4; i++)
        #pragma unroll
        for (int j = 0; j < 4; j++)
            #pragma unroll
            for (int c = 0; c < 4; c++) oacc[i][j][c] = 0.f;
    float mrow[4][2], lrow[4][2];
    #pragma unroll
    for (int i = 0; i < 4; i++) { mrow[i][0] = -1e30f; mrow[i][1] = -1e30f;
                                  lrow[i][0] = 0.f;    lrow[i][1] = 0.f; }

    const float scale = 0.08838834764831845f;   // 1/sqrt(128)

    for (int ch = 0; ch < SEQ / 64; ch++) {
        int kv0 = ch * 64;
        __syncthreads();   // prev-iter PV readers done with sK/sV/sP
        // K chunk: 64 rows x 64 u32, pitch 68
        {
            int r = tid >> 2, qo = (tid & 3) * 16;
            const unsigned* src = Km + (size_t)(base + kv0 + r) * kvld2 + hoff2 + qo;
            unsigned* dst = fsu + SK_O + r * 68 + qo;
            #pragma unroll
            for (int i = 0; i < 4; i++) *(uint4*)(dst + 4*i) = *(const uint4*)(src + 4*i);
        }
        // V chunk repacked token-pair-major: sVp[kp][d], pitch 136
        {
            int kp = tid >> 3, dg = (tid & 7) * 8;   // dg: u32 offset in source row
            const unsigned* v0p = Vm + (size_t)(base + kv0 + 2*kp) * kvld2 + hoff2 + dg;
            const unsigned* v1p = v0p + kvld2;
            unsigned lo[8], hi[8], o[16];
            *(uint4*)&lo[0] = *(const uint4*)v0p; *(uint4*)&lo[4] = *(const uint4*)(v0p + 4);
            *(uint4*)&hi[0] = *(const uint4*)v1p; *(uint4*)&hi[4] = *(const uint4*)(v1p + 4);
            #pragma unroll
            for (int i = 0; i < 8; i++) {
                o[2*i]   = __byte_perm(lo[i], hi[i], 0x5410);
                o[2*i+1] = __byte_perm(lo[i], hi[i], 0x7632);
            }
            unsigned* dst = fsu + SV_O + kp * 136 + dg * 2;
            #pragma unroll
            for (int i = 0; i < 4; i++) *(uint4*)(dst + 4*i) = *(uint4*)&o[4*i];
        }
        __syncthreads();

        // S = Q @ K^T : warp tile 64x16 (ma 4, nb 2), 8 k-steps of 16
        float s[4][2][4];
        #pragma unroll
        for (int i = 0; i < 4; i++)
            #pragma unroll
            for (int j = 0; j < 2; j++)
                #pragma unroll
                for (int c = 0; c < 4; c++) s[i][j][c] = 0.f;

        #pragma unroll
        for (int ks = 0; ks < 8; ks++) {
            int kb = ks * 8;
            unsigned af[4][4], bf2[2][2];
            #pragma unroll
            for (int ma = 0; ma < 4; ma++) {
                int mb = (wm * 64 + ma * 16 + gid) * 68 + kb + tig;
                af[ma][0] = fsu[SQ_O + mb];
                af[ma][1] = fsu[SQ_O + mb + 544];
                af[ma][2] = fsu[SQ_O + mb + 4];
                af[ma][3] = fsu[SQ_O + mb + 548];
            }
            #pragma unroll
            for (int nb = 0; nb < 2; nb++) {
                int nbase = (wn * 16 + nb * 8 + gid) * 68 + kb + tig;
                bf2[nb][0] = fsu[SK_O + nbase];
                bf2[nb][1] = fsu[SK_O + nbase + 4];
            }
            #pragma unroll
            for (int ma = 0; ma < 4; ma++)
                #pragma unroll
                for (int nb = 0; nb < 2; nb++)
                    MMA_BF16(s[ma][nb], af[ma], bf2[nb]);
        }

        // online softmax pass 1: per-warp row max -> sR1
        #pragma unroll
        for (int ma = 0; ma < 4; ma++)
            #pragma unroll
            for (int hf = 0; hf < 2; hf++) {
                float mx = fmaxf(fmaxf(s[ma][0][hf*2], s[ma][0][hf*2+1]),
                                 fmaxf(s[ma][1][hf*2], s[ma][1][hf*2+1])) * scale;
                mx = fmaxf(mx, __shfl_xor_sync(0xffffffffu, mx, 1));
                mx = fmaxf(mx, __shfl_xor_sync(0xffffffffu, mx, 2));
                if (tig == 0) sR1[(wm*64 + ma*16 + hf*8 + gid) * 4 + wn] = mx;
            }
        __syncthreads();

        // pass 2: global max, exp, sums, rescale O, pack P (bf16) to smem
        #pragma unroll
        for (int ma = 0; ma < 4; ma++)
            #pragma unroll
            for (int hf = 0; hf < 2; hf++) {
                int r = wm*64 + ma*16 + hf*8 + gid;
                float cm = fmaxf(fmaxf(sR1[r*4+0], sR1[r*4+1]),
                                 fmaxf(sR1[r*4+2], sR1[r*4+3]));
                float nm = fmaxf(mrow[ma][hf], cm);
                float alpha = __expf(mrow[ma][hf] - nm);
                mrow[ma][hf] = nm;
                float p0 = __expf(s[ma][0][hf*2]   * scale - nm);
                float p1 = __expf(s[ma][0][hf*2+1] * scale - nm);
                float p2 = __expf(s[ma][1][hf*2]   * scale - nm);
                float p3 = __expf(s[ma][1][hf*2+1] * scale - nm);
                float sum = p0 + p1 + p2 + p3;
                sum += __shfl_xor_sync(0xffffffffu, sum, 1);
                sum += __shfl_xor_sync(0xffffffffu, sum, 2);
                if (tig == 0) sR2[r*4 + wn] = sum;
                lrow[ma][hf] *= alpha;
                #pragma unroll
                for (int nb = 0; nb < 4; nb++) {
                    oacc[ma][nb][hf*2]   *= alpha;
                    oacc[ma][nb][hf*2+1] *= alpha;
                }
                fsu[SP_O + r*36 + wn*8 + tig]     = packbf(p0, p1);
                fsu[SP_O + r*36 + wn*8 + 4 + tig] = packbf(p2, p3);
            }
        __syncthreads();

        #pragma unroll
        for (int ma = 0; ma < 4; ma++)
            #pragma unroll
            for (int hf = 0; hf < 2; hf++) {
                int r = wm*64 + ma*16 + hf*8 + gid;
                lrow[ma][hf] += sR2[r*4+0] + sR2[r*4+1] + sR2[r*4+2] + sR2[r*4+3];
            }

        // O += P @ V : warp tile 64x32 (ma 4, nb 4), 4 k-steps of 16 tokens
        #pragma unroll
        for (int ks = 0; ks < 4; ks++) {
            int kb = ks * 8;
            unsigned ap[4][4], bv[4][2];
            #pragma unroll
            for (int ma = 0; ma < 4; ma++) {
                int pb = (wm * 64 + ma * 16 + gid) * 36 + kb + tig;
                ap[ma][0] = fsu[SP_O + pb];
                ap[ma][1] = fsu[SP_O + pb + 288];
                ap[ma][2] = fsu[SP_O + pb + 4];
                ap[ma][3] = fsu[SP_O + pb + 292];
            }
            #pragma unroll
            for (int nb = 0; nb < 4; nb++) {
                int n0 = wn * 32 + nb * 8 + gid;
                bv[nb][0] = fsu[SV_O + (kb + tig) * 136 + n0];
                bv[nb][1] = fsu[SV_O + (kb + tig + 4) * 136 + n0];
            }
            #pragma unroll
            for (int ma = 0; ma < 4; ma++)
                #pragma unroll
                for (int nb = 0; nb < 4; nb++)
                    MMA_BF16(oacc[ma][nb], ap[ma], bv[nb]);
        }
    }

    // epilogue: divide by l, pack bf16, store ctx [token][256 u32]
    #pragma unroll
    for (int ma = 0; ma < 4; ma++)
        #pragma unroll
        for (int hf = 0; hf < 2; hf++) {
            float inv = 1.0f / lrow[ma][hf];
            int gr = base + q0 + wm*64 + ma*16 + hf*8 + gid;
            #pragma unroll
            for (int nb = 0; nb < 4; nb++) {
                int cp = h*64 + wn*16 + nb*4 + tig;   // u32 col index
                Om[(size_t)gr * 256 + cp] =
                    packbf(oacc[ma][nb][hf*2] * inv, oacc[ma][nb][hf*2+1] * inv);
            }
        }
}

// ============================================================
// Host orchestration
// ============================================================
static inline void run_gemm(const unsigned* A, const unsigned* BT, const float* bias,
                            const float* addf, const unsigned* addb,
                            float* Cf, unsigned* Cb, int M, int N, int K, int act) {
    dim3 grid(N / 128, M / 128);
    gemm_bf<<<grid, 256>>>(A, BT, bias, addf, addb, Cf, Cb, N, K, act);
}

static inline void run_flash(const unsigned* Qm, int qld2,
                             const unsigned* Km, const unsigned* Vm, int kvld2,
                             unsigned* Om) {
    cudaFuncSetAttribute(flash_bf, cudaFuncAttributeMaxDynamicSharedMemorySize, FL_SMEM_BYTES);
    dim3 grid(SEQ / 128, NBH);
    flash_bf<<<grid, 256, FL_SMEM_BYTES>>>(Qm, qld2, Km, Vm, kvld2, Om);
}

extern "C" void kernel_launch(void* const* d_in, const int* in_sizes, int n_in,
                              void* d_out, int out_size) {
    const float* x1    = (const float*)d_in[0];
    const float* x2    = (const float*)d_in[1];
    const float* ln1_g = (const float*)d_in[2];
    const float* ln1_b = (const float*)d_in[3];
    const float* ln2_g = (const float*)d_in[4];
    const float* ln2_b = (const float*)d_in[5];
    const float* lnf_g = (const float*)d_in[6];
    const float* lnf_b = (const float*)d_in[7];
    const float* Wq1 = (const float*)d_in[8],  *bq1 = (const float*)d_in[9];
    const float* Wk1 = (const float*)d_in[10], *bk1 = (const float*)d_in[11];
    const float* Wv1 = (const float*)d_in[12], *bv1 = (const float*)d_in[13];
    const float* Wq2 = (const float*)d_in[14], *bq2 = (const float*)d_in[15];
    const float* Wk2 = (const float*)d_in[16], *bk2 = (const float*)d_in[17];
    const float* Wv2 = (const float*)d_in[18], *bv2 = (const float*)d_in[19];
    const float* Wq12 = (const float*)d_in[20], *bq12 = (const float*)d_in[21];
    const float* Wk12 = (const float*)d_in[22], *bk12 = (const float*)d_in[23];
    const float* Wv12 = (const float*)d_in[24], *bv12 = (const float*)d_in[25];
    const float* Wo  = (const float*)d_in[26], *bo = (const float*)d_in[27];
    const float* W1  = (const float*)d_in[28], *b1 = (const float*)d_in[29];
    const float* W2  = (const float*)d_in[30], *b2 = (const float*)d_in[31];
    float* out = (float*)d_out;

    unsigned *x1n, *x2n, *qv, *qkv, *ctx, *s1, *s2, *h1, *wb;
    float *xres, *bc;
    cudaGetSymbolAddress((void**)&x1n,  g_x1n);
    cudaGetSymbolAddress((void**)&x2n,  g_x2n);
    cudaGetSymbolAddress((void**)&qv,   g_qv);
    cudaGetSymbolAddress((void**)&qkv,  g_qkv);
    cudaGetSymbolAddress((void**)&ctx,  g_ctx);
    cudaGetSymbolAddress((void**)&s1,   g_s1);
    cudaGetSymbolAddress((void**)&s2,   g_s2);
    cudaGetSymbolAddress((void**)&h1,   g_h1);
    cudaGetSymbolAddress((void**)&wb,   g_wb);
    cudaGetSymbolAddress((void**)&xres, g_x);
    cudaGetSymbolAddress((void**)&bc,   g_bc);

    // transposed bf16 weight offsets (u32)
    unsigned* wS1t  = wb;               // [1536][256]
    unsigned* wS2t  = wb + 393216;      // [1536][256]
    unsigned* wCQt  = wb + 786432;      // [512][256]
    unsigned* wCKVt = wb + 917504;      // [1024][256]
    unsigned* wWot  = wb + 1179648;     // [512][256]
    unsigned* wW1t  = wb + 1310720;     // [1024][256]
    unsigned* wW2t  = wb + 1572864;     // [512][512]

    // one merged launch for the 10 square (512x512) transposes
    Sq10 sq;
    sq.s[0] = Wq1;  sq.d[0] = wS1t;
    sq.s[1] = Wk1;  sq.d[1] = wS1t + 131072;
    sq.s[2] = Wv1;  sq.d[2] = wS1t + 262144;
    sq.s[3] = Wq2;  sq.d[3] = wS2t;
    sq.s[4] = Wk2;  sq.d[4] = wS2t + 131072;
    sq.s[5] = Wv2;  sq.d[5] = wS2t + 262144;
    sq.s[6] = Wq12; sq.d[6] = wCQt;
    sq.s[7] = Wk12; sq.d[7] = wCKVt;
    sq.s[8] = Wv12; sq.d[8] = wCKVt + 131072;
    sq.s[9] = Wo;   sq.d[9] = wWot;
    wt10_kernel<<<dim3(16, 16, 10), dim3(32, 8)>>>(sq);
    wt_kernel<<<dim3(16, 32), dim3(32, 8)>>>(W1, wW1t, 512, 1024);
    wt_kernel<<<dim3(32, 16), dim3(32, 8)>>>(W2, wW2t, 1024, 512);

    // fp32 bias concats (one launch)
    B8 bp; bp.s[0]=bq1; bp.s[1]=bk1; bp.s[2]=bv1; bp.s[3]=bq2;
           bp.s[4]=bk2; bp.s[5]=bv2; bp.s[6]=bk12; bp.s[7]=bv12;
    bias_concat<<<16, 256>>>(bp, bc);
    float* bS1 = bc, *bS2 = bc + 1536, *bCKV = bc + 3072;

    // 1) pre-LN of both streams (bf16 out)
    ln_kernel<<<NTOK, 256>>>(x1, ln1_g, ln1_b, x1n);
    ln_kernel<<<NTOK, 256>>>(x2, ln2_g, ln2_b, x2n);

    // 2) stream-1 self-attention (residual x1n bf16 -> s1 bf16)
    run_gemm(x1n, wS1t, bS1, nullptr, nullptr, nullptr, qkv, NTOK, 1536, 512, 0);
    run_flash(qkv, 768, qkv + 256, qkv + 512, 768, ctx);
    run_gemm(ctx, wWot, bo, nullptr, x1n, nullptr, s1, NTOK, 512, 512, 0);

    // 3) stream-2 self-attention
    run_gemm(x2n, wS2t, bS2, nullptr, nullptr, nullptr, qkv, NTOK, 1536, 512, 0);
    run_flash(qkv, 768, qkv + 256, qkv + 512, 768, ctx);
    run_gemm(ctx, wWot, bo, nullptr, x2n, nullptr, s2, NTOK, 512, 512, 0);

    // 4) cross-attention: q from s1, k/v from s2; residual = x1 (fp32) -> xres fp32
    run_gemm(s1, wCQt, bq12, nullptr, nullptr, nullptr, qv, NTOK, 512, 512, 0);
    run_gemm(s2, wCKVt, bCKV, nullptr, nullptr, nullptr, qkv, NTOK, 1024, 512, 0);
    run_flash(qv, 256, qkv, qkv + 256, 512, ctx);
    run_gemm(ctx, wWot, bo, x1, nullptr, xres, nullptr, NTOK, 512, 512, 0);

    // 5) final LN + MLP, residual onto xres (fp32) -> out fp32
    ln_kernel<<<NTOK, 256>>>(xres, lnf_g, lnf_b, x1n);
    run_gemm(x1n, wW1t, b1, nullptr, nullptr, nullptr, h1, NTOK, 1024, 512, 1);
    run_gemm(h1, wW2t, b2, xres, nullptr, out, nullptr, NTOK, 512, 1024, 0);
    (void)in_sizes; (void)n_in; (void)out_size;
}

// round 9
// speedup vs baseline: 2.0375x; 1.0729x over previous
#include <cuda_runtime.h>
#include <cuda_bf16.h>
#include <math.h>
#include <stdint.h>

// Problem constants
#define BATCH 16
#define SEQ   1024
#define NTOK  (BATCH*SEQ)        // 16384
#define DMODEL 512
#define NHEAD  4
#define HDIM   128
#define DMLP   1024
#define NBH    (BATCH*NHEAD)     // 64

// -------- scratch (no cudaMalloc allowed). bf16 tensors stored as packed u32 pairs.
__device__ unsigned g_x1n[NTOK*256];
__device__ unsigned g_x2n[NTOK*256];
__device__ unsigned g_qv [NTOK*256];
__device__ unsigned g_qkv[NTOK*768];
__device__ unsigned g_ctx[NTOK*256];
__device__ unsigned g_s1 [NTOK*256];
__device__ unsigned g_s2 [NTOK*256];
__device__ float    g_x  [NTOK*DMODEL];
__device__ unsigned g_h1 [NTOK*512];
__device__ unsigned g_wb [1835008];
__device__ float    g_bc [4096];

extern __shared__ unsigned dsm[];

// ---------- helpers ----------
__device__ __forceinline__ unsigned packbf(float a, float b) {
    __nv_bfloat162 h = __floats2bfloat162_rn(a, b);
    return *reinterpret_cast<unsigned*>(&h);
}
__device__ __forceinline__ float2 unpackbf(unsigned u) {
    __nv_bfloat162 h = *reinterpret_cast<__nv_bfloat162*>(&u);
    return __bfloat1622float2(h);
}
__device__ __forceinline__ uint32_t smem_u32(const void* p) {
    uint32_t a;
    asm("{ .reg .u64 t; cvta.to.shared.u64 t, %1; cvt.u32.u64 %0, t; }" : "=r"(a) : "l"(p));
    return a;
}

#define MMA_BF16(acc, a, b) \
    asm volatile("mma.sync.aligned.m16n8k16.row.col.f32.bf16.bf16.f32 " \
        "{%0,%1,%2,%3}, {%4,%5,%6,%7}, {%8,%9}, {%0,%1,%2,%3};\n" \
        : "+f"((acc)[0]), "+f"((acc)[1]), "+f"((acc)[2]), "+f"((acc)[3]) \
        : "r"((a)[0]), "r"((a)[1]), "r"((a)[2]), "r"((a)[3]), "r"((b)[0]), "r"((b)[1]))

#define CP16(daddr, src) \
    asm volatile("cp.async.cg.shared.global [%0], [%1], 16;" :: "r"(daddr), "l"(src))
#define CPCOMMIT() asm volatile("cp.async.commit_group;" ::: "memory")
#define CPWAIT(n)  asm volatile("cp.async.wait_group %0;" :: "n"(n) : "memory")

// ============================================================
// Weight prep: transpose fp32 [K,N] -> bf16 [N, K/2 u32]
// ============================================================
__global__ void wt_kernel(const float* __restrict__ in, unsigned* __restrict__ out,
                          int K, int N) {
    __shared__ float t[32][33];
    int k0 = blockIdx.x * 32, n0 = blockIdx.y * 32;
    int tx = threadIdx.x, ty = threadIdx.y;
    #pragma unroll
    for (int i = 0; i < 4; i++)
        t[ty + i*8][tx] = in[(size_t)(k0 + ty + i*8) * N + n0 + tx];
    __syncthreads();
    #pragma unroll
    for (int i = 0; i < 2; i++) {
        int kp = ty + 8 * i;
        out[(size_t)(n0 + tx) * (K >> 1) + (k0 >> 1) + kp] =
            packbf(t[2*kp][tx], t[2*kp+1][tx]);
    }
}

struct Sq10 { const float* s[10]; unsigned* d[10]; };
__global__ void wt10_kernel(Sq10 p) {
    __shared__ float t[32][33];
    int m = blockIdx.z;
    const float* in = p.s[m];
    unsigned* out = p.d[m];
    int k0 = blockIdx.x * 32, n0 = blockIdx.y * 32;
    int tx = threadIdx.x, ty = threadIdx.y;
    #pragma unroll
    for (int i = 0; i < 4; i++)
        t[ty + i*8][tx] = in[(size_t)(k0 + ty + i*8) * 512 + n0 + tx];
    __syncthreads();
    #pragma unroll
    for (int i = 0; i < 2; i++) {
        int kp = ty + 8 * i;
        out[(size_t)(n0 + tx) * 256 + (k0 >> 1) + kp] =
            packbf(t[2*kp][tx], t[2*kp+1][tx]);
    }
}

struct B8 { const float* s[8]; };
__global__ void bias_concat(B8 p, float* __restrict__ dst) {
    int i = blockIdx.x * 256 + threadIdx.x;
    dst[i] = p.s[i >> 9][i & 511];
}

// ============================================================
// LayerNorm: fp32 in, bf16 (packed) out.
// ============================================================
__global__ void ln_kernel(const float* __restrict__ x,
                          const float* __restrict__ g,
                          const float* __restrict__ b,
                          unsigned* __restrict__ out) {
    int row = blockIdx.x;
    const float* xr = x + (size_t)row * DMODEL;
    unsigned* orow = out + (size_t)row * 256;
    int tid = threadIdx.x;
    float v0 = xr[2*tid], v1 = xr[2*tid + 1];

    __shared__ float sm[8];
    float s = v0 + v1;
    #pragma unroll
    for (int o = 16; o; o >>= 1) s += __shfl_xor_sync(0xffffffffu, s, o);
    if ((tid & 31) == 0) sm[tid >> 5] = s;
    __syncthreads();
    if (tid == 0) {
        float t = 0.f;
        #pragma unroll
        for (int i = 0; i < 8; i++) t += sm[i];
        sm[0] = t * (1.0f / DMODEL);
    }
    __syncthreads();
    float mean = sm[0];
    __syncthreads();

    float d0 = v0 - mean, d1 = v1 - mean;
    float q = d0 * d0 + d1 * d1;
    #pragma unroll
    for (int o = 16; o; o >>= 1) q += __shfl_xor_sync(0xffffffffu, q, o);
    if ((tid & 31) == 0) sm[tid >> 5] = q;
    __syncthreads();
    if (tid == 0) {
        float t = 0.f;
        #pragma unroll
        for (int i = 0; i < 8; i++) t += sm[i];
        sm[0] = rsqrtf(t * (1.0f / DMODEL) + 1e-6f);
    }
    __syncthreads();
    float rstd = sm[0];

    float y0 = d0 * rstd * g[2*tid]     + b[2*tid];
    float y1 = d1 * rstd * g[2*tid + 1] + b[2*tid + 1];
    orow[tid] = packbf(y0, y1);
}

// ============================================================
// bf16 GEMM with cp.async 4-stage pipeline. BK=16 elems (8 u32/row).
// 128x128 CTA tile, 8 warps (2x4), warp 64x32, pitch 12 u32 (conflict-free
// fragment loads). Stage = As(1536)+Bs(1536) u32; 4 stages = 48 KB dynamic.
// Epilogue: +bias(fp32), gelu, +addf(fp32) or +addb(bf16); out fp32/bf16.
// ============================================================
#define GM_STAGE 3072
#define GM_SMEM  (4 * GM_STAGE * 4)

__global__ void __launch_bounds__(256, 2)
gemm_bf(const unsigned* __restrict__ A, const unsigned* __restrict__ BT,
        const float* __restrict__ bias,
        const float* __restrict__ addf, const unsigned* __restrict__ addb,
        float* __restrict__ Cf, unsigned* __restrict__ Cb,
        int N, int K, int act)
{
    uint32_t sb = smem_u32(dsm);
    int bm = blockIdx.y * 128, bn = blockIdx.x * 128;
    int tid = threadIdx.x;
    int warp = tid >> 5, lane = tid & 31;
    int wm = warp >> 2, wn = warp & 3;
    int gid = lane >> 2, tig = lane & 3;
    int lda2 = K >> 1;
    int chunks = K >> 4;

    // cp.async loader: each thread 1x16B for A and B per chunk
    int crow = tid >> 1, cseg = tid & 1;
    const unsigned* Asrc = A + (size_t)(bm + crow) * lda2 + cseg * 4;
    const unsigned* Bsrc = BT + (size_t)(bn + crow) * lda2 + cseg * 4;
    int dsto = crow * 12 + cseg * 4;

    float acc[4][4][4];
    #pragma unroll
    for (int i = 0; i < 4; i++)
        #pragma unroll
        for (int j = 0; j < 4; j++)
            #pragma unroll
            for (int c = 0; c < 4; c++) acc[i][j][c] = 0.f;

    // prologue: stages 0..2
    #pragma unroll
    for (int c = 0; c < 3; c++) {
        int st = c & 3;
        CP16(sb + (st * GM_STAGE + dsto) * 4, Asrc + c * 8);
        CP16(sb + (st * GM_STAGE + 1536 + dsto) * 4, Bsrc + c * 8);
        CPCOMMIT();
    }

    for (int c = 0; c < chunks; c++) {
        CPWAIT(2);
        __syncthreads();
        // prefetch chunk c+3 into stage (c+3)&3 (== (c-1)&3; readers barrier-done)
        if (c + 3 < chunks) {
            int st = (c + 3) & 3;
            CP16(sb + (st * GM_STAGE + dsto) * 4, Asrc + (c + 3) * 8);
            CP16(sb + (st * GM_STAGE + 1536 + dsto) * 4, Bsrc + (c + 3) * 8);
        }
        CPCOMMIT();   // uniform group count even when no cp issued

        unsigned* As = dsm + (c & 3) * GM_STAGE;
        unsigned* Bs = As + 1536;
        unsigned af[4][4], bf2[4][2];
        #pragma unroll
        for (int ma = 0; ma < 4; ma++) {
            int mb = (wm * 64 + ma * 16 + gid) * 12 + tig;
            af[ma][0] = As[mb];
            af[ma][1] = As[mb + 96];
            af[ma][2] = As[mb + 4];
            af[ma][3] = As[mb + 100];
        }
        #pragma unroll
        for (int nb = 0; nb < 4; nb++) {
            int nbase = (wn * 32 + nb * 8 + gid) * 12 + tig;
            bf2[nb][0] = Bs[nbase];
            bf2[nb][1] = Bs[nbase + 4];
        }
        #pragma unroll
        for (int ma = 0; ma < 4; ma++)
            #pragma unroll
            for (int nb = 0; nb < 4; nb++)
                MMA_BF16(acc[ma][nb], af[ma], bf2[nb]);
    }

    // epilogue
    #pragma unroll
    for (int ma = 0; ma < 4; ma++) {
        #pragma unroll
        for (int nb = 0; nb < 4; nb++) {
            int c = bn + wn * 32 + nb * 8 + tig * 2;
            float bv0 = bias ? bias[c] : 0.f;
            float bv1 = bias ? bias[c + 1] : 0.f;
            #pragma unroll
            for (int half = 0; half < 2; half++) {
                int r = bm + wm * 64 + ma * 16 + gid + half * 8;
                float t0 = acc[ma][nb][half * 2 + 0] + bv0;
                float t1 = acc[ma][nb][half * 2 + 1] + bv1;
                if (act) {
                    t0 = 0.5f * t0 * (1.0f + erff(t0 * 0.70710678118654752f));
                    t1 = 0.5f * t1 * (1.0f + erff(t1 * 0.70710678118654752f));
                }
                size_t off = (size_t)r * N + c;
                if (addf) { t0 += addf[off]; t1 += addf[off + 1]; }
                if (addb) {
                    float2 av = unpackbf(addb[(size_t)r * (N >> 1) + (c >> 1)]);
                    t0 += av.x; t1 += av.y;
                }
                if (Cf) *(float2*)&Cf[off] = make_float2(t0, t1);
                if (Cb) Cb[(size_t)r * (N >> 1) + (c >> 1)] = packbf(t0, t1);
            }
        }
    }
}

// ============================================================
// bf16 flash attention (R7 known-good version, unchanged):
// 128 Q rows per CTA, KV chunks of 64, online softmax,
// bf16 m16n8k16 for S=QK^T and O=PV. 2 CTAs/SM.
// ============================================================
// smem u32 offsets
#define SQ_O 0        // 128 x 68
#define SK_O 8704     // 64 x 68
#define SV_O 13056    // 32 x 136 (token-pair packed)
#define SP_O 17408    // 128 x 36
#define R1_O 22016    // 512 floats
#define R2_O 22528    // 512 floats
#define FL_SMEM_BYTES (23040 * 4)

__global__ void __launch_bounds__(256, 2)
flash_bf(const unsigned* __restrict__ Qm, int qld2,
         const unsigned* __restrict__ Km, const unsigned* __restrict__ Vm, int kvld2,
         unsigned* __restrict__ Om)
{
    unsigned* fsu = dsm;
    float* sR1 = (float*)(fsu + R1_O);
    float* sR2 = (float*)(fsu + R2_O);

    int tid = threadIdx.x;
    int warp = tid >> 5, lane = tid & 31;
    int wm = warp >> 2, wn = warp & 3;
    int gid = lane >> 2, tig = lane & 3;

    int bh = blockIdx.y, b = bh >> 2, h = bh & 3;
    int q0 = blockIdx.x * 128, base = b * SEQ;
    int hoff2 = h * 64;   // u32 offset of head within row

    // load Q tile (128 x 64 u32), pitch 68
    {
        int r = tid >> 1, hq = tid & 1;
        const unsigned* src = Qm + (size_t)(base + q0 + r) * qld2 + hoff2 + hq * 32;
        unsigned* dst = fsu + SQ_O + r * 68 + hq * 32;
        #pragma unroll
        for (int i = 0; i < 8; i++) *(uint4*)(dst + 4*i) = *(const uint4*)(src + 4*i);
    }

    float oacc[4][4][4];
    #pragma unroll
    for (int i = 0; i < 4; i++)
        #pragma unroll
        for (int j = 0; j < 4; j++)
            #pragma unroll
            for (int c = 0; c < 4; c++) oacc[i][j][c] = 0.f;
    float mrow[4][2], lrow[4][2];
    #pragma unroll
    for (int i = 0; i < 4; i++) { mrow[i][0] = -1e30f; mrow[i][1] = -1e30f;
                                  lrow[i][0] = 0.f;    lrow[i][1] = 0.f; }

    const float scale = 0.08838834764831845f;   // 1/sqrt(128)

    for (int ch = 0; ch < SEQ / 64; ch++) {
        int kv0 = ch * 64;
        __syncthreads();   // prev-iter PV readers done with sK/sV/sP
        // K chunk: 64 rows x 64 u32, pitch 68
        {
            int r = tid >> 2, qo = (tid & 3) * 16;
            const unsigned* src = Km + (size_t)(base + kv0 + r) * kvld2 + hoff2 + qo;
            unsigned* dst = fsu + SK_O + r * 68 + qo;
            #pragma unroll
            for (int i = 0; i < 4; i++) *(uint4*)(dst + 4*i) = *(const uint4*)(src + 4*i);
        }
        // V chunk repacked token-pair-major: sVp[kp][d], pitch 136
        {
            int kp = tid >> 3, dg = (tid & 7) * 8;
            const unsigned* v0p = Vm + (size_t)(base + kv0 + 2*kp) * kvld2 + hoff2 + dg;
            const unsigned* v1p = v0p + kvld2;
            unsigned lo[8], hi[8], o[16];
            *(uint4*)&lo[0] = *(const uint4*)v0p; *(uint4*)&lo[4] = *(const uint4*)(v0p + 4);
            *(uint4*)&hi[0] = *(const uint4*)v1p; *(uint4*)&hi[4] = *(const uint4*)(v1p + 4);
            #pragma unroll
            for (int i = 0; i < 8; i++) {
                o[2*i]   = __byte_perm(lo[i], hi[i], 0x5410);
                o[2*i+1] = __byte_perm(lo[i], hi[i], 0x7632);
            }
            unsigned* dst = fsu + SV_O + kp * 136 + dg * 2;
            #pragma unroll
            for (int i = 0; i < 4; i++) *(uint4*)(dst + 4*i) = *(uint4*)&o[4*i];
        }
        __syncthreads();

        // S = Q @ K^T : warp tile 64x16 (ma 4, nb 2), 8 k-steps of 16
        float s[4][2][4];
        #pragma unroll
        for (int i = 0; i < 4; i++)
            #pragma unroll
            for (int j = 0; j < 2; j++)
                #pragma unroll
                for (int c = 0; c < 4; c++) s[i][j][c] = 0.f;

        #pragma unroll
        for (int ks = 0; ks < 8; ks++) {
            int kb = ks * 8;
            unsigned af[4][4], bf2[2][2];
            #pragma unroll
            for (int ma = 0; ma < 4; ma++) {
                int mb = (wm * 64 + ma * 16 + gid) * 68 + kb + tig;
                af[ma][0] = fsu[SQ_O + mb];
                af[ma][1] = fsu[SQ_O + mb + 544];
                af[ma][2] = fsu[SQ_O + mb + 4];
                af[ma][3] = fsu[SQ_O + mb + 548];
            }
            #pragma unroll
            for (int nb = 0; nb < 2; nb++) {
                int nbase = (wn * 16 + nb * 8 + gid) * 68 + kb + tig;
                bf2[nb][0] = fsu[SK_O + nbase];
                bf2[nb][1] = fsu[SK_O + nbase + 4];
            }
            #pragma unroll
            for (int ma = 0; ma < 4; ma++)
                #pragma unroll
                for (int nb = 0; nb < 2; nb++)
                    MMA_BF16(s[ma][nb], af[ma], bf2[nb]);
        }

        // online softmax pass 1: per-warp row max -> sR1
        #pragma unroll
        for (int ma = 0; ma < 4; ma++)
            #pragma unroll
            for (int hf = 0; hf < 2; hf++) {
                float mx = fmaxf(fmaxf(s[ma][0][hf*2], s[ma][0][hf*2+1]),
                                 fmaxf(s[ma][1][hf*2], s[ma][1][hf*2+1])) * scale;
                mx = fmaxf(mx, __shfl_xor_sync(0xffffffffu, mx, 1));
                mx = fmaxf(mx, __shfl_xor_sync(0xffffffffu, mx, 2));
                if (tig == 0) sR1[(wm*64 + ma*16 + hf*8 + gid) * 4 + wn] = mx;
            }
        __syncthreads();

        // pass 2: global max, exp, sums, rescale O, pack P (bf16) to smem
        #pragma unroll
        for (int ma = 0; ma < 4; ma++)
            #pragma unroll
            for (int hf = 0; hf < 2; hf++) {
                int r = wm*64 + ma*16 + hf*8 + gid;
                float cm = fmaxf(fmaxf(sR1[r*4+0], sR1[r*4+1]),
                                 fmaxf(sR1[r*4+2], sR1[r*4+3]));
                float nm = fmaxf(mrow[ma][hf], cm);
                float alpha = __expf(mrow[ma][hf] - nm);
                mrow[ma][hf] = nm;
                float p0 = __expf(s[ma][0][hf*2]   * scale - nm);
                float p1 = __expf(s[ma][0][hf*2+1] * scale - nm);
                float p2 = __expf(s[ma][1][hf*2]   * scale - nm);
                float p3 = __expf(s[ma][1][hf*2+1] * scale - nm);
                float sum = p0 + p1 + p2 + p3;
                sum += __shfl_xor_sync(0xffffffffu, sum, 1);
                sum += __shfl_xor_sync(0xffffffffu, sum, 2);
                if (tig == 0) sR2[r*4 + wn] = sum;
                lrow[ma][hf] *= alpha;
                #pragma unroll
                for (int nb = 0; nb < 4; nb++) {
                    oacc[ma][nb][hf*2]   *= alpha;
                    oacc[ma][nb][hf*2+1] *= alpha;
                }
                fsu[SP_O + r*36 + wn*8 + tig]     = packbf(p0, p1);
                fsu[SP_O + r*36 + wn*8 + 4 + tig] = packbf(p2, p3);
            }
        __syncthreads();

        #pragma unroll
        for (int ma = 0; ma < 4; ma++)
            #pragma unroll
            for (int hf = 0; hf < 2; hf++) {
                int r = wm*64 + ma*16 + hf*8 + gid;
                lrow[ma][hf] += sR2[r*4+0] + sR2[r*4+1] + sR2[r*4+2] + sR2[r*4+3];
            }

        // O += P @ V : warp tile 64x32 (ma 4, nb 4), 4 k-steps of 16 tokens
        #pragma unroll
        for (int ks = 0; ks < 4; ks++) {
            int kb = ks * 8;
            unsigned ap[4][4], bv[4][2];
            #pragma unroll
            for (int ma = 0; ma < 4; ma++) {
                int pb = (wm * 64 + ma * 16 + gid) * 36 + kb + tig;
                ap[ma][0] = fsu[SP_O + pb];
                ap[ma][1] = fsu[SP_O + pb + 288];
                ap[ma][2] = fsu[SP_O + pb + 4];
                ap[ma][3] = fsu[SP_O + pb + 292];
            }
            #pragma unroll
            for (int nb = 0; nb < 4; nb++) {
                int n0 = wn * 32 + nb * 8 + gid;
                bv[nb][0] = fsu[SV_O + (kb + tig) * 136 + n0];
                bv[nb][1] = fsu[SV_O + (kb + tig + 4) * 136 + n0];
            }
            #pragma unroll
            for (int ma = 0; ma < 4; ma++)
                #pragma unroll
                for (int nb = 0; nb < 4; nb++)
                    MMA_BF16(oacc[ma][nb], ap[ma], bv[nb]);
        }
    }

    // epilogue: divide by l, pack bf16, store ctx [token][256 u32]
    #pragma unroll
    for (int ma = 0; ma < 4; ma++)
        #pragma unroll
        for (int hf = 0; hf < 2; hf++) {
            float inv = 1.0f / lrow[ma][hf];
            int gr = base + q0 + wm*64 + ma*16 + hf*8 + gid;
            #pragma unroll
            for (int nb = 0; nb < 4; nb++) {
                int cp = h*64 + wn*16 + nb*4 + tig;
                Om[(size_t)gr * 256 + cp] =
                    packbf(oacc[ma][nb][hf*2] * inv, oacc[ma][nb][hf*2+1] * inv);
            }
        }
}

// ============================================================
// Host orchestration
// ============================================================
static inline void run_gemm(const unsigned* A, const unsigned* BT, const float* bias,
                            const float* addf, const unsigned* addb,
                            float* Cf, unsigned* Cb, int M, int N, int K, int act) {
    cudaFuncSetAttribute(gemm_bf, cudaFuncAttributeMaxDynamicSharedMemorySize, GM_SMEM);
    dim3 grid(N / 128, M / 128);
    gemm_bf<<<grid, 256, GM_SMEM>>>(A, BT, bias, addf, addb, Cf, Cb, N, K, act);
}

static inline void run_flash(const unsigned* Qm, int qld2,
                             const unsigned* Km, const unsigned* Vm, int kvld2,
                             unsigned* Om) {
    cudaFuncSetAttribute(flash_bf, cudaFuncAttributeMaxDynamicSharedMemorySize, FL_SMEM_BYTES);
    dim3 grid(SEQ / 128, NBH);
    flash_bf<<<grid, 256, FL_SMEM_BYTES>>>(Qm, qld2, Km, Vm, kvld2, Om);
}

extern "C" void kernel_launch(void* const* d_in, const int* in_sizes, int n_in,
                              void* d_out, int out_size) {
    const float* x1    = (const float*)d_in[0];
    const float* x2    = (const float*)d_in[1];
    const float* ln1_g = (const float*)d_in[2];
    const float* ln1_b = (const float*)d_in[3];
    const float* ln2_g = (const float*)d_in[4];
    const float* ln2_b = (const float*)d_in[5];
    const float* lnf_g = (const float*)d_in[6];
    const float* lnf_b = (const float*)d_in[7];
    const float* Wq1 = (const float*)d_in[8],  *bq1 = (const float*)d_in[9];
    const float* Wk1 = (const float*)d_in[10], *bk1 = (const float*)d_in[11];
    const float* Wv1 = (const float*)d_in[12], *bv1 = (const float*)d_in[13];
    const float* Wq2 = (const float*)d_in[14], *bq2 = (const float*)d_in[15];
    const float* Wk2 = (const float*)d_in[16], *bk2 = (const float*)d_in[17];
    const float* Wv2 = (const float*)d_in[18], *bv2 = (const float*)d_in[19];
    const float* Wq12 = (const float*)d_in[20], *bq12 = (const float*)d_in[21];
    const float* Wk12 = (const float*)d_in[22], *bk12 = (const float*)d_in[23];
    const float* Wv12 = (const float*)d_in[24], *bv12 = (const float*)d_in[25];
    const float* Wo  = (const float*)d_in[26], *bo = (const float*)d_in[27];
    const float* W1  = (const float*)d_in[28], *b1 = (const float*)d_in[29];
    const float* W2  = (const float*)d_in[30], *b2 = (const float*)d_in[31];
    float* out = (float*)d_out;

    unsigned *x1n, *x2n, *qv, *qkv, *ctx, *s1, *s2, *h1, *wb;
    float *xres, *bc;
    cudaGetSymbolAddress((void**)&x1n,  g_x1n);
    cudaGetSymbolAddress((void**)&x2n,  g_x2n);
    cudaGetSymbolAddress((void**)&qv,   g_qv);
    cudaGetSymbolAddress((void**)&qkv,  g_qkv);
    cudaGetSymbolAddress((void**)&ctx,  g_ctx);
    cudaGetSymbolAddress((void**)&s1,   g_s1);
    cudaGetSymbolAddress((void**)&s2,   g_s2);
    cudaGetSymbolAddress((void**)&h1,   g_h1);
    cudaGetSymbolAddress((void**)&wb,   g_wb);
    cudaGetSymbolAddress((void**)&xres, g_x);
    cudaGetSymbolAddress((void**)&bc,   g_bc);

    unsigned* wS1t  = wb;
    unsigned* wS2t  = wb + 393216;
    unsigned* wCQt  = wb + 786432;
    unsigned* wCKVt = wb + 917504;
    unsigned* wWot  = wb + 1179648;
    unsigned* wW1t  = wb + 1310720;
    unsigned* wW2t  = wb + 1572864;

    Sq10 sq;
    sq.s[0] = Wq1;  sq.d[0] = wS1t;
    sq.s[1] = Wk1;  sq.d[1] = wS1t + 131072;
    sq.s[2] = Wv1;  sq.d[2] = wS1t + 262144;
    sq.s[3] = Wq2;  sq.d[3] = wS2t;
    sq.s[4] = Wk2;  sq.d[4] = wS2t + 131072;
    sq.s[5] = Wv2;  sq.d[5] = wS2t + 262144;
    sq.s[6] = Wq12; sq.d[6] = wCQt;
    sq.s[7] = Wk12; sq.d[7] = wCKVt;
    sq.s[8] = Wv12; sq.d[8] = wCKVt + 131072;
    sq.s[9] = Wo;   sq.d[9] = wWot;
    wt10_kernel<<<dim3(16, 16, 10), dim3(32, 8)>>>(sq);
    wt_kernel<<<dim3(16, 32), dim3(32, 8)>>>(W1, wW1t, 512, 1024);
    wt_kernel<<<dim3(32, 16), dim3(32, 8)>>>(W2, wW2t, 1024, 512);

    B8 bp; bp.s[0]=bq1; bp.s[1]=bk1; bp.s[2]=bv1; bp.s[3]=bq2;
           bp.s[4]=bk2; bp.s[5]=bv2; bp.s[6]=bk12; bp.s[7]=bv12;
    bias_concat<<<16, 256>>>(bp, bc);
    float* bS1 = bc, *bS2 = bc + 1536, *bCKV = bc + 3072;

    // 1) pre-LN
    ln_kernel<<<NTOK, 256>>>(x1, ln1_g, ln1_b, x1n);
    ln_kernel<<<NTOK, 256>>>(x2, ln2_g, ln2_b, x2n);

    // 2) stream-1 self-attention
    run_gemm(x1n, wS1t, bS1, nullptr, nullptr, nullptr, qkv, NTOK, 1536, 512, 0);
    run_flash(qkv, 768, qkv + 256, qkv + 512, 768, ctx);
    run_gemm(ctx, wWot, bo, nullptr, x1n, nullptr, s1, NTOK, 512, 512, 0);

    // 3) stream-2 self-attention
    run_gemm(x2n, wS2t, bS2, nullptr, nullptr, nullptr, qkv, NTOK, 1536, 512, 0);
    run_flash(qkv, 768, qkv + 256, qkv + 512, 768, ctx);
    run_gemm(ctx, wWot, bo, nullptr, x2n, nullptr, s2, NTOK, 512, 512, 0);

    // 4) cross-attention
    run_gemm(s1, wCQt, bq12, nullptr, nullptr, nullptr, qv, NTOK, 512, 512, 0);
    run_gemm(s2, wCKVt, bCKV, nullptr, nullptr, nullptr, qkv, NTOK, 1024, 512, 0);
    run_flash(qv, 256, qkv, qkv + 256, 512, ctx);
    run_gemm(ctx, wWot, bo, x1, nullptr, xres, nullptr, NTOK, 512, 512, 0);

    // 5) final LN + MLP
    ln_kernel<<<NTOK, 256>>>(xres, lnf_g, lnf_b, x1n);
    run_gemm(x1n, wW1t, b1, nullptr, nullptr, nullptr, h1, NTOK, 1024, 512, 1);
    run_gemm(h1, wW2t, b2, xres, nullptr, out, nullptr, NTOK, 512, 1024, 0);
    (void)in_sizes; (void)n_in; (void)out_size;
}

// round 10
// speedup vs baseline: 2.1076x; 1.0344x over previous
#include <cuda_runtime.h>
#include <cuda_bf16.h>
#include <math.h>
#include <stdint.h>

// Problem constants
#define BATCH 16
#define SEQ   1024
#define NTOK  (BATCH*SEQ)        // 16384
#define DMODEL 512
#define NHEAD  4
#define HDIM   128
#define DMLP   1024
#define NBH    (BATCH*NHEAD)     // 64

// -------- scratch (no cudaMalloc allowed). bf16 tensors stored as packed u32 pairs.
__device__ unsigned g_x1n[NTOK*256];
__device__ unsigned g_x2n[NTOK*256];
__device__ unsigned g_qv [NTOK*256];
__device__ unsigned g_qkv1[NTOK*768];
__device__ unsigned g_qkv2[NTOK*768];
__device__ unsigned g_ctx1[NTOK*256];
__device__ unsigned g_ctx2[NTOK*256];
__device__ unsigned g_s1 [NTOK*256];
__device__ unsigned g_s2 [NTOK*256];
__device__ float    g_x  [NTOK*DMODEL];
__device__ unsigned g_h1 [NTOK*512];
__device__ unsigned g_wb [1835008];
__device__ float    g_bc [4096];

extern __shared__ unsigned dsm[];

// ---------- helpers ----------
__device__ __forceinline__ unsigned packbf(float a, float b) {
    __nv_bfloat162 h = __floats2bfloat162_rn(a, b);
    return *reinterpret_cast<unsigned*>(&h);
}
__device__ __forceinline__ float2 unpackbf(unsigned u) {
    __nv_bfloat162 h = *reinterpret_cast<__nv_bfloat162*>(&u);
    return __bfloat1622float2(h);
}
__device__ __forceinline__ uint32_t smem_u32(const void* p) {
    uint32_t a;
    asm("{ .reg .u64 t; cvta.to.shared.u64 t, %1; cvt.u32.u64 %0, t; }" : "=r"(a) : "l"(p));
    return a;
}

#define MMA_BF16(acc, a, b) \
    asm volatile("mma.sync.aligned.m16n8k16.row.col.f32.bf16.bf16.f32 " \
        "{%0,%1,%2,%3}, {%4,%5,%6,%7}, {%8,%9}, {%0,%1,%2,%3};\n" \
        : "+f"((acc)[0]), "+f"((acc)[1]), "+f"((acc)[2]), "+f"((acc)[3]) \
        : "r"((a)[0]), "r"((a)[1]), "r"((a)[2]), "r"((a)[3]), "r"((b)[0]), "r"((b)[1]))

#define CP16(daddr, src) \
    asm volatile("cp.async.cg.shared.global [%0], [%1], 16;" :: "r"(daddr), "l"(src))
#define CPCOMMIT() asm volatile("cp.async.commit_group;" ::: "memory")
#define CPWAIT(n)  asm volatile("cp.async.wait_group %0;" :: "n"(n) : "memory")

// ============================================================
// Merged prep: 12 weight transposes (fp32 [K,N] -> bf16 [N][K/2]) + bias concat
// Block (32,8). Grid 3586 blocks.
// ============================================================
struct Prep {
    const float* ws[12]; unsigned* wd[12];
    const float* bs[8];  float* bdst;
};

__device__ __forceinline__ void tile_transpose(const float* __restrict__ in,
                                               unsigned* __restrict__ out,
                                               int K, int N, int bx, int by) {
    __shared__ float t[32][33];
    int k0 = bx * 32, n0 = by * 32;
    int tx = threadIdx.x, ty = threadIdx.y;
    #pragma unroll
    for (int i = 0; i < 4; i++)
        t[ty + i*8][tx] = in[(size_t)(k0 + ty + i*8) * N + n0 + tx];
    __syncthreads();
    #pragma unroll
    for (int i = 0; i < 2; i++) {
        int kp = ty + 8 * i;
        out[(size_t)(n0 + tx) * (K >> 1) + (k0 >> 1) + kp] =
            packbf(t[2*kp][tx], t[2*kp+1][tx]);
    }
}

__global__ void prep_kernel(Prep p) {
    int id = blockIdx.x;
    if (id < 2560) {
        int m = id >> 8, t = id & 255;
        tile_transpose(p.ws[m], p.wd[m], 512, 512, t & 15, t >> 4);
    } else if (id < 3072) {
        int t = id - 2560;
        tile_transpose(p.ws[10], p.wd[10], 512, 1024, t & 15, t >> 4);
    } else if (id < 3584) {
        int t = id - 3072;
        tile_transpose(p.ws[11], p.wd[11], 1024, 512, t & 31, t >> 5);
    } else {
        int t = threadIdx.y * 32 + threadIdx.x;
        int i0 = (id - 3584) * 2048 + t * 8;
        #pragma unroll
        for (int j = 0; j < 8; j++) {
            int i = i0 + j;
            p.bdst[i] = p.bs[i >> 9][i & 511];
        }
    }
}

// ============================================================
// Batched LayerNorm: fp32 in, bf16 (packed) out. blockIdx.y picks stream.
// ============================================================
__global__ void ln_kernel(const float* __restrict__ xA, const float* __restrict__ gA,
                          const float* __restrict__ bA, unsigned* __restrict__ oA,
                          const float* __restrict__ xB, const float* __restrict__ gB,
                          const float* __restrict__ bB, unsigned* __restrict__ oB) {
    const float* x = blockIdx.y ? xB : xA;
    const float* g = blockIdx.y ? gB : gA;
    const float* b = blockIdx.y ? bB : bA;
    unsigned* out  = blockIdx.y ? oB : oA;

    int row = blockIdx.x;
    const float* xr = x + (size_t)row * DMODEL;
    unsigned* orow = out + (size_t)row * 256;
    int tid = threadIdx.x;
    float v0 = xr[2*tid], v1 = xr[2*tid + 1];

    __shared__ float sm[8];
    float s = v0 + v1;
    #pragma unroll
    for (int o = 16; o; o >>= 1) s += __shfl_xor_sync(0xffffffffu, s, o);
    if ((tid & 31) == 0) sm[tid >> 5] = s;
    __syncthreads();
    if (tid == 0) {
        float t = 0.f;
        #pragma unroll
        for (int i = 0; i < 8; i++) t += sm[i];
        sm[0] = t * (1.0f / DMODEL);
    }
    __syncthreads();
    float mean = sm[0];
    __syncthreads();

    float d0 = v0 - mean, d1 = v1 - mean;
    float q = d0 * d0 + d1 * d1;
    #pragma unroll
    for (int o = 16; o; o >>= 1) q += __shfl_xor_sync(0xffffffffu, q, o);
    if ((tid & 31) == 0) sm[tid >> 5] = q;
    __syncthreads();
    if (tid == 0) {
        float t = 0.f;
        #pragma unroll
        for (int i = 0; i < 8; i++) t += sm[i];
        sm[0] = rsqrtf(t * (1.0f / DMODEL) + 1e-6f);
    }
    __syncthreads();
    float rstd = sm[0];

    float y0 = d0 * rstd * g[2*tid]     + b[2*tid];
    float y1 = d1 * rstd * g[2*tid + 1] + b[2*tid + 1];
    orow[tid] = packbf(y0, y1);
}

// ============================================================
// bf16 GEMM with cp.async 4-stage pipeline, z-batched (2 slices).
// 128x128 CTA tile, 8 warps (2x4), warp 64x32, pitch 12 u32.
// ============================================================
#define GM_STAGE 3072
#define GM_SMEM  (4 * GM_STAGE * 4)

struct GB {
    const unsigned* A; const unsigned* BT; const float* bias;
    const float* addf; const unsigned* addb;
    float* Cf; unsigned* Cb;
};

__global__ void __launch_bounds__(256, 2)
gemm_bf(GB g0, GB g1, int N0, int N1, int K, int act)
{
    GB G = blockIdx.z ? g1 : g0;
    int N = blockIdx.z ? N1 : N0;
    int bn = blockIdx.x * 128;
    if (bn >= N) return;

    uint32_t sb = smem_u32(dsm);
    int bm = blockIdx.y * 128;
    int tid = threadIdx.x;
    int warp = tid >> 5, lane = tid & 31;
    int wm = warp >> 2, wn = warp & 3;
    int gid = lane >> 2, tig = lane & 3;
    int lda2 = K >> 1;
    int chunks = K >> 4;

    int crow = tid >> 1, cseg = tid & 1;
    const unsigned* Asrc = G.A + (size_t)(bm + crow) * lda2 + cseg * 4;
    const unsigned* Bsrc = G.BT + (size_t)(bn + crow) * lda2 + cseg * 4;
    int dsto = crow * 12 + cseg * 4;

    float acc[4][4][4];
    #pragma unroll
    for (int i = 0; i < 4; i++)
        #pragma unroll
        for (int j = 0; j < 4; j++)
            #pragma unroll
            for (int c = 0; c < 4; c++) acc[i][j][c] = 0.f;

    #pragma unroll
    for (int c = 0; c < 3; c++) {
        int st = c & 3;
        CP16(sb + (st * GM_STAGE + dsto) * 4, Asrc + c * 8);
        CP16(sb + (st * GM_STAGE + 1536 + dsto) * 4, Bsrc + c * 8);
        CPCOMMIT();
    }

    for (int c = 0; c < chunks; c++) {
        CPWAIT(2);
        __syncthreads();
        if (c + 3 < chunks) {
            int st = (c + 3) & 3;
            CP16(sb + (st * GM_STAGE + dsto) * 4, Asrc + (c + 3) * 8);
            CP16(sb + (st * GM_STAGE + 1536 + dsto) * 4, Bsrc + (c + 3) * 8);
        }
        CPCOMMIT();

        unsigned* As = dsm + (c & 3) * GM_STAGE;
        unsigned* Bs = As + 1536;
        unsigned af[4][4], bf2[4][2];
        #pragma unroll
        for (int ma = 0; ma < 4; ma++) {
            int mb = (wm * 64 + ma * 16 + gid) * 12 + tig;
            af[ma][0] = As[mb];
            af[ma][1] = As[mb + 96];
            af[ma][2] = As[mb + 4];
            af[ma][3] = As[mb + 100];
        }
        #pragma unroll
        for (int nb = 0; nb < 4; nb++) {
            int nbase = (wn * 32 + nb * 8 + gid) * 12 + tig;
            bf2[nb][0] = Bs[nbase];
            bf2[nb][1] = Bs[nbase + 4];
        }
        #pragma unroll
        for (int ma = 0; ma < 4; ma++)
            #pragma unroll
            for (int nb = 0; nb < 4; nb++)
                MMA_BF16(acc[ma][nb], af[ma], bf2[nb]);
    }

    // epilogue
    #pragma unroll
    for (int ma = 0; ma < 4; ma++) {
        #pragma unroll
        for (int nb = 0; nb < 4; nb++) {
            int c = bn + wn * 32 + nb * 8 + tig * 2;
            float bv0 = G.bias ? G.bias[c] : 0.f;
            float bv1 = G.bias ? G.bias[c + 1] : 0.f;
            #pragma unroll
            for (int half = 0; half < 2; half++) {
                int r = bm + wm * 64 + ma * 16 + gid + half * 8;
                float t0 = acc[ma][nb][half * 2 + 0] + bv0;
                float t1 = acc[ma][nb][half * 2 + 1] + bv1;
                if (act) {
                    t0 = 0.5f * t0 * (1.0f + erff(t0 * 0.70710678118654752f));
                    t1 = 0.5f * t1 * (1.0f + erff(t1 * 0.70710678118654752f));
                }
                size_t off = (size_t)r * N + c;
                if (G.addf) { t0 += G.addf[off]; t1 += G.addf[off + 1]; }
                if (G.addb) {
                    float2 av = unpackbf(G.addb[(size_t)r * (N >> 1) + (c >> 1)]);
                    t0 += av.x; t1 += av.y;
                }
                if (G.Cf) *(float2*)&G.Cf[off] = make_float2(t0, t1);
                if (G.Cb) G.Cb[(size_t)r * (N >> 1) + (c >> 1)] = packbf(t0, t1);
            }
        }
    }
}

// ============================================================
// bf16 flash attention (R7/R9 known-good compute), z-batched.
// ============================================================
#define SQ_O 0        // 128 x 68
#define SK_O 8704     // 64 x 68
#define SV_O 13056    // 32 x 136 (token-pair packed)
#define SP_O 17408    // 128 x 36
#define R1_O 22016    // 512 floats
#define R2_O 22528    // 512 floats
#define FL_SMEM_BYTES (23040 * 4)

struct FB { const unsigned* Qm; const unsigned* Km; const unsigned* Vm; unsigned* Om; };

__global__ void __launch_bounds__(256, 2)
flash_bf(FB f0, FB f1, int qld2, int kvld2)
{
    FB F = blockIdx.z ? f1 : f0;
    unsigned* fsu = dsm;
    float* sR1 = (float*)(fsu + R1_O);
    float* sR2 = (float*)(fsu + R2_O);

    int tid = threadIdx.x;
    int warp = tid >> 5, lane = tid & 31;
    int wm = warp >> 2, wn = warp & 3;
    int gid = lane >> 2, tig = lane & 3;

    int bh = blockIdx.y, b = bh >> 2, h = bh & 3;
    int q0 = blockIdx.x * 128, base = b * SEQ;
    int hoff2 = h * 64;

    {
        int r = tid >> 1, hq = tid & 1;
        const unsigned* src = F.Qm + (size_t)(base + q0 + r) * qld2 + hoff2 + hq * 32;
        unsigned* dst = fsu + SQ_O + r * 68 + hq * 32;
        #pragma unroll
        for (int i = 0; i < 8; i++) *(uint4*)(dst + 4*i) = *(const uint4*)(src + 4*i);
    }

    float oacc[4][4][4];
    #pragma unroll
    for (int i = 0; i < 4; i++)
        #pragma unroll
        for (int j = 0; j < 4; j++)
            #pragma unroll
            for (int c = 0; c < 4; c++) oacc[i][j][c] = 0.f;
    float mrow[4][2], lrow[4][2];
    #pragma unroll
    for (int i = 0; i < 4; i++) { mrow[i][0] = -1e30f; mrow[i][1] = -1e30f;
                                  lrow[i][0] = 0.f;    lrow[i][1] = 0.f; }

    const float scale = 0.08838834764831845f;

    for (int ch = 0; ch < SEQ / 64; ch++) {
        int kv0 = ch * 64;
        __syncthreads();
        {
            int r = tid >> 2, qo = (tid & 3) * 16;
            const unsigned* src = F.Km + (size_t)(base + kv0 + r) * kvld2 + hoff2 + qo;
            unsigned* dst = fsu + SK_O + r * 68 + qo;
            #pragma unroll
            for (int i = 0; i < 4; i++) *(uint4*)(dst + 4*i) = *(const uint4*)(src + 4*i);
        }
        {
            int kp = tid >> 3, dg = (tid & 7) * 8;
            const unsigned* v0p = F.Vm + (size_t)(base + kv0 + 2*kp) * kvld2 + hoff2 + dg;
            const unsigned* v1p = v0p + kvld2;
            unsigned lo[8], hi[8], o[16];
            *(uint4*)&lo[0] = *(const uint4*)v0p; *(uint4*)&lo[4] = *(const uint4*)(v0p + 4);
            *(uint4*)&hi[0] = *(const uint4*)v1p; *(uint4*)&hi[4] = *(const uint4*)(v1p + 4);
            #pragma unroll
            for (int i = 0; i < 8; i++) {
                o[2*i]   = __byte_perm(lo[i], hi[i], 0x5410);
                o[2*i+1] = __byte_perm(lo[i], hi[i], 0x7632);
            }
            unsigned* dst = fsu + SV_O + kp * 136 + dg * 2;
            #pragma unroll
            for (int i = 0; i < 4; i++) *(uint4*)(dst + 4*i) = *(uint4*)&o[4*i];
        }
        __syncthreads();

        float s[4][2][4];
        #pragma unroll
        for (int i = 0; i < 4; i++)
            #pragma unroll
            for (int j = 0; j < 2; j++)
                #pragma unroll
                for (int c = 0; c < 4; c++) s[i][j][c] = 0.f;

        #pragma unroll
        for (int ks = 0; ks < 8; ks++) {
            int kb = ks * 8;
            unsigned af[4][4], bf2[2][2];
            #pragma unroll
            for (int ma = 0; ma < 4; ma++) {
                int mb = (wm * 64 + ma * 16 + gid) * 68 + kb + tig;
                af[ma][0] = fsu[SQ_O + mb];
                af[ma][1] = fsu[SQ_O + mb + 544];
                af[ma][2] = fsu[SQ_O + mb + 4];
                af[ma][3] = fsu[SQ_O + mb + 548];
            }
            #pragma unroll
            for (int nb = 0; nb < 2; nb++) {
                int nbase = (wn * 16 + nb * 8 + gid) * 68 + kb + tig;
                bf2[nb][0] = fsu[SK_O + nbase];
                bf2[nb][1] = fsu[SK_O + nbase + 4];
            }
            #pragma unroll
            for (int ma = 0; ma < 4; ma++)
                #pragma unroll
                for (int nb = 0; nb < 2; nb++)
                    MMA_BF16(s[ma][nb], af[ma], bf2[nb]);
        }

        #pragma unroll
        for (int ma = 0; ma < 4; ma++)
            #pragma unroll
            for (int hf = 0; hf < 2; hf++) {
                float mx = fmaxf(fmaxf(s[ma][0][hf*2], s[ma][0][hf*2+1]),
                                 fmaxf(s[ma][1][hf*2], s[ma][1][hf*2+1])) * scale;
                mx = fmaxf(mx, __shfl_xor_sync(0xffffffffu, mx, 1));
                mx = fmaxf(mx, __shfl_xor_sync(0xffffffffu, mx, 2));
                if (tig == 0) sR1[(wm*64 + ma*16 + hf*8 + gid) * 4 + wn] = mx;
            }
        __syncthreads();

        #pragma unroll
        for (int ma = 0; ma < 4; ma++)
            #pragma unroll
            for (int hf = 0; hf < 2; hf++) {
                int r = wm*64 + ma*16 + hf*8 + gid;
                float cm = fmaxf(fmaxf(sR1[r*4+0], sR1[r*4+1]),
                                 fmaxf(sR1[r*4+2], sR1[r*4+3]));
                float nm = fmaxf(mrow[ma][hf], cm);
                float alpha = __expf(mrow[ma][hf] - nm);
                mrow[ma][hf] = nm;
                float p0 = __expf(s[ma][0][hf*2]   * scale - nm);
                float p1 = __expf(s[ma][0][hf*2+1] * scale - nm);
                float p2 = __expf(s[ma][1][hf*2]   * scale - nm);
                float p3 = __expf(s[ma][1][hf*2+1] * scale - nm);
                float sum = p0 + p1 + p2 + p3;
                sum += __shfl_xor_sync(0xffffffffu, sum, 1);
                sum += __shfl_xor_sync(0xffffffffu, sum, 2);
                if (tig == 0) sR2[r*4 + wn] = sum;
                lrow[ma][hf] *= alpha;
                #pragma unroll
                for (int nb = 0; nb < 4; nb++) {
                    oacc[ma][nb][hf*2]   *= alpha;
                    oacc[ma][nb][hf*2+1] *= alpha;
                }
                fsu[SP_O + r*36 + wn*8 + tig]     = packbf(p0, p1);
                fsu[SP_O + r*36 + wn*8 + 4 + tig] = packbf(p2, p3);
            }
        __syncthreads();

        #pragma unroll
        for (int ma = 0; ma < 4; ma++)
            #pragma unroll
            for (int hf = 0; hf < 2; hf++) {
                int r = wm*64 + ma*16 + hf*8 + gid;
                lrow[ma][hf] += sR2[r*4+0] + sR2[r*4+1] + sR2[r*4+2] + sR2[r*4+3];
            }

        #pragma unroll
        for (int ks = 0; ks < 4; ks++) {
            int kb = ks * 8;
            unsigned ap[4][4], bv[4][2];
            #pragma unroll
            for (int ma = 0; ma < 4; ma++) {
                int pb = (wm * 64 + ma * 16 + gid) * 36 + kb + tig;
                ap[ma][0] = fsu[SP_O + pb];
                ap[ma][1] = fsu[SP_O + pb + 288];
                ap[ma][2] = fsu[SP_O + pb + 4];
                ap[ma][3] = fsu[SP_O + pb + 292];
            }
            #pragma unroll
            for (int nb = 0; nb < 4; nb++) {
                int n0 = wn * 32 + nb * 8 + gid;
                bv[nb][0] = fsu[SV_O + (kb + tig) * 136 + n0];
                bv[nb][1] = fsu[SV_O + (kb + tig + 4) * 136 + n0];
            }
            #pragma unroll
            for (int ma = 0; ma < 4; ma++)
                #pragma unroll
                for (int nb = 0; nb < 4; nb++)
                    MMA_BF16(oacc[ma][nb], ap[ma], bv[nb]);
        }
    }

    #pragma unroll
    for (int ma = 0; ma < 4; ma++)
        #pragma unroll
        for (int hf = 0; hf < 2; hf++) {
            float inv = 1.0f / lrow[ma][hf];
            int gr = base + q0 + wm*64 + ma*16 + hf*8 + gid;
            #pragma unroll
            for (int nb = 0; nb < 4; nb++) {
                int cp = h*64 + wn*16 + nb*4 + tig;
                F.Om[(size_t)gr * 256 + cp] =
                    packbf(oacc[ma][nb][hf*2] * inv, oacc[ma][nb][hf*2+1] * inv);
            }
        }
}

// ============================================================
// Host orchestration
// ============================================================
static inline void run_gemm2(GB g0, GB g1, int N0, int N1, int K, int act, int nz) {
    cudaFuncSetAttribute(gemm_bf, cudaFuncAttributeMaxDynamicSharedMemorySize, GM_SMEM);
    int nmax = N0 > N1 ? N0 : N1;
    dim3 grid(nmax / 128, NTOK / 128, nz);
    gemm_bf<<<grid, 256, GM_SMEM>>>(g0, g1, N0, N1, K, act);
}

static inline void run_flash2(FB f0, FB f1, int qld2, int kvld2, int nz) {
    cudaFuncSetAttribute(flash_bf, cudaFuncAttributeMaxDynamicSharedMemorySize, FL_SMEM_BYTES);
    dim3 grid(SEQ / 128, NBH, nz);
    flash_bf<<<grid, 256, FL_SMEM_BYTES>>>(f0, f1, qld2, kvld2);
}

extern "C" void kernel_launch(void* const* d_in, const int* in_sizes, int n_in,
                              void* d_out, int out_size) {
    const float* x1    = (const float*)d_in[0];
    const float* x2    = (const float*)d_in[1];
    const float* ln1_g = (const float*)d_in[2];
    const float* ln1_b = (const float*)d_in[3];
    const float* ln2_g = (const float*)d_in[4];
    const float* ln2_b = (const float*)d_in[5];
    const float* lnf_g = (const float*)d_in[6];
    const float* lnf_b = (const float*)d_in[7];
    const float* Wq1 = (const float*)d_in[8],  *bq1 = (const float*)d_in[9];
    const float* Wk1 = (const float*)d_in[10], *bk1 = (const float*)d_in[11];
    const float* Wv1 = (const float*)d_in[12], *bv1 = (const float*)d_in[13];
    const float* Wq2 = (const float*)d_in[14], *bq2 = (const float*)d_in[15];
    const float* Wk2 = (const float*)d_in[16], *bk2 = (const float*)d_in[17];
    const float* Wv2 = (const float*)d_in[18], *bv2 = (const float*)d_in[19];
    const float* Wq12 = (const float*)d_in[20], *bq12 = (const float*)d_in[21];
    const float* Wk12 = (const float*)d_in[22], *bk12 = (const float*)d_in[23];
    const float* Wv12 = (const float*)d_in[24], *bv12 = (const float*)d_in[25];
    const float* Wo  = (const float*)d_in[26], *bo = (const float*)d_in[27];
    const float* W1  = (const float*)d_in[28], *b1 = (const float*)d_in[29];
    const float* W2  = (const float*)d_in[30], *b2 = (const float*)d_in[31];
    float* out = (float*)d_out;

    unsigned *x1n, *x2n, *qv, *qkv1, *qkv2, *ctx1, *ctx2, *s1, *s2, *h1, *wb;
    float *xres, *bc;
    cudaGetSymbolAddress((void**)&x1n,  g_x1n);
    cudaGetSymbolAddress((void**)&x2n,  g_x2n);
    cudaGetSymbolAddress((void**)&qv,   g_qv);
    cudaGetSymbolAddress((void**)&qkv1, g_qkv1);
    cudaGetSymbolAddress((void**)&qkv2, g_qkv2);
    cudaGetSymbolAddress((void**)&ctx1, g_ctx1);
    cudaGetSymbolAddress((void**)&ctx2, g_ctx2);
    cudaGetSymbolAddress((void**)&s1,   g_s1);
    cudaGetSymbolAddress((void**)&s2,   g_s2);
    cudaGetSymbolAddress((void**)&h1,   g_h1);
    cudaGetSymbolAddress((void**)&wb,   g_wb);
    cudaGetSymbolAddress((void**)&xres, g_x);
    cudaGetSymbolAddress((void**)&bc,   g_bc);

    unsigned* wS1t  = wb;
    unsigned* wS2t  = wb + 393216;
    unsigned* wCQt  = wb + 786432;
    unsigned* wCKVt = wb + 917504;
    unsigned* wWot  = wb + 1179648;
    unsigned* wW1t  = wb + 1310720;
    unsigned* wW2t  = wb + 1572864;

    // 0) merged prep: 12 transposes + bias concat, ONE launch
    Prep p;
    p.ws[0] = Wq1;  p.wd[0] = wS1t;
    p.ws[1] = Wk1;  p.wd[1] = wS1t + 131072;
    p.ws[2] = Wv1;  p.wd[2] = wS1t + 262144;
    p.ws[3] = Wq2;  p.wd[3] = wS2t;
    p.ws[4] = Wk2;  p.wd[4] = wS2t + 131072;
    p.ws[5] = Wv2;  p.wd[5] = wS2t + 262144;
    p.ws[6] = Wq12; p.wd[6] = wCQt;
    p.ws[7] = Wk12; p.wd[7] = wCKVt;
    p.ws[8] = Wv12; p.wd[8] = wCKVt + 131072;
    p.ws[9] = Wo;   p.wd[9] = wWot;
    p.ws[10] = W1;  p.wd[10] = wW1t;
    p.ws[11] = W2;  p.wd[11] = wW2t;
    p.bs[0]=bq1; p.bs[1]=bk1; p.bs[2]=bv1; p.bs[3]=bq2;
    p.bs[4]=bk2; p.bs[5]=bv2; p.bs[6]=bk12; p.bs[7]=bv12;
    p.bdst = bc;
    prep_kernel<<<3586, dim3(32, 8)>>>(p);
    float* bS1 = bc, *bS2 = bc + 1536, *bCKV = bc + 3072;

    // 1) pre-LN, both streams in one launch
    ln_kernel<<<dim3(NTOK, 2), 256>>>(x1, ln1_g, ln1_b, x1n,
                                      x2, ln2_g, ln2_b, x2n);

    // 2+3) both self-attentions, batched over z
    GB q0 = {x1n, wS1t, bS1, nullptr, nullptr, nullptr, qkv1};
    GB q1 = {x2n, wS2t, bS2, nullptr, nullptr, nullptr, qkv2};
    run_gemm2(q0, q1, 1536, 1536, 512, 0, 2);

    FB fa = {qkv1, qkv1 + 256, qkv1 + 512, ctx1};
    FB fb = {qkv2, qkv2 + 256, qkv2 + 512, ctx2};
    run_flash2(fa, fb, 768, 768, 2);

    GB w0 = {ctx1, wWot, bo, nullptr, x1n, nullptr, s1};
    GB w1 = {ctx2, wWot, bo, nullptr, x2n, nullptr, s2};
    run_gemm2(w0, w1, 512, 512, 512, 0, 2);

    // 4) cross-attention: cq (z=0, N=512) + ckv (z=1, N=1024) in one launch
    GB c0 = {s1, wCQt, bq12, nullptr, nullptr, nullptr, qv};
    GB c1 = {s2, wCKVt, bCKV, nullptr, nullptr, nullptr, qkv1};
    run_gemm2(c0, c1, 512, 1024, 512, 0, 2);

    FB fc = {qv, qkv1, qkv1 + 256, ctx1};
    run_flash2(fc, fc, 256, 512, 1);

    GB wc = {ctx1, wWot, bo, x1, nullptr, xres, nullptr};
    run_gemm2(wc, wc, 512, 512, 512, 0, 1);

    // 5) final LN + MLP
    ln_kernel<<<dim3(NTOK, 1), 256>>>(xres, lnf_g, lnf_b, x1n,
                                      xres, lnf_g, lnf_b, x1n);
    GB m1 = {x1n, wW1t, b1, nullptr, nullptr, nullptr, h1};
    run_gemm2(m1, m1, 1024, 1024, 512, 1, 1);
    GB m2 = {h1, wW2t, b2, xres, nullptr, out, nullptr};
    run_gemm2(m2, m2, 512, 512, 1024, 0, 1);
    (void)in_sizes; (void)n_in; (void)out_size;
}

// round 12
// speedup vs baseline: 2.2647x; 1.0746x over previous
#include <cuda_runtime.h>
#include <cuda_bf16.h>
#include <math.h>
#include <stdint.h>

// Problem constants
#define BATCH 16
#define SEQ   1024
#define NTOK  (BATCH*SEQ)        // 16384
#define DMODEL 512
#define NHEAD  4
#define HDIM   128
#define DMLP   1024
#define NBH    (BATCH*NHEAD)     // 64

// -------- scratch (no cudaMalloc allowed). bf16 tensors stored as packed u32 pairs.
__device__ unsigned g_x1n[NTOK*256];
__device__ unsigned g_x2n[NTOK*256];
__device__ unsigned g_qv [NTOK*256];
__device__ unsigned g_qkv1[NTOK*768];
__device__ unsigned g_qkv2[NTOK*768];
__device__ unsigned g_ctx1[NTOK*256];
__device__ unsigned g_ctx2[NTOK*256];
__device__ unsigned g_s1 [NTOK*256];
__device__ unsigned g_s2 [NTOK*256];
__device__ float    g_x  [NTOK*DMODEL];
__device__ unsigned g_h1 [NTOK*512];
__device__ unsigned g_wb [1835008];
__device__ float    g_bc [4096];
// pre-transposed V: [bh][token-pair][d] u32 (token-pair packed bf16)
__device__ unsigned g_vt1[NBH*512*128];
__device__ unsigned g_vt2[NBH*512*128];

extern __shared__ unsigned dsm[];

// ---------- helpers ----------
__device__ __forceinline__ unsigned packbf(float a, float b) {
    __nv_bfloat162 h = __floats2bfloat162_rn(a, b);
    return *reinterpret_cast<unsigned*>(&h);
}
__device__ __forceinline__ float2 unpackbf(unsigned u) {
    __nv_bfloat162 h = *reinterpret_cast<__nv_bfloat162*>(&u);
    return __bfloat1622float2(h);
}
__device__ __forceinline__ uint32_t smem_u32(const void* p) {
    uint32_t a;
    asm("{ .reg .u64 t; cvta.to.shared.u64 t, %1; cvt.u32.u64 %0, t; }" : "=r"(a) : "l"(p));
    return a;
}

#define MMA_BF16(acc, a, b) \
    asm volatile("mma.sync.aligned.m16n8k16.row.col.f32.bf16.bf16.f32 " \
        "{%0,%1,%2,%3}, {%4,%5,%6,%7}, {%8,%9}, {%0,%1,%2,%3};\n" \
        : "+f"((acc)[0]), "+f"((acc)[1]), "+f"((acc)[2]), "+f"((acc)[3]) \
        : "r"((a)[0]), "r"((a)[1]), "r"((a)[2]), "r"((a)[3]), "r"((b)[0]), "r"((b)[1]))

#define CP16(daddr, src) \
    asm volatile("cp.async.cg.shared.global [%0], [%1], 16;" :: "r"(daddr), "l"(src))
#define CPCOMMIT() asm volatile("cp.async.commit_group;" ::: "memory")
#define CPWAIT(n)  asm volatile("cp.async.wait_group %0;" :: "n"(n) : "memory")

// ============================================================
// Merged prep: 12 weight transposes + bias concat (one launch)
// ============================================================
struct Prep {
    const float* ws[12]; unsigned* wd[12];
    const float* bs[8];  float* bdst;
};

__device__ __forceinline__ void tile_transpose(const float* __restrict__ in,
                                               unsigned* __restrict__ out,
                                               int K, int N, int bx, int by) {
    __shared__ float t[32][33];
    int k0 = bx * 32, n0 = by * 32;
    int tx = threadIdx.x, ty = threadIdx.y;
    #pragma unroll
    for (int i = 0; i < 4; i++)
        t[ty + i*8][tx] = in[(size_t)(k0 + ty + i*8) * N + n0 + tx];
    __syncthreads();
    #pragma unroll
    for (int i = 0; i < 2; i++) {
        int kp = ty + 8 * i;
        out[(size_t)(n0 + tx) * (K >> 1) + (k0 >> 1) + kp] =
            packbf(t[2*kp][tx], t[2*kp+1][tx]);
    }
}

__global__ void prep_kernel(Prep p) {
    int id = blockIdx.x;
    if (id < 2560) {
        int m = id >> 8, t = id & 255;
        tile_transpose(p.ws[m], p.wd[m], 512, 512, t & 15, t >> 4);
    } else if (id < 3072) {
        int t = id - 2560;
        tile_transpose(p.ws[10], p.wd[10], 512, 1024, t & 15, t >> 4);
    } else if (id < 3584) {
        int t = id - 3072;
        tile_transpose(p.ws[11], p.wd[11], 1024, 512, t & 31, t >> 5);
    } else {
        int t = threadIdx.y * 32 + threadIdx.x;
        int i0 = (id - 3584) * 2048 + t * 8;
        #pragma unroll
        for (int j = 0; j < 8; j++) {
            int i = i0 + j;
            p.bdst[i] = p.bs[i >> 9][i & 511];
        }
    }
}

// ============================================================
// Batched LayerNorm: fp32 in, bf16 (packed) out.
// ============================================================
__global__ void ln_kernel(const float* __restrict__ xA, const float* __restrict__ gA,
                          const float* __restrict__ bA, unsigned* __restrict__ oA,
                          const float* __restrict__ xB, const float* __restrict__ gB,
                          const float* __restrict__ bB, unsigned* __restrict__ oB) {
    const float* x = blockIdx.y ? xB : xA;
    const float* g = blockIdx.y ? gB : gA;
    const float* b = blockIdx.y ? bB : bA;
    unsigned* out  = blockIdx.y ? oB : oA;

    int row = blockIdx.x;
    const float* xr = x + (size_t)row * DMODEL;
    unsigned* orow = out + (size_t)row * 256;
    int tid = threadIdx.x;
    float v0 = xr[2*tid], v1 = xr[2*tid + 1];

    __shared__ float sm[8];
    float s = v0 + v1;
    #pragma unroll
    for (int o = 16; o; o >>= 1) s += __shfl_xor_sync(0xffffffffu, s, o);
    if ((tid & 31) == 0) sm[tid >> 5] = s;
    __syncthreads();
    if (tid == 0) {
        float t = 0.f;
        #pragma unroll
        for (int i = 0; i < 8; i++) t += sm[i];
        sm[0] = t * (1.0f / DMODEL);
    }
    __syncthreads();
    float mean = sm[0];
    __syncthreads();

    float d0 = v0 - mean, d1 = v1 - mean;
    float q = d0 * d0 + d1 * d1;
    #pragma unroll
    for (int o = 16; o; o >>= 1) q += __shfl_xor_sync(0xffffffffu, q, o);
    if ((tid & 31) == 0) sm[tid >> 5] = q;
    __syncthreads();
    if (tid == 0) {
        float t = 0.f;
        #pragma unroll
        for (int i = 0; i < 8; i++) t += sm[i];
        sm[0] = rsqrtf(t * (1.0f / DMODEL) + 1e-6f);
    }
    __syncthreads();
    float rstd = sm[0];

    float y0 = d0 * rstd * g[2*tid]     + b[2*tid];
    float y1 = d1 * rstd * g[2*tid + 1] + b[2*tid + 1];
    orow[tid] = packbf(y0, y1);
}

// ============================================================
// bf16 GEMM with cp.async 4-stage pipeline, z-batched (2 slices).
// Optional Vt epilogue: for columns >= vcol0, also emit a
// pre-transposed token-pair-packed V copy (for flash).
// ============================================================
#define GM_STAGE 3072
#define GM_SMEM  (4 * GM_STAGE * 4)

struct GB {
    const unsigned* A; const unsigned* BT; const float* bias;
    const float* addf; const unsigned* addb;
    float* Cf; unsigned* Cb;
    unsigned* Vt; int vcol0;
};

__global__ void __launch_bounds__(256, 2)
gemm_bf(GB g0, GB g1, int N0, int N1, int K, int act)
{
    GB G = blockIdx.z ? g1 : g0;
    int N = blockIdx.z ? N1 : N0;
    int bn = blockIdx.x * 128;
    if (bn >= N) return;

    uint32_t sb = smem_u32(dsm);
    int bm = blockIdx.y * 128;
    int tid = threadIdx.x;
    int warp = tid >> 5, lane = tid & 31;
    int wm = warp >> 2, wn = warp & 3;
    int gid = lane >> 2, tig = lane & 3;
    int lda2 = K >> 1;
    int chunks = K >> 4;

    int crow = tid >> 1, cseg = tid & 1;
    const unsigned* Asrc = G.A + (size_t)(bm + crow) * lda2 + cseg * 4;
    const unsigned* Bsrc = G.BT + (size_t)(bn + crow) * lda2 + cseg * 4;
    int dsto = crow * 12 + cseg * 4;

    float acc[4][4][4];
    #pragma unroll
    for (int i = 0; i < 4; i++)
        #pragma unroll
        for (int j = 0; j < 4; j++)
            #pragma unroll
            for (int c = 0; c < 4; c++) acc[i][j][c] = 0.f;

    #pragma unroll
    for (int c = 0; c < 3; c++) {
        int st = c & 3;
        CP16(sb + (st * GM_STAGE + dsto) * 4, Asrc + c * 8);
        CP16(sb + (st * GM_STAGE + 1536 + dsto) * 4, Bsrc + c * 8);
        CPCOMMIT();
    }

    for (int c = 0; c < chunks; c++) {
        CPWAIT(2);
        __syncthreads();
        if (c + 3 < chunks) {
            int st = (c + 3) & 3;
            CP16(sb + (st * GM_STAGE + dsto) * 4, Asrc + (c + 3) * 8);
            CP16(sb + (st * GM_STAGE + 1536 + dsto) * 4, Bsrc + (c + 3) * 8);
        }
        CPCOMMIT();

        unsigned* As = dsm + (c & 3) * GM_STAGE;
        unsigned* Bs = As + 1536;
        unsigned af[4][4], bf2[4][2];
        #pragma unroll
        for (int ma = 0; ma < 4; ma++) {
            int mb = (wm * 64 + ma * 16 + gid) * 12 + tig;
            af[ma][0] = As[mb];
            af[ma][1] = As[mb + 96];
            af[ma][2] = As[mb + 4];
            af[ma][3] = As[mb + 100];
        }
        #pragma unroll
        for (int nb = 0; nb < 4; nb++) {
            int nbase = (wn * 32 + nb * 8 + gid) * 12 + tig;
            bf2[nb][0] = Bs[nbase];
            bf2[nb][1] = Bs[nbase + 4];
        }
        #pragma unroll
        for (int ma = 0; ma < 4; ma++)
            #pragma unroll
            for (int nb = 0; nb < 4; nb++)
                MMA_BF16(acc[ma][nb], af[ma], bf2[nb]);
    }

    // epilogue
    #pragma unroll
    for (int ma = 0; ma < 4; ma++) {
        #pragma unroll
        for (int nb = 0; nb < 4; nb++) {
            int c = bn + wn * 32 + nb * 8 + tig * 2;
            float bv0 = G.bias ? G.bias[c] : 0.f;
            float bv1 = G.bias ? G.bias[c + 1] : 0.f;
            #pragma unroll
            for (int half = 0; half < 2; half++) {
                int r = bm + wm * 64 + ma * 16 + gid + half * 8;
                float t0 = acc[ma][nb][half * 2 + 0] + bv0;
                float t1 = acc[ma][nb][half * 2 + 1] + bv1;
                if (act) {
                    t0 = 0.5f * t0 * (1.0f + erff(t0 * 0.70710678118654752f));
                    t1 = 0.5f * t1 * (1.0f + erff(t1 * 0.70710678118654752f));
                }
                size_t off = (size_t)r * N + c;
                if (G.addf) { t0 += G.addf[off]; t1 += G.addf[off + 1]; }
                if (G.addb) {
                    float2 av = unpackbf(G.addb[(size_t)r * (N >> 1) + (c >> 1)]);
                    t0 += av.x; t1 += av.y;
                }
                if (G.Cf) *(float2*)&G.Cf[off] = make_float2(t0, t1);
                if (G.Cb) G.Cb[(size_t)r * (N >> 1) + (c >> 1)] = packbf(t0, t1);
                // pre-transposed V emit (pairs rows r, r+1 via shfl across gid^1)
                if (G.Vt && c >= G.vcol0) {
                    float u0 = __shfl_xor_sync(0xffffffffu, t0, 4);
                    float u1 = __shfl_xor_sync(0xffffffffu, t1, 4);
                    if (!(gid & 1)) {
                        int d = c - G.vcol0;            // element 0..511
                        int h = d >> 7, dh = d & 127;
                        int bb = r >> 10, tp = (r & 1023) >> 1;
                        size_t vo = (((size_t)(bb * 4 + h) * 512) + tp) * 128 + dh;
                        G.Vt[vo]     = packbf(t0, u0);
                        G.Vt[vo + 1] = packbf(t1, u1);
                    }
                }
            }
        }
    }
}

// ============================================================
// bf16 flash attention: K double-buffered + V (pre-transposed)
// via cp.async; compute math identical to R9. 16 KV chunks of 64.
// smem u32: sQ 128x68 @0; sK[2] 64x68 @8704; sV 32x136 @17408;
// sP 128x36 @21760; R1 @26368; R2 @26880. Total 27392 u32.
// ============================================================
#define SQ_O 0
#define SK_O 8704
#define SV_O 17408
#define SP_O 21760
#define R1_O 26368
#define R2_O 26880
#define FL_SMEM_BYTES (27392 * 4)
#define NCH 16   // SEQ / 64

struct FB { const unsigned* Qm; const unsigned* Km; const unsigned* Vt; unsigned* Om; };

__global__ void __launch_bounds__(256, 2)
flash_bf(FB f0, FB f1, int qld2, int kvld2)
{
    FB F = blockIdx.z ? f1 : f0;
    unsigned* fsu = dsm;
    float* sR1 = (float*)(fsu + R1_O);
    float* sR2 = (float*)(fsu + R2_O);
    uint32_t sb = smem_u32(dsm);

    int tid = threadIdx.x;
    int warp = tid >> 5, lane = tid & 31;
    int wm = warp >> 2, wn = warp & 3;
    int gid = lane >> 2, tig = lane & 3;

    int bh = blockIdx.y, b = bh >> 2, h = bh & 3;
    int q0 = blockIdx.x * 128, base = b * SEQ;
    int hoff2 = h * 64;

    // prologue group: Q (128x64 u32) + K(0) (64x64 u32)
    {
        #pragma unroll
        for (int i = 0; i < 8; i++) {
            int seg = tid + 256 * i;
            int r = seg >> 4, sg = seg & 15;
            CP16(sb + (SQ_O + r * 68 + sg * 4) * 4,
                 F.Qm + (size_t)(base + q0 + r) * qld2 + hoff2 + sg * 4);
        }
        #pragma unroll
        for (int i = 0; i < 4; i++) {
            int seg = tid + 256 * i;
            int r = seg >> 4, sg = seg & 15;
            CP16(sb + (SK_O + r * 68 + sg * 4) * 4,
                 F.Km + (size_t)(base + r) * kvld2 + hoff2 + sg * 4);
        }
        CPCOMMIT();
    }

    float oacc[4][4][4];
    #pragma unroll
    for (int i = 0; i < 4; i++)
        #pragma unroll
        for (int j = 0; j < 4; j++)
            #pragma unroll
            for (int c = 0; c < 4; c++) oacc[i][j][c] = 0.f;
    float mrow[4][2], lrow[4][2];
    #pragma unroll
    for (int i = 0; i < 4; i++) { mrow[i][0] = -1e30f; mrow[i][1] = -1e30f;
                                  lrow[i][0] = 0.f;    lrow[i][1] = 0.f; }

    const float scale = 0.08838834764831845f;

    for (int ch = 0; ch < NCH; ch++) {
        int kbuf = ch & 1;
        __syncthreads();   // prev PV readers done with sV; prev S done with K[kbuf^1]
        // group A: V(ch) straight copy from pre-transposed Vt (32 pairs x 128 u32)
        #pragma unroll
        for (int i = 0; i < 4; i++) {
            int seg = tid + 256 * i;
            int row = seg >> 5, sg = seg & 31;
            CP16(sb + (SV_O + row * 136 + sg * 4) * 4,
                 F.Vt + (((size_t)bh * 512) + ch * 32 + row) * 128 + sg * 4);
        }
        CPCOMMIT();
        // group B: K(ch+1)
        if (ch + 1 < NCH) {
            #pragma unroll
            for (int i = 0; i < 4; i++) {
                int seg = tid + 256 * i;
                int r = seg >> 4, sg = seg & 15;
                CP16(sb + (SK_O + (kbuf ^ 1) * 4352 + r * 68 + sg * 4) * 4,
                     F.Km + (size_t)(base + (ch + 1) * 64 + r) * kvld2 + hoff2 + sg * 4);
            }
        }
        CPCOMMIT();
        CPWAIT(2);          // Q + K(ch) complete
        __syncthreads();

        // S = Q @ K^T : warp tile 64x16 (ma 4, nb 2), 8 k-steps of 16
        float s[4][2][4];
        #pragma unroll
        for (int i = 0; i < 4; i++)
            #pragma unroll
            for (int j = 0; j < 2; j++)
                #pragma unroll
                for (int c = 0; c < 4; c++) s[i][j][c] = 0.f;

        int skb = SK_O + kbuf * 4352;
        #pragma unroll
        for (int ks = 0; ks < 8; ks++) {
            int kb = ks * 8;
            unsigned af[4][4], bf2[2][2];
            #pragma unroll
            for (int ma = 0; ma < 4; ma++) {
                int mb = (wm * 64 + ma * 16 + gid) * 68 + kb + tig;
                af[ma][0] = fsu[SQ_O + mb];
                af[ma][1] = fsu[SQ_O + mb + 544];
                af[ma][2] = fsu[SQ_O + mb + 4];
                af[ma][3] = fsu[SQ_O + mb + 548];
            }
            #pragma unroll
            for (int nb = 0; nb < 2; nb++) {
                int nbase = (wn * 16 + nb * 8 + gid) * 68 + kb + tig;
                bf2[nb][0] = fsu[skb + nbase];
                bf2[nb][1] = fsu[skb + nbase + 4];
            }
            #pragma unroll
            for (int ma = 0; ma < 4; ma++)
                #pragma unroll
                for (int nb = 0; nb < 2; nb++)
                    MMA_BF16(s[ma][nb], af[ma], bf2[nb]);
        }

        // online softmax pass 1
        #pragma unroll
        for (int ma = 0; ma < 4; ma++)
            #pragma unroll
            for (int hf = 0; hf < 2; hf++) {
                float mx = fmaxf(fmaxf(s[ma][0][hf*2], s[ma][0][hf*2+1]),
                                 fmaxf(s[ma][1][hf*2], s[ma][1][hf*2+1])) * scale;
                mx = fmaxf(mx, __shfl_xor_sync(0xffffffffu, mx, 1));
                mx = fmaxf(mx, __shfl_xor_sync(0xffffffffu, mx, 2));
                if (tig == 0) sR1[(wm*64 + ma*16 + hf*8 + gid) * 4 + wn] = mx;
            }
        __syncthreads();

        // pass 2
        #pragma unroll
        for (int ma = 0; ma < 4; ma++)
            #pragma unroll
            for (int hf = 0; hf < 2; hf++) {
                int r = wm*64 + ma*16 + hf*8 + gid;
                float cm = fmaxf(fmaxf(sR1[r*4+0], sR1[r*4+1]),
                                 fmaxf(sR1[r*4+2], sR1[r*4+3]));
                float nm = fmaxf(mrow[ma][hf], cm);
                float alpha = __expf(mrow[ma][hf] - nm);
                mrow[ma][hf] = nm;
                float p0 = __expf(s[ma][0][hf*2]   * scale - nm);
                float p1 = __expf(s[ma][0][hf*2+1] * scale - nm);
                float p2 = __expf(s[ma][1][hf*2]   * scale - nm);
                float p3 = __expf(s[ma][1][hf*2+1] * scale - nm);
                float sum = p0 + p1 + p2 + p3;
                sum += __shfl_xor_sync(0xffffffffu, sum, 1);
                sum += __shfl_xor_sync(0xffffffffu, sum, 2);
                if (tig == 0) sR2[r*4 + wn] = sum;
                lrow[ma][hf] *= alpha;
                #pragma unroll
                for (int nb = 0; nb < 4; nb++) {
                    oacc[ma][nb][hf*2]   *= alpha;
                    oacc[ma][nb][hf*2+1] *= alpha;
                }
                fsu[SP_O + r*36 + wn*8 + tig]     = packbf(p0, p1);
                fsu[SP_O + r*36 + wn*8 + 4 + tig] = packbf(p2, p3);
            }
        CPWAIT(1);          // V(ch) complete (only K(ch+1) may remain in flight)
        __syncthreads();    // sP/sR2 + V visible

        #pragma unroll
        for (int ma = 0; ma < 4; ma++)
            #pragma unroll
            for (int hf = 0; hf < 2; hf++) {
                int r = wm*64 + ma*16 + hf*8 + gid;
                lrow[ma][hf] += sR2[r*4+0] + sR2[r*4+1] + sR2[r*4+2] + sR2[r*4+3];
            }

        // O += P @ V
        #pragma unroll
        for (int ks = 0; ks < 4; ks++) {
            int kb = ks * 8;
            unsigned ap[4][4], bv[4][2];
            #pragma unroll
            for (int ma = 0; ma < 4; ma++) {
                int pb = (wm * 64 + ma * 16 + gid) * 36 + kb + tig;
                ap[ma][0] = fsu[SP_O + pb];
                ap[ma][1] = fsu[SP_O + pb + 288];
                ap[ma][2] = fsu[SP_O + pb + 4];
                ap[ma][3] = fsu[SP_O + pb + 292];
            }
            #pragma unroll
            for (int nb = 0; nb < 4; nb++) {
                int n0 = wn * 32 + nb * 8 + gid;
                bv[nb][0] = fsu[SV_O + (kb + tig) * 136 + n0];
                bv[nb][1] = fsu[SV_O + (kb + tig + 4) * 136 + n0];
            }
            #pragma unroll
            for (int ma = 0; ma < 4; ma++)
                #pragma unroll
                for (int nb = 0; nb < 4; nb++)
                    MMA_BF16(oacc[ma][nb], ap[ma], bv[nb]);
        }
    }

    // epilogue
    #pragma unroll
    for (int ma = 0; ma < 4; ma++)
        #pragma unroll
        for (int hf = 0; hf < 2; hf++) {
            float inv = 1.0f / lrow[ma][hf];
            int gr = base + q0 + wm*64 + ma*16 + hf*8 + gid;
            #pragma unroll
            for (int nb = 0; nb < 4; nb++) {
                int cp = h*64 + wn*16 + nb*4 + tig;
                F.Om[(size_t)gr * 256 + cp] =
                    packbf(oacc[ma][nb][hf*2] * inv, oacc[ma][nb][hf*2+1] * inv);
            }
        }
}

// ============================================================
// Host orchestration
// ============================================================
static inline void run_gemm2(GB g0, GB g1, int N0, int N1, int K, int act, int nz) {
    cudaFuncSetAttribute(gemm_bf, cudaFuncAttributeMaxDynamicSharedMemorySize, GM_SMEM);
    int nmax = N0 > N1 ? N0 : N1;
    dim3 grid(nmax / 128, NTOK / 128, nz);
    gemm_bf<<<grid, 256, GM_SMEM>>>(g0, g1, N0, N1, K, act);
}

static inline void run_flash2(FB f0, FB f1, int qld2, int kvld2, int nz) {
    cudaFuncSetAttribute(flash_bf, cudaFuncAttributeMaxDynamicSharedMemorySize, FL_SMEM_BYTES);
    dim3 grid(SEQ / 128, NBH, nz);
    flash_bf<<<grid, 256, FL_SMEM_BYTES>>>(f0, f1, qld2, kvld2);
}

extern "C" void kernel_launch(void* const* d_in, const int* in_sizes, int n_in,
                              void* d_out, int out_size) {
    const float* x1    = (const float*)d_in[0];
    const float* x2    = (const float*)d_in[1];
    const float* ln1_g = (const float*)d_in[2];
    const float* ln1_b = (const float*)d_in[3];
    const float* ln2_g = (const float*)d_in[4];
    const float* ln2_b = (const float*)d_in[5];
    const float* lnf_g = (const float*)d_in[6];
    const float* lnf_b = (const float*)d_in[7];
    const float* Wq1 = (const float*)d_in[8],  *bq1 = (const float*)d_in[9];
    const float* Wk1 = (const float*)d_in[10], *bk1 = (const float*)d_in[11];
    const float* Wv1 = (const float*)d_in[12], *bv1 = (const float*)d_in[13];
    const float* Wq2 = (const float*)d_in[14], *bq2 = (const float*)d_in[15];
    const float* Wk2 = (const float*)d_in[16], *bk2 = (const float*)d_in[17];
    const float* Wv2 = (const float*)d_in[18], *bv2 = (const float*)d_in[19];
    const float* Wq12 = (const float*)d_in[20], *bq12 = (const float*)d_in[21];
    const float* Wk12 = (const float*)d_in[22], *bk12 = (const float*)d_in[23];
    const float* Wv12 = (const float*)d_in[24], *bv12 = (const float*)d_in[25];
    const float* Wo  = (const float*)d_in[26], *bo = (const float*)d_in[27];
    const float* W1  = (const float*)d_in[28], *b1 = (const float*)d_in[29];
    const float* W2  = (const float*)d_in[30], *b2 = (const float*)d_in[31];
    float* out = (float*)d_out;

    unsigned *x1n, *x2n, *qv, *qkv1, *qkv2, *ctx1, *ctx2, *s1, *s2, *h1, *wb, *vt1, *vt2;
    float *xres, *bc;
    cudaGetSymbolAddress((void**)&x1n,  g_x1n);
    cudaGetSymbolAddress((void**)&x2n,  g_x2n);
    cudaGetSymbolAddress((void**)&qv,   g_qv);
    cudaGetSymbolAddress((void**)&qkv1, g_qkv1);
    cudaGetSymbolAddress((void**)&qkv2, g_qkv2);
    cudaGetSymbolAddress((void**)&ctx1, g_ctx1);
    cudaGetSymbolAddress((void**)&ctx2, g_ctx2);
    cudaGetSymbolAddress((void**)&s1,   g_s1);
    cudaGetSymbolAddress((void**)&s2,   g_s2);
    cudaGetSymbolAddress((void**)&h1,   g_h1);
    cudaGetSymbolAddress((void**)&wb,   g_wb);
    cudaGetSymbolAddress((void**)&vt1,  g_vt1);
    cudaGetSymbolAddress((void**)&vt2,  g_vt2);
    cudaGetSymbolAddress((void**)&xres, g_x);
    cudaGetSymbolAddress((void**)&bc,   g_bc);

    unsigned* wS1t  = wb;
    unsigned* wS2t  = wb + 393216;
    unsigned* wCQt  = wb + 786432;
    unsigned* wCKVt = wb + 917504;
    unsigned* wWot  = wb + 1179648;
    unsigned* wW1t  = wb + 1310720;
    unsigned* wW2t  = wb + 1572864;

    // 0) merged prep
    Prep p;
    p.ws[0] = Wq1;  p.wd[0] = wS1t;
    p.ws[1] = Wk1;  p.wd[1] = wS1t + 131072;
    p.ws[2] = Wv1;  p.wd[2] = wS1t + 262144;
    p.ws[3] = Wq2;  p.wd[3] = wS2t;
    p.ws[4] = Wk2;  p.wd[4] = wS2t + 131072;
    p.ws[5] = Wv2;  p.wd[5] = wS2t + 262144;
    p.ws[6] = Wq12; p.wd[6] = wCQt;
    p.ws[7] = Wk12; p.wd[7] = wCKVt;
    p.ws[8] = Wv12; p.wd[8] = wCKVt + 131072;
    p.ws[9] = Wo;   p.wd[9] = wWot;
    p.ws[10] = W1;  p.wd[10] = wW1t;
    p.ws[11] = W2;  p.wd[11] = wW2t;
    p.bs[0]=bq1; p.bs[1]=bk1; p.bs[2]=bv1; p.bs[3]=bq2;
    p.bs[4]=bk2; p.bs[5]=bv2; p.bs[6]=bk12; p.bs[7]=bv12;
    p.bdst = bc;
    prep_kernel<<<3586, dim3(32, 8)>>>(p);
    float* bS1 = bc, *bS2 = bc + 1536, *bCKV = bc + 3072;

    // 1) pre-LN, both streams
    ln_kernel<<<dim3(NTOK, 2), 256>>>(x1, ln1_g, ln1_b, x1n,
                                      x2, ln2_g, ln2_b, x2n);

    // 2+3) both self-attentions, z-batched; qkv gemm also emits Vt
    GB q0 = {x1n, wS1t, bS1, nullptr, nullptr, nullptr, qkv1, vt1, 1024};
    GB q1 = {x2n, wS2t, bS2, nullptr, nullptr, nullptr, qkv2, vt2, 1024};
    run_gemm2(q0, q1, 1536, 1536, 512, 0, 2);

    FB fa = {qkv1, qkv1 + 256, vt1, ctx1};
    FB fb = {qkv2, qkv2 + 256, vt2, ctx2};
    run_flash2(fa, fb, 768, 768, 2);

    GB w0 = {ctx1, wWot, bo, nullptr, x1n, nullptr, s1, nullptr, 0};
    GB w1 = {ctx2, wWot, bo, nullptr, x2n, nullptr, s2, nullptr, 0};
    run_gemm2(w0, w1, 512, 512, 512, 0, 2);

    // 4) cross-attention: cq (N=512) + ckv (N=1024, V part -> vt1 reuse)
    GB c0 = {s1, wCQt, bq12, nullptr, nullptr, nullptr, qv, nullptr, 0};
    GB c1 = {s2, wCKVt, bCKV, nullptr, nullptr, nullptr, qkv1, vt1, 512};
    run_gemm2(c0, c1, 512, 1024, 512, 0, 2);

    FB fc = {qv, qkv1, vt1, ctx1};
    run_flash2(fc, fc, 256, 512, 1);

    GB wc = {ctx1, wWot, bo, x1, nullptr, xres, nullptr, nullptr, 0};
    run_gemm2(wc, wc, 512, 512, 512, 0, 1);

    // 5) final LN + MLP
    ln_kernel<<<dim3(NTOK, 1), 256>>>(xres, lnf_g, lnf_b, x1n,
                                      xres, lnf_g, lnf_b, x1n);
    GB m1 = {x1n, wW1t, b1, nullptr, nullptr, nullptr, h1, nullptr, 0};
    run_gemm2(m1, m1, 1024, 1024, 512, 1, 1);
    GB m2 = {h1, wW2t, b2, xres, nullptr, out, nullptr, nullptr, 0};
    run_gemm2(m2, m2, 512, 512, 1024, 0, 1);
    (void)in_sizes; (void)n_in; (void)out_size;
}

// round 13
// speedup vs baseline: 2.4219x; 1.0694x over previous
#include <cuda_runtime.h>
#include <cuda_bf16.h>
#include <math.h>
#include <stdint.h>

// Problem constants
#define BATCH 16
#define SEQ   1024
#define NTOK  (BATCH*SEQ)        // 16384
#define DMODEL 512
#define NHEAD  4
#define HDIM   128
#define DMLP   1024
#define NBH    (BATCH*NHEAD)     // 64

// -------- scratch (no cudaMalloc allowed). bf16 tensors stored as packed u32 pairs.
__device__ unsigned g_x1n[NTOK*256];
__device__ unsigned g_x2n[NTOK*256];
__device__ unsigned g_qv [NTOK*256];
__device__ unsigned g_qkv1[NTOK*768];
__device__ unsigned g_qkv2[NTOK*768];
__device__ unsigned g_ctx1[NTOK*256];
__device__ unsigned g_ctx2[NTOK*256];
__device__ unsigned g_s1 [NTOK*256];
__device__ unsigned g_s2 [NTOK*256];
__device__ float    g_x  [NTOK*DMODEL];
__device__ unsigned g_h1 [NTOK*512];
__device__ unsigned g_wb [1835008];
__device__ float    g_bc [4096];
// pre-transposed V: [bh][token-pair][d] u32 (token-pair packed bf16)
__device__ unsigned g_vt1[NBH*512*128];
__device__ unsigned g_vt2[NBH*512*128];

extern __shared__ unsigned dsm[];

// ---------- helpers ----------
__device__ __forceinline__ unsigned packbf(float a, float b) {
    __nv_bfloat162 h = __floats2bfloat162_rn(a, b);
    return *reinterpret_cast<unsigned*>(&h);
}
__device__ __forceinline__ float2 unpackbf(unsigned u) {
    __nv_bfloat162 h = *reinterpret_cast<__nv_bfloat162*>(&u);
    return __bfloat1622float2(h);
}
__device__ __forceinline__ uint32_t smem_u32(const void* p) {
    uint32_t a;
    asm("{ .reg .u64 t; cvta.to.shared.u64 t, %1; cvt.u32.u64 %0, t; }" : "=r"(a) : "l"(p));
    return a;
}

#define MMA_BF16(acc, a, b) \
    asm volatile("mma.sync.aligned.m16n8k16.row.col.f32.bf16.bf16.f32 " \
        "{%0,%1,%2,%3}, {%4,%5,%6,%7}, {%8,%9}, {%0,%1,%2,%3};\n" \
        : "+f"((acc)[0]), "+f"((acc)[1]), "+f"((acc)[2]), "+f"((acc)[3]) \
        : "r"((a)[0]), "r"((a)[1]), "r"((a)[2]), "r"((a)[3]), "r"((b)[0]), "r"((b)[1]))

#define CP16(daddr, src) \
    asm volatile("cp.async.cg.shared.global [%0], [%1], 16;" :: "r"(daddr), "l"(src))
#define CPCOMMIT() asm volatile("cp.async.commit_group;" ::: "memory")
#define CPWAIT(n)  asm volatile("cp.async.wait_group %0;" :: "n"(n) : "memory")

// ============================================================
// Merged prep: 12 weight transposes + bias concat (one launch)
// ============================================================
struct Prep {
    const float* ws[12]; unsigned* wd[12];
    const float* bs[8];  float* bdst;
};

__device__ __forceinline__ void tile_transpose(const float* __restrict__ in,
                                               unsigned* __restrict__ out,
                                               int K, int N, int bx, int by) {
    __shared__ float t[32][33];
    int k0 = bx * 32, n0 = by * 32;
    int tx = threadIdx.x, ty = threadIdx.y;
    #pragma unroll
    for (int i = 0; i < 4; i++)
        t[ty + i*8][tx] = in[(size_t)(k0 + ty + i*8) * N + n0 + tx];
    __syncthreads();
    #pragma unroll
    for (int i = 0; i < 2; i++) {
        int kp = ty + 8 * i;
        out[(size_t)(n0 + tx) * (K >> 1) + (k0 >> 1) + kp] =
            packbf(t[2*kp][tx], t[2*kp+1][tx]);
    }
}

__global__ void prep_kernel(Prep p) {
    int id = blockIdx.x;
    if (id < 2560) {
        int m = id >> 8, t = id & 255;
        tile_transpose(p.ws[m], p.wd[m], 512, 512, t & 15, t >> 4);
    } else if (id < 3072) {
        int t = id - 2560;
        tile_transpose(p.ws[10], p.wd[10], 512, 1024, t & 15, t >> 4);
    } else if (id < 3584) {
        int t = id - 3072;
        tile_transpose(p.ws[11], p.wd[11], 1024, 512, t & 31, t >> 5);
    } else {
        int t = threadIdx.y * 32 + threadIdx.x;
        int i0 = (id - 3584) * 2048 + t * 8;
        #pragma unroll
        for (int j = 0; j < 8; j++) {
            int i = i0 + j;
            p.bdst[i] = p.bs[i >> 9][i & 511];
        }
    }
}

// ============================================================
// Batched LayerNorm: fp32 in, bf16 (packed) out.
// ============================================================
__global__ void ln_kernel(const float* __restrict__ xA, const float* __restrict__ gA,
                          const float* __restrict__ bA, unsigned* __restrict__ oA,
                          const float* __restrict__ xB, const float* __restrict__ gB,
                          const float* __restrict__ bB, unsigned* __restrict__ oB) {
    const float* x = blockIdx.y ? xB : xA;
    const float* g = blockIdx.y ? gB : gA;
    const float* b = blockIdx.y ? bB : bA;
    unsigned* out  = blockIdx.y ? oB : oA;

    int row = blockIdx.x;
    const float* xr = x + (size_t)row * DMODEL;
    unsigned* orow = out + (size_t)row * 256;
    int tid = threadIdx.x;
    float v0 = xr[2*tid], v1 = xr[2*tid + 1];

    __shared__ float sm[8];
    float s = v0 + v1;
    #pragma unroll
    for (int o = 16; o; o >>= 1) s += __shfl_xor_sync(0xffffffffu, s, o);
    if ((tid & 31) == 0) sm[tid >> 5] = s;
    __syncthreads();
    if (tid == 0) {
        float t = 0.f;
        #pragma unroll
        for (int i = 0; i < 8; i++) t += sm[i];
        sm[0] = t * (1.0f / DMODEL);
    }
    __syncthreads();
    float mean = sm[0];
    __syncthreads();

    float d0 = v0 - mean, d1 = v1 - mean;
    float q = d0 * d0 + d1 * d1;
    #pragma unroll
    for (int o = 16; o; o >>= 1) q += __shfl_xor_sync(0xffffffffu, q, o);
    if ((tid & 31) == 0) sm[tid >> 5] = q;
    __syncthreads();
    if (tid == 0) {
        float t = 0.f;
        #pragma unroll
        for (int i = 0; i < 8; i++) t += sm[i];
        sm[0] = rsqrtf(t * (1.0f / DMODEL) + 1e-6f);
    }
    __syncthreads();
    float rstd = sm[0];

    float y0 = d0 * rstd * g[2*tid]     + b[2*tid];
    float y1 = d1 * rstd * g[2*tid + 1] + b[2*tid + 1];
    orow[tid] = packbf(y0, y1);
}

// ============================================================
// bf16 GEMM with cp.async 4-stage pipeline, z-batched (2 slices).
// Optional Vt epilogue (pre-transposed token-pair-packed V copy).
// ============================================================
#define GM_STAGE 3072
#define GM_SMEM  (4 * GM_STAGE * 4)

struct GB {
    const unsigned* A; const unsigned* BT; const float* bias;
    const float* addf; const unsigned* addb;
    float* Cf; unsigned* Cb;
    unsigned* Vt; int vcol0;
};

__global__ void __launch_bounds__(256, 2)
gemm_bf(GB g0, GB g1, int N0, int N1, int K, int act)
{
    GB G = blockIdx.z ? g1 : g0;
    int N = blockIdx.z ? N1 : N0;
    int bn = blockIdx.x * 128;
    if (bn >= N) return;

    uint32_t sb = smem_u32(dsm);
    int bm = blockIdx.y * 128;
    int tid = threadIdx.x;
    int warp = tid >> 5, lane = tid & 31;
    int wm = warp >> 2, wn = warp & 3;
    int gid = lane >> 2, tig = lane & 3;
    int lda2 = K >> 1;
    int chunks = K >> 4;

    int crow = tid >> 1, cseg = tid & 1;
    const unsigned* Asrc = G.A + (size_t)(bm + crow) * lda2 + cseg * 4;
    const unsigned* Bsrc = G.BT + (size_t)(bn + crow) * lda2 + cseg * 4;
    int dsto = crow * 12 + cseg * 4;

    float acc[4][4][4];
    #pragma unroll
    for (int i = 0; i < 4; i++)
        #pragma unroll
        for (int j = 0; j < 4; j++)
            #pragma unroll
            for (int c = 0; c < 4; c++) acc[i][j][c] = 0.f;

    #pragma unroll
    for (int c = 0; c < 3; c++) {
        int st = c & 3;
        CP16(sb + (st * GM_STAGE + dsto) * 4, Asrc + c * 8);
        CP16(sb + (st * GM_STAGE + 1536 + dsto) * 4, Bsrc + c * 8);
        CPCOMMIT();
    }

    for (int c = 0; c < chunks; c++) {
        CPWAIT(2);
        __syncthreads();
        if (c + 3 < chunks) {
            int st = (c + 3) & 3;
            CP16(sb + (st * GM_STAGE + dsto) * 4, Asrc + (c + 3) * 8);
            CP16(sb + (st * GM_STAGE + 1536 + dsto) * 4, Bsrc + (c + 3) * 8);
        }
        CPCOMMIT();

        unsigned* As = dsm + (c & 3) * GM_STAGE;
        unsigned* Bs = As + 1536;
        unsigned af[4][4], bf2[4][2];
        #pragma unroll
        for (int ma = 0; ma < 4; ma++) {
            int mb = (wm * 64 + ma * 16 + gid) * 12 + tig;
            af[ma][0] = As[mb];
            af[ma][1] = As[mb + 96];
            af[ma][2] = As[mb + 4];
            af[ma][3] = As[mb + 100];
        }
        #pragma unroll
        for (int nb = 0; nb < 4; nb++) {
            int nbase = (wn * 32 + nb * 8 + gid) * 12 + tig;
            bf2[nb][0] = Bs[nbase];
            bf2[nb][1] = Bs[nbase + 4];
        }
        #pragma unroll
        for (int ma = 0; ma < 4; ma++)
            #pragma unroll
            for (int nb = 0; nb < 4; nb++)
                MMA_BF16(acc[ma][nb], af[ma], bf2[nb]);
    }

    // epilogue
    #pragma unroll
    for (int ma = 0; ma < 4; ma++) {
        #pragma unroll
        for (int nb = 0; nb < 4; nb++) {
            int c = bn + wn * 32 + nb * 8 + tig * 2;
            float bv0 = G.bias ? G.bias[c] : 0.f;
            float bv1 = G.bias ? G.bias[c + 1] : 0.f;
            #pragma unroll
            for (int half = 0; half < 2; half++) {
                int r = bm + wm * 64 + ma * 16 + gid + half * 8;
                float t0 = acc[ma][nb][half * 2 + 0] + bv0;
                float t1 = acc[ma][nb][half * 2 + 1] + bv1;
                if (act) {
                    t0 = 0.5f * t0 * (1.0f + erff(t0 * 0.70710678118654752f));
                    t1 = 0.5f * t1 * (1.0f + erff(t1 * 0.70710678118654752f));
                }
                size_t off = (size_t)r * N + c;
                if (G.addf) { t0 += G.addf[off]; t1 += G.addf[off + 1]; }
                if (G.addb) {
                    float2 av = unpackbf(G.addb[(size_t)r * (N >> 1) + (c >> 1)]);
                    t0 += av.x; t1 += av.y;
                }
                if (G.Cf) *(float2*)&G.Cf[off] = make_float2(t0, t1);
                if (G.Cb) G.Cb[(size_t)r * (N >> 1) + (c >> 1)] = packbf(t0, t1);
                if (G.Vt && c >= G.vcol0) {
                    float u0 = __shfl_xor_sync(0xffffffffu, t0, 4);
                    float u1 = __shfl_xor_sync(0xffffffffu, t1, 4);
                    if (!(gid & 1)) {
                        int d = c - G.vcol0;
                        int h = d >> 7, dh = d & 127;
                        int bb = r >> 10, tp = (r & 1023) >> 1;
                        size_t vo = (((size_t)(bb * 4 + h) * 512) + tp) * 128 + dh;
                        G.Vt[vo]     = packbf(t0, u0);
                        G.Vt[vo + 1] = packbf(t1, u1);
                    }
                }
            }
        }
    }
}

// ============================================================
// Flash v3: warp-owns-rows. 8 warps x 16 Q-rows; S warp tile 16x64;
// register-only softmax (quad shfl); in-register P->A-frag; V from
// pre-transposed Vt. K and V double-buffered, ONE barrier per chunk.
// smem u32: sQ 128x68 @0; sK[2] @8704; sV[2] @17408. 104448 B.
// ============================================================
#define SQ_O 0
#define SK_O 8704
#define SV_O 17408
#define FL_SMEM_BYTES (26112 * 4)
#define NCH 16   // SEQ / 64

struct FB { const unsigned* Qm; const unsigned* Km; const unsigned* Vt; unsigned* Om; };

__global__ void __launch_bounds__(256, 2)
flash_bf(FB f0, FB f1, int qld2, int kvld2)
{
    FB F = blockIdx.z ? f1 : f0;
    unsigned* fsu = dsm;
    uint32_t sb = smem_u32(dsm);

    int tid = threadIdx.x;
    int warp = tid >> 5, lane = tid & 31;
    int gid = lane >> 2, tig = lane & 3;
    int m0 = warp * 16;

    int bh = blockIdx.y, b = bh >> 2, h = bh & 3;
    int q0 = blockIdx.x * 128, base = b * SEQ;
    int hoff2 = h * 64;

    // prologue group G0: Q + K(0) + V(0)
    {
        #pragma unroll
        for (int i = 0; i < 8; i++) {
            int seg = tid + 256 * i;
            int r = seg >> 4, sg = seg & 15;
            CP16(sb + (SQ_O + r * 68 + sg * 4) * 4,
                 F.Qm + (size_t)(base + q0 + r) * qld2 + hoff2 + sg * 4);
        }
        #pragma unroll
        for (int i = 0; i < 4; i++) {
            int seg = tid + 256 * i;
            int r = seg >> 4, sg = seg & 15;
            CP16(sb + (SK_O + r * 68 + sg * 4) * 4,
                 F.Km + (size_t)(base + r) * kvld2 + hoff2 + sg * 4);
        }
        #pragma unroll
        for (int i = 0; i < 4; i++) {
            int seg = tid + 256 * i;
            int row = seg >> 5, sg = seg & 31;
            CP16(sb + (SV_O + row * 136 + sg * 4) * 4,
                 F.Vt + (((size_t)bh * 512) + row) * 128 + sg * 4);
        }
        CPCOMMIT();
    }

    float oacc[16][4];
    #pragma unroll
    for (int i = 0; i < 16; i++)
        #pragma unroll
        for (int c = 0; c < 4; c++) oacc[i][c] = 0.f;
    float mrow[2] = {-1e30f, -1e30f}, lrow[2] = {0.f, 0.f};

    const float scale = 0.08838834764831845f;   // 1/sqrt(128)

    for (int ch = 0; ch < NCH; ch++) {
        CPWAIT(0);          // K(ch)+V(ch) (and Q on ch==0) complete
        __syncthreads();    // visible to all warps; prev chunk's readers done

        // issue K(ch+1)+V(ch+1) into the other buffers
        if (ch + 1 < NCH) {
            int nb2f = (ch + 1) & 1;
            #pragma unroll
            for (int i = 0; i < 4; i++) {
                int seg = tid + 256 * i;
                int r = seg >> 4, sg = seg & 15;
                CP16(sb + (SK_O + nb2f * 4352 + r * 68 + sg * 4) * 4,
                     F.Km + (size_t)(base + (ch + 1) * 64 + r) * kvld2 + hoff2 + sg * 4);
            }
            #pragma unroll
            for (int i = 0; i < 4; i++) {
                int seg = tid + 256 * i;
                int row = seg >> 5, sg = seg & 31;
                CP16(sb + (SV_O + nb2f * 4352 + row * 136 + sg * 4) * 4,
                     F.Vt + (((size_t)bh * 512) + (ch + 1) * 32 + row) * 128 + sg * 4);
            }
            CPCOMMIT();
        }

        int kbs = SK_O + (ch & 1) * 4352;
        int vbs = SV_O + (ch & 1) * 4352;

        // S = Q @ K^T : warp tile 16x64 (nb 0..7), 8 k16 steps
        float s[8][4];
        #pragma unroll
        for (int i = 0; i < 8; i++)
            #pragma unroll
            for (int c = 0; c < 4; c++) s[i][c] = 0.f;

        #pragma unroll
        for (int ks = 0; ks < 8; ks++) {
            int kb = ks * 8;
            unsigned af[4];
            int mb = (m0 + gid) * 68 + kb + tig;
            af[0] = fsu[SQ_O + mb];
            af[1] = fsu[SQ_O + mb + 544];
            af[2] = fsu[SQ_O + mb + 4];
            af[3] = fsu[SQ_O + mb + 548];
            #pragma unroll
            for (int nb = 0; nb < 8; nb++) {
                unsigned bf2[2];
                int nbase = (nb * 8 + gid) * 68 + kb + tig;
                bf2[0] = fsu[kbs + nbase];
                bf2[1] = fsu[kbs + nbase + 4];
                MMA_BF16(s[nb], af, bf2);
            }
        }

        // register-only online softmax (rows m0+gid, m0+gid+8; quad covers cols)
        #pragma unroll
        for (int hf = 0; hf < 2; hf++) {
            float mx = -1e30f;
            #pragma unroll
            for (int nb = 0; nb < 8; nb++)
                mx = fmaxf(mx, fmaxf(s[nb][2*hf], s[nb][2*hf+1]));
            mx *= scale;
            mx = fmaxf(mx, __shfl_xor_sync(0xffffffffu, mx, 1));
            mx = fmaxf(mx, __shfl_xor_sync(0xffffffffu, mx, 2));
            float nm = fmaxf(mrow[hf], mx);
            float alpha = __expf(mrow[hf] - nm);
            mrow[hf] = nm;
            float sum = 0.f;
            #pragma unroll
            for (int nb = 0; nb < 8; nb++) {
                float p0 = __expf(s[nb][2*hf]   * scale - nm);
                float p1 = __expf(s[nb][2*hf+1] * scale - nm);
                s[nb][2*hf] = p0; s[nb][2*hf+1] = p1;
                sum += p0 + p1;
            }
            sum += __shfl_xor_sync(0xffffffffu, sum, 1);
            sum += __shfl_xor_sync(0xffffffffu, sum, 2);
            lrow[hf] = lrow[hf] * alpha + sum;
            #pragma unroll
            for (int nb2 = 0; nb2 < 16; nb2++) {
                oacc[nb2][2*hf]   *= alpha;
                oacc[nb2][2*hf+1] *= alpha;
            }
        }

        // O += P @ V : in-register P A-frags; V B-frags from token-pair Vt
        #pragma unroll
        for (int ks = 0; ks < 4; ks++) {
            unsigned ap[4];
            ap[0] = packbf(s[2*ks][0],   s[2*ks][1]);
            ap[1] = packbf(s[2*ks][2],   s[2*ks][3]);
            ap[2] = packbf(s[2*ks+1][0], s[2*ks+1][1]);
            ap[3] = packbf(s[2*ks+1][2], s[2*ks+1][3]);
            #pragma unroll
            for (int nb2 = 0; nb2 < 16; nb2++) {
                unsigned bv[2];
                int n0 = nb2 * 8 + gid;
                bv[0] = fsu[vbs + (8*ks + tig) * 136 + n0];
                bv[1] = fsu[vbs + (8*ks + tig + 4) * 136 + n0];
                MMA_BF16(oacc[nb2], ap, bv);
            }
        }
    }

    // epilogue: divide by l, pack bf16
    #pragma unroll
    for (int hf = 0; hf < 2; hf++) {
        float inv = 1.0f / lrow[hf];
        int gr = base + q0 + m0 + gid + hf * 8;
        #pragma unroll
        for (int nb2 = 0; nb2 < 16; nb2++) {
            F.Om[(size_t)gr * 256 + hoff2 + nb2 * 4 + tig] =
                packbf(oacc[nb2][2*hf] * inv, oacc[nb2][2*hf+1] * inv);
        }
    }
}

// ============================================================
// Host orchestration
// ============================================================
static inline void run_gemm2(GB g0, GB g1, int N0, int N1, int K, int act, int nz) {
    cudaFuncSetAttribute(gemm_bf, cudaFuncAttributeMaxDynamicSharedMemorySize, GM_SMEM);
    int nmax = N0 > N1 ? N0 : N1;
    dim3 grid(nmax / 128, NTOK / 128, nz);
    gemm_bf<<<grid, 256, GM_SMEM>>>(g0, g1, N0, N1, K, act);
}

static inline void run_flash2(FB f0, FB f1, int qld2, int kvld2, int nz) {
    cudaFuncSetAttribute(flash_bf, cudaFuncAttributeMaxDynamicSharedMemorySize, FL_SMEM_BYTES);
    dim3 grid(SEQ / 128, NBH, nz);
    flash_bf<<<grid, 256, FL_SMEM_BYTES>>>(f0, f1, qld2, kvld2);
}

extern "C" void kernel_launch(void* const* d_in, const int* in_sizes, int n_in,
                              void* d_out, int out_size) {
    const float* x1    = (const float*)d_in[0];
    const float* x2    = (const float*)d_in[1];
    const float* ln1_g = (const float*)d_in[2];
    const float* ln1_b = (const float*)d_in[3];
    const float* ln2_g = (const float*)d_in[4];
    const float* ln2_b = (const float*)d_in[5];
    const float* lnf_g = (const float*)d_in[6];
    const float* lnf_b = (const float*)d_in[7];
    const float* Wq1 = (const float*)d_in[8],  *bq1 = (const float*)d_in[9];
    const float* Wk1 = (const float*)d_in[10], *bk1 = (const float*)d_in[11];
    const float* Wv1 = (const float*)d_in[12], *bv1 = (const float*)d_in[13];
    const float* Wq2 = (const float*)d_in[14], *bq2 = (const float*)d_in[15];
    const float* Wk2 = (const float*)d_in[16], *bk2 = (const float*)d_in[17];
    const float* Wv2 = (const float*)d_in[18], *bv2 = (const float*)d_in[19];
    const float* Wq12 = (const float*)d_in[20], *bq12 = (const float*)d_in[21];
    const float* Wk12 = (const float*)d_in[22], *bk12 = (const float*)d_in[23];
    const float* Wv12 = (const float*)d_in[24], *bv12 = (const float*)d_in[25];
    const float* Wo  = (const float*)d_in[26], *bo = (const float*)d_in[27];
    const float* W1  = (const float*)d_in[28], *b1 = (const float*)d_in[29];
    const float* W2  = (const float*)d_in[30], *b2 = (const float*)d_in[31];
    float* out = (float*)d_out;

    unsigned *x1n, *x2n, *qv, *qkv1, *qkv2, *ctx1, *ctx2, *s1, *s2, *h1, *wb, *vt1, *vt2;
    float *xres, *bc;
    cudaGetSymbolAddress((void**)&x1n,  g_x1n);
    cudaGetSymbolAddress((void**)&x2n,  g_x2n);
    cudaGetSymbolAddress((void**)&qv,   g_qv);
    cudaGetSymbolAddress((void**)&qkv1, g_qkv1);
    cudaGetSymbolAddress((void**)&qkv2, g_qkv2);
    cudaGetSymbolAddress((void**)&ctx1, g_ctx1);
    cudaGetSymbolAddress((void**)&ctx2, g_ctx2);
    cudaGetSymbolAddress((void**)&s1,   g_s1);
    cudaGetSymbolAddress((void**)&s2,   g_s2);
    cudaGetSymbolAddress((void**)&h1,   g_h1);
    cudaGetSymbolAddress((void**)&wb,   g_wb);
    cudaGetSymbolAddress((void**)&vt1,  g_vt1);
    cudaGetSymbolAddress((void**)&vt2,  g_vt2);
    cudaGetSymbolAddress((void**)&xres, g_x);
    cudaGetSymbolAddress((void**)&bc,   g_bc);

    unsigned* wS1t  = wb;
    unsigned* wS2t  = wb + 393216;
    unsigned* wCQt  = wb + 786432;
    unsigned* wCKVt = wb + 917504;
    unsigned* wWot  = wb + 1179648;
    unsigned* wW1t  = wb + 1310720;
    unsigned* wW2t  = wb + 1572864;

    // 0) merged prep
    Prep p;
    p.ws[0] = Wq1;  p.wd[0] = wS1t;
    p.ws[1] = Wk1;  p.wd[1] = wS1t + 131072;
    p.ws[2] = Wv1;  p.wd[2] = wS1t + 262144;
    p.ws[3] = Wq2;  p.wd[3] = wS2t;
    p.ws[4] = Wk2;  p.wd[4] = wS2t + 131072;
    p.ws[5] = Wv2;  p.wd[5] = wS2t + 262144;
    p.ws[6] = Wq12; p.wd[6] = wCQt;
    p.ws[7] = Wk12; p.wd[7] = wCKVt;
    p.ws[8] = Wv12; p.wd[8] = wCKVt + 131072;
    p.ws[9] = Wo;   p.wd[9] = wWot;
    p.ws[10] = W1;  p.wd[10] = wW1t;
    p.ws[11] = W2;  p.wd[11] = wW2t;
    p.bs[0]=bq1; p.bs[1]=bk1; p.bs[2]=bv1; p.bs[3]=bq2;
    p.bs[4]=bk2; p.bs[5]=bv2; p.bs[6]=bk12; p.bs[7]=bv12;
    p.bdst = bc;
    prep_kernel<<<3586, dim3(32, 8)>>>(p);
    float* bS1 = bc, *bS2 = bc + 1536, *bCKV = bc + 3072;

    // 1) pre-LN, both streams
    ln_kernel<<<dim3(NTOK, 2), 256>>>(x1, ln1_g, ln1_b, x1n,
                                      x2, ln2_g, ln2_b, x2n);

    // 2+3) both self-attentions, z-batched; qkv gemm also emits Vt
    GB q0 = {x1n, wS1t, bS1, nullptr, nullptr, nullptr, qkv1, vt1, 1024};
    GB q1 = {x2n, wS2t, bS2, nullptr, nullptr, nullptr, qkv2, vt2, 1024};
    run_gemm2(q0, q1, 1536, 1536, 512, 0, 2);

    FB fa = {qkv1, qkv1 + 256, vt1, ctx1};
    FB fb = {qkv2, qkv2 + 256, vt2, ctx2};
    run_flash2(fa, fb, 768, 768, 2);

    GB w0 = {ctx1, wWot, bo, nullptr, x1n, nullptr, s1, nullptr, 0};
    GB w1 = {ctx2, wWot, bo, nullptr, x2n, nullptr, s2, nullptr, 0};
    run_gemm2(w0, w1, 512, 512, 512, 0, 2);

    // 4) cross-attention
    GB c0 = {s1, wCQt, bq12, nullptr, nullptr, nullptr, qv, nullptr, 0};
    GB c1 = {s2, wCKVt, bCKV, nullptr, nullptr, nullptr, qkv1, vt1, 512};
    run_gemm2(c0, c1, 512, 1024, 512, 0, 2);

    FB fc = {qv, qkv1, vt1, ctx1};
    run_flash2(fc, fc, 256, 512, 1);

    GB wc = {ctx1, wWot, bo, x1, nullptr, xres, nullptr, nullptr, 0};
    run_gemm2(wc, wc, 512, 512, 512, 0, 1);

    // 5) final LN + MLP
    ln_kernel<<<dim3(NTOK, 1), 256>>>(xres, lnf_g, lnf_b, x1n,
                                      xres, lnf_g, lnf_b, x1n);
    GB m1 = {x1n, wW1t, b1, nullptr, nullptr, nullptr, h1, nullptr, 0};
    run_gemm2(m1, m1, 1024, 1024, 512, 1, 1);
    GB m2 = {h1, wW2t, b2, xres, nullptr, out, nullptr, nullptr, 0};
    run_gemm2(m2, m2, 512, 512, 1024, 0, 1);
    (void)in_sizes; (void)n_in; (void)out_size;
}

// round 14
// speedup vs baseline: 2.6790x; 1.1062x over previous
#include <cuda_runtime.h>
#include <cuda_bf16.h>
#include <math.h>
#include <stdint.h>

// Problem constants
#define BATCH 16
#define SEQ   1024
#define NTOK  (BATCH*SEQ)        // 16384
#define DMODEL 512
#define NHEAD  4
#define HDIM   128
#define DMLP   1024
#define NBH    (BATCH*NHEAD)     // 64

// -------- scratch (no cudaMalloc allowed). bf16 tensors stored as packed u32 pairs.
__device__ unsigned g_x1n[NTOK*256];
__device__ unsigned g_x2n[NTOK*256];
__device__ unsigned g_qv [NTOK*256];
__device__ unsigned g_qkv1[NTOK*768];
__device__ unsigned g_qkv2[NTOK*768];
__device__ unsigned g_ctx1[NTOK*256];
__device__ unsigned g_ctx2[NTOK*256];
__device__ unsigned g_s1 [NTOK*256];
__device__ unsigned g_s2 [NTOK*256];
__device__ float    g_x  [NTOK*DMODEL];
__device__ unsigned g_h1 [NTOK*512];
__device__ unsigned g_wb [1835008];
__device__ float    g_bc [4096];
// pre-transposed V: [bh][token-pair][d] u32 (token-pair packed bf16)
__device__ unsigned g_vt1[NBH*512*128];
__device__ unsigned g_vt2[NBH*512*128];

extern __shared__ unsigned dsm[];

// ---------- helpers ----------
__device__ __forceinline__ unsigned packbf(float a, float b) {
    __nv_bfloat162 h = __floats2bfloat162_rn(a, b);
    return *reinterpret_cast<unsigned*>(&h);
}
__device__ __forceinline__ float2 unpackbf(unsigned u) {
    __nv_bfloat162 h = *reinterpret_cast<__nv_bfloat162*>(&u);
    return __bfloat1622float2(h);
}
__device__ __forceinline__ uint32_t smem_u32(const void* p) {
    uint32_t a;
    asm("{ .reg .u64 t; cvta.to.shared.u64 t, %1; cvt.u32.u64 %0, t; }" : "=r"(a) : "l"(p));
    return a;
}

#define MMA_BF16(acc, a, b) \
    asm volatile("mma.sync.aligned.m16n8k16.row.col.f32.bf16.bf16.f32 " \
        "{%0,%1,%2,%3}, {%4,%5,%6,%7}, {%8,%9}, {%0,%1,%2,%3};\n" \
        : "+f"((acc)[0]), "+f"((acc)[1]), "+f"((acc)[2]), "+f"((acc)[3]) \
        : "r"((a)[0]), "r"((a)[1]), "r"((a)[2]), "r"((a)[3]), "r"((b)[0]), "r"((b)[1]))

#define CP16(daddr, src) \
    asm volatile("cp.async.cg.shared.global [%0], [%1], 16;" :: "r"(daddr), "l"(src))
#define CPCOMMIT() asm volatile("cp.async.commit_group;" ::: "memory")
#define CPWAIT(n)  asm volatile("cp.async.wait_group %0;" :: "n"(n) : "memory")

// ============================================================
// Merged prep: 12 weight transposes + bias concat (one launch)
// ============================================================
struct Prep {
    const float* ws[12]; unsigned* wd[12];
    const float* bs[8];  float* bdst;
};

__device__ __forceinline__ void tile_transpose(const float* __restrict__ in,
                                               unsigned* __restrict__ out,
                                               int K, int N, int bx, int by) {
    __shared__ float t[32][33];
    int k0 = bx * 32, n0 = by * 32;
    int tx = threadIdx.x, ty = threadIdx.y;
    #pragma unroll
    for (int i = 0; i < 4; i++)
        t[ty + i*8][tx] = in[(size_t)(k0 + ty + i*8) * N + n0 + tx];
    __syncthreads();
    #pragma unroll
    for (int i = 0; i < 2; i++) {
        int kp = ty + 8 * i;
        out[(size_t)(n0 + tx) * (K >> 1) + (k0 >> 1) + kp] =
            packbf(t[2*kp][tx], t[2*kp+1][tx]);
    }
}

__global__ void prep_kernel(Prep p) {
    int id = blockIdx.x;
    if (id < 2560) {
        int m = id >> 8, t = id & 255;
        tile_transpose(p.ws[m], p.wd[m], 512, 512, t & 15, t >> 4);
    } else if (id < 3072) {
        int t = id - 2560;
        tile_transpose(p.ws[10], p.wd[10], 512, 1024, t & 15, t >> 4);
    } else if (id < 3584) {
        int t = id - 3072;
        tile_transpose(p.ws[11], p.wd[11], 1024, 512, t & 31, t >> 5);
    } else {
        int t = threadIdx.y * 32 + threadIdx.x;
        int i0 = (id - 3584) * 2048 + t * 8;
        #pragma unroll
        for (int j = 0; j < 8; j++) {
            int i = i0 + j;
            p.bdst[i] = p.bs[i >> 9][i & 511];
        }
    }
}

// ============================================================
// Batched LayerNorm: fp32 in, bf16 (packed) out.
// ============================================================
__global__ void ln_kernel(const float* __restrict__ xA, const float* __restrict__ gA,
                          const float* __restrict__ bA, unsigned* __restrict__ oA,
                          const float* __restrict__ xB, const float* __restrict__ gB,
                          const float* __restrict__ bB, unsigned* __restrict__ oB) {
    const float* x = blockIdx.y ? xB : xA;
    const float* g = blockIdx.y ? gB : gA;
    const float* b = blockIdx.y ? bB : bA;
    unsigned* out  = blockIdx.y ? oB : oA;

    int row = blockIdx.x;
    const float* xr = x + (size_t)row * DMODEL;
    unsigned* orow = out + (size_t)row * 256;
    int tid = threadIdx.x;
    float v0 = xr[2*tid], v1 = xr[2*tid + 1];

    __shared__ float sm[8];
    float s = v0 + v1;
    #pragma unroll
    for (int o = 16; o; o >>= 1) s += __shfl_xor_sync(0xffffffffu, s, o);
    if ((tid & 31) == 0) sm[tid >> 5] = s;
    __syncthreads();
    if (tid == 0) {
        float t = 0.f;
        #pragma unroll
        for (int i = 0; i < 8; i++) t += sm[i];
        sm[0] = t * (1.0f / DMODEL);
    }
    __syncthreads();
    float mean = sm[0];
    __syncthreads();

    float d0 = v0 - mean, d1 = v1 - mean;
    float q = d0 * d0 + d1 * d1;
    #pragma unroll
    for (int o = 16; o; o >>= 1) q += __shfl_xor_sync(0xffffffffu, q, o);
    if ((tid & 31) == 0) sm[tid >> 5] = q;
    __syncthreads();
    if (tid == 0) {
        float t = 0.f;
        #pragma unroll
        for (int i = 0; i < 8; i++) t += sm[i];
        sm[0] = rsqrtf(t * (1.0f / DMODEL) + 1e-6f);
    }
    __syncthreads();
    float rstd = sm[0];

    float y0 = d0 * rstd * g[2*tid]     + b[2*tid];
    float y1 = d1 * rstd * g[2*tid + 1] + b[2*tid + 1];
    orow[tid] = packbf(y0, y1);
}

// ============================================================
// bf16 GEMM, BK=32 (16 u32/row), 3-stage cp.async ring, ONE barrier
// per chunk. 128x128 CTA tile, 8 warps (2x4), warp 64x32, pitch 20 u32
// (conflict-free). Stage = As(2560)+Bs(2560) u32; 3 stages = 61440 B.
// ============================================================
#define GM_STAGE 5120
#define GM_SMEM  (3 * GM_STAGE * 4)

struct GB {
    const unsigned* A; const unsigned* BT; const float* bias;
    const float* addf; const unsigned* addb;
    float* Cf; unsigned* Cb;
    unsigned* Vt; int vcol0;
};

__global__ void __launch_bounds__(256, 2)
gemm_bf(GB g0, GB g1, int N0, int N1, int K, int act)
{
    GB G = blockIdx.z ? g1 : g0;
    int N = blockIdx.z ? N1 : N0;
    int bn = blockIdx.x * 128;
    if (bn >= N) return;

    uint32_t sb = smem_u32(dsm);
    int bm = blockIdx.y * 128;
    int tid = threadIdx.x;
    int warp = tid >> 5, lane = tid & 31;
    int wm = warp >> 2, wn = warp & 3;
    int gid = lane >> 2, tig = lane & 3;
    int lda2 = K >> 1;
    int chunks = K >> 5;   // 32-elem chunks (16 u32)

    // loader: 512 segments of 16B per operand; thread does segs tid, tid+256
    int r0l = tid >> 2, q0l = (tid & 3) * 4;          // seg tid
    int r1l = (tid + 256) >> 2, q1l = ((tid + 256) & 3) * 4;
    const unsigned* Asrc0 = G.A + (size_t)(bm + r0l) * lda2 + q0l;
    const unsigned* Asrc1 = G.A + (size_t)(bm + r1l) * lda2 + q1l;
    const unsigned* Bsrc0 = G.BT + (size_t)(bn + r0l) * lda2 + q0l;
    const unsigned* Bsrc1 = G.BT + (size_t)(bn + r1l) * lda2 + q1l;
    int d0l = r0l * 20 + q0l, d1l = r1l * 20 + q1l;

    float acc[4][4][4];
    #pragma unroll
    for (int i = 0; i < 4; i++)
        #pragma unroll
        for (int j = 0; j < 4; j++)
            #pragma unroll
            for (int c = 0; c < 4; c++) acc[i][j][c] = 0.f;

    // prologue: chunks 0,1 into stages 0,1
    #pragma unroll
    for (int c = 0; c < 2; c++) {
        uint32_t st = sb + c * GM_STAGE * 4;
        CP16(st + d0l * 4, Asrc0 + c * 16);
        CP16(st + d1l * 4, Asrc1 + c * 16);
        CP16(st + (2560 + d0l) * 4, Bsrc0 + c * 16);
        CP16(st + (2560 + d1l) * 4, Bsrc1 + c * 16);
        CPCOMMIT();
    }

    int stc = 0;              // stage of current chunk
    for (int c = 0; c < chunks; c++) {
        CPWAIT(1);
        __syncthreads();
        if (c + 2 < chunks) {
            int stp = stc + 2; if (stp >= 3) stp -= 3;
            uint32_t st = sb + stp * GM_STAGE * 4;
            CP16(st + d0l * 4, Asrc0 + (c + 2) * 16);
            CP16(st + d1l * 4, Asrc1 + (c + 2) * 16);
            CP16(st + (2560 + d0l) * 4, Bsrc0 + (c + 2) * 16);
            CP16(st + (2560 + d1l) * 4, Bsrc1 + (c + 2) * 16);
        }
        CPCOMMIT();   // uniform group count

        unsigned* As = dsm + stc * GM_STAGE;
        unsigned* Bs = As + 2560;
        #pragma unroll
        for (int ks = 0; ks < 2; ks++) {
            int kb = ks * 8;
            unsigned af[4][4], bf2[4][2];
            #pragma unroll
            for (int ma = 0; ma < 4; ma++) {
                int mb = (wm * 64 + ma * 16 + gid) * 20 + kb + tig;
                af[ma][0] = As[mb];
                af[ma][1] = As[mb + 160];
                af[ma][2] = As[mb + 4];
                af[ma][3] = As[mb + 164];
            }
            #pragma unroll
            for (int nb = 0; nb < 4; nb++) {
                int nbase = (wn * 32 + nb * 8 + gid) * 20 + kb + tig;
                bf2[nb][0] = Bs[nbase];
                bf2[nb][1] = Bs[nbase + 4];
            }
            #pragma unroll
            for (int ma = 0; ma < 4; ma++)
                #pragma unroll
                for (int nb = 0; nb < 4; nb++)
                    MMA_BF16(acc[ma][nb], af[ma], bf2[nb]);
        }
        if (++stc >= 3) stc = 0;
    }

    // epilogue
    #pragma unroll
    for (int ma = 0; ma < 4; ma++) {
        #pragma unroll
        for (int nb = 0; nb < 4; nb++) {
            int c = bn + wn * 32 + nb * 8 + tig * 2;
            float bv0 = G.bias ? G.bias[c] : 0.f;
            float bv1 = G.bias ? G.bias[c + 1] : 0.f;
            #pragma unroll
            for (int half = 0; half < 2; half++) {
                int r = bm + wm * 64 + ma * 16 + gid + half * 8;
                float t0 = acc[ma][nb][half * 2 + 0] + bv0;
                float t1 = acc[ma][nb][half * 2 + 1] + bv1;
                if (act) {
                    t0 = 0.5f * t0 * (1.0f + erff(t0 * 0.70710678118654752f));
                    t1 = 0.5f * t1 * (1.0f + erff(t1 * 0.70710678118654752f));
                }
                size_t off = (size_t)r * N + c;
                if (G.addf) { t0 += G.addf[off]; t1 += G.addf[off + 1]; }
                if (G.addb) {
                    float2 av = unpackbf(G.addb[(size_t)r * (N >> 1) + (c >> 1)]);
                    t0 += av.x; t1 += av.y;
                }
                if (G.Cf) *(float2*)&G.Cf[off] = make_float2(t0, t1);
                if (G.Cb) G.Cb[(size_t)r * (N >> 1) + (c >> 1)] = packbf(t0, t1);
                if (G.Vt && c >= G.vcol0) {
                    float u0 = __shfl_xor_sync(0xffffffffu, t0, 4);
                    float u1 = __shfl_xor_sync(0xffffffffu, t1, 4);
                    if (!(gid & 1)) {
                        int d = c - G.vcol0;
                        int h = d >> 7, dh = d & 127;
                        int bb = r >> 10, tp = (r & 1023) >> 1;
                        size_t vo = (((size_t)(bb * 4 + h) * 512) + tp) * 128 + dh;
                        G.Vt[vo]     = packbf(t0, u0);
                        G.Vt[vo + 1] = packbf(t1, u1);
                    }
                }
            }
        }
    }
}

// ============================================================
// Flash v3 (R13, unchanged): warp-owns-rows, register softmax,
// in-register P->A-frag, pre-transposed Vt, K/V double-buffered.
// ============================================================
#define SQ_O 0
#define SK_O 8704
#define SV_O 17408
#define FL_SMEM_BYTES (26112 * 4)
#define NCH 16   // SEQ / 64

struct FB { const unsigned* Qm; const unsigned* Km; const unsigned* Vt; unsigned* Om; };

__global__ void __launch_bounds__(256, 2)
flash_bf(FB f0, FB f1, int qld2, int kvld2)
{
    FB F = blockIdx.z ? f1 : f0;
    unsigned* fsu = dsm;
    uint32_t sb = smem_u32(dsm);

    int tid = threadIdx.x;
    int warp = tid >> 5, lane = tid & 31;
    int gid = lane >> 2, tig = lane & 3;
    int m0 = warp * 16;

    int bh = blockIdx.y, b = bh >> 2, h = bh & 3;
    int q0 = blockIdx.x * 128, base = b * SEQ;
    int hoff2 = h * 64;

    // prologue group G0: Q + K(0) + V(0)
    {
        #pragma unroll
        for (int i = 0; i < 8; i++) {
            int seg = tid + 256 * i;
            int r = seg >> 4, sg = seg & 15;
            CP16(sb + (SQ_O + r * 68 + sg * 4) * 4,
                 F.Qm + (size_t)(base + q0 + r) * qld2 + hoff2 + sg * 4);
        }
        #pragma unroll
        for (int i = 0; i < 4; i++) {
            int seg = tid + 256 * i;
            int r = seg >> 4, sg = seg & 15;
            CP16(sb + (SK_O + r * 68 + sg * 4) * 4,
                 F.Km + (size_t)(base + r) * kvld2 + hoff2 + sg * 4);
        }
        #pragma unroll
        for (int i = 0; i < 4; i++) {
            int seg = tid + 256 * i;
            int row = seg >> 5, sg = seg & 31;
            CP16(sb + (SV_O + row * 136 + sg * 4) * 4,
                 F.Vt + (((size_t)bh * 512) + row) * 128 + sg * 4);
        }
        CPCOMMIT();
    }

    float oacc[16][4];
    #pragma unroll
    for (int i = 0; i < 16; i++)
        #pragma unroll
        for (int c = 0; c < 4; c++) oacc[i][c] = 0.f;
    float mrow[2] = {-1e30f, -1e30f}, lrow[2] = {0.f, 0.f};

    const float scale = 0.08838834764831845f;   // 1/sqrt(128)

    for (int ch = 0; ch < NCH; ch++) {
        CPWAIT(0);
        __syncthreads();

        if (ch + 1 < NCH) {
            int nb2f = (ch + 1) & 1;
            #pragma unroll
            for (int i = 0; i < 4; i++) {
                int seg = tid + 256 * i;
                int r = seg >> 4, sg = seg & 15;
                CP16(sb + (SK_O + nb2f * 4352 + r * 68 + sg * 4) * 4,
                     F.Km + (size_t)(base + (ch + 1) * 64 + r) * kvld2 + hoff2 + sg * 4);
            }
            #pragma unroll
            for (int i = 0; i < 4; i++) {
                int seg = tid + 256 * i;
                int row = seg >> 5, sg = seg & 31;
                CP16(sb + (SV_O + nb2f * 4352 + row * 136 + sg * 4) * 4,
                     F.Vt + (((size_t)bh * 512) + (ch + 1) * 32 + row) * 128 + sg * 4);
            }
            CPCOMMIT();
        }

        int kbs = SK_O + (ch & 1) * 4352;
        int vbs = SV_O + (ch & 1) * 4352;

        float s[8][4];
        #pragma unroll
        for (int i = 0; i < 8; i++)
            #pragma unroll
            for (int c = 0; c < 4; c++) s[i][c] = 0.f;

        #pragma unroll
        for (int ks = 0; ks < 8; ks++) {
            int kb = ks * 8;
            unsigned af[4];
            int mb = (m0 + gid) * 68 + kb + tig;
            af[0] = fsu[SQ_O + mb];
            af[1] = fsu[SQ_O + mb + 544];
            af[2] = fsu[SQ_O + mb + 4];
            af[3] = fsu[SQ_O + mb + 548];
            #pragma unroll
            for (int nb = 0; nb < 8; nb++) {
                unsigned bf2[2];
                int nbase = (nb * 8 + gid) * 68 + kb + tig;
                bf2[0] = fsu[kbs + nbase];
                bf2[1] = fsu[kbs + nbase + 4];
                MMA_BF16(s[nb], af, bf2);
            }
        }

        #pragma unroll
        for (int hf = 0; hf < 2; hf++) {
            float mx = -1e30f;
            #pragma unroll
            for (int nb = 0; nb < 8; nb++)
                mx = fmaxf(mx, fmaxf(s[nb][2*hf], s[nb][2*hf+1]));
            mx *= scale;
            mx = fmaxf(mx, __shfl_xor_sync(0xffffffffu, mx, 1));
            mx = fmaxf(mx, __shfl_xor_sync(0xffffffffu, mx, 2));
            float nm = fmaxf(mrow[hf], mx);
            float alpha = __expf(mrow[hf] - nm);
            mrow[hf] = nm;
            float sum = 0.f;
            #pragma unroll
            for (int nb = 0; nb < 8; nb++) {
                float p0 = __expf(s[nb][2*hf]   * scale - nm);
                float p1 = __expf(s[nb][2*hf+1] * scale - nm);
                s[nb][2*hf] = p0; s[nb][2*hf+1] = p1;
                sum += p0 + p1;
            }
            sum += __shfl_xor_sync(0xffffffffu, sum, 1);
            sum += __shfl_xor_sync(0xffffffffu, sum, 2);
            lrow[hf] = lrow[hf] * alpha + sum;
            #pragma unroll
            for (int nb2 = 0; nb2 < 16; nb2++) {
                oacc[nb2][2*hf]   *= alpha;
                oacc[nb2][2*hf+1] *= alpha;
            }
        }

        #pragma unroll
        for (int ks = 0; ks < 4; ks++) {
            unsigned ap[4];
            ap[0] = packbf(s[2*ks][0],   s[2*ks][1]);
            ap[1] = packbf(s[2*ks][2],   s[2*ks][3]);
            ap[2] = packbf(s[2*ks+1][0], s[2*ks+1][1]);
            ap[3] = packbf(s[2*ks+1][2], s[2*ks+1][3]);
            #pragma unroll
            for (int nb2 = 0; nb2 < 16; nb2++) {
                unsigned bv[2];
                int n0 = nb2 * 8 + gid;
                bv[0] = fsu[vbs + (8*ks + tig) * 136 + n0];
                bv[1] = fsu[vbs + (8*ks + tig + 4) * 136 + n0];
                MMA_BF16(oacc[nb2], ap, bv);
            }
        }
    }

    #pragma unroll
    for (int hf = 0; hf < 2; hf++) {
        float inv = 1.0f / lrow[hf];
        int gr = base + q0 + m0 + gid + hf * 8;
        #pragma unroll
        for (int nb2 = 0; nb2 < 16; nb2++) {
            F.Om[(size_t)gr * 256 + hoff2 + nb2 * 4 + tig] =
                packbf(oacc[nb2][2*hf] * inv, oacc[nb2][2*hf+1] * inv);
        }
    }
}

// ============================================================
// Host orchestration
// ============================================================
static inline void run_gemm2(GB g0, GB g1, int N0, int N1, int K, int act, int nz) {
    cudaFuncSetAttribute(gemm_bf, cudaFuncAttributeMaxDynamicSharedMemorySize, GM_SMEM);
    int nmax = N0 > N1 ? N0 : N1;
    dim3 grid(nmax / 128, NTOK / 128, nz);
    gemm_bf<<<grid, 256, GM_SMEM>>>(g0, g1, N0, N1, K, act);
}

static inline void run_flash2(FB f0, FB f1, int qld2, int kvld2, int nz) {
    cudaFuncSetAttribute(flash_bf, cudaFuncAttributeMaxDynamicSharedMemorySize, FL_SMEM_BYTES);
    dim3 grid(SEQ / 128, NBH, nz);
    flash_bf<<<grid, 256, FL_SMEM_BYTES>>>(f0, f1, qld2, kvld2);
}

extern "C" void kernel_launch(void* const* d_in, const int* in_sizes, int n_in,
                              void* d_out, int out_size) {
    const float* x1    = (const float*)d_in[0];
    const float* x2    = (const float*)d_in[1];
    const float* ln1_g = (const float*)d_in[2];
    const float* ln1_b = (const float*)d_in[3];
    const float* ln2_g = (const float*)d_in[4];
    const float* ln2_b = (const float*)d_in[5];
    const float* lnf_g = (const float*)d_in[6];
    const float* lnf_b = (const float*)d_in[7];
    const float* Wq1 = (const float*)d_in[8],  *bq1 = (const float*)d_in[9];
    const float* Wk1 = (const float*)d_in[10], *bk1 = (const float*)d_in[11];
    const float* Wv1 = (const float*)d_in[12], *bv1 = (const float*)d_in[13];
    const float* Wq2 = (const float*)d_in[14], *bq2 = (const float*)d_in[15];
    const float* Wk2 = (const float*)d_in[16], *bk2 = (const float*)d_in[17];
    const float* Wv2 = (const float*)d_in[18], *bv2 = (const float*)d_in[19];
    const float* Wq12 = (const float*)d_in[20], *bq12 = (const float*)d_in[21];
    const float* Wk12 = (const float*)d_in[22], *bk12 = (const float*)d_in[23];
    const float* Wv12 = (const float*)d_in[24], *bv12 = (const float*)d_in[25];
    const float* Wo  = (const float*)d_in[26], *bo = (const float*)d_in[27];
    const float* W1  = (const float*)d_in[28], *b1 = (const float*)d_in[29];
    const float* W2  = (const float*)d_in[30], *b2 = (const float*)d_in[31];
    float* out = (float*)d_out;

    unsigned *x1n, *x2n, *qv, *qkv1, *qkv2, *ctx1, *ctx2, *s1, *s2, *h1, *wb, *vt1, *vt2;
    float *xres, *bc;
    cudaGetSymbolAddress((void**)&x1n,  g_x1n);
    cudaGetSymbolAddress((void**)&x2n,  g_x2n);
    cudaGetSymbolAddress((void**)&qv,   g_qv);
    cudaGetSymbolAddress((void**)&qkv1, g_qkv1);
    cudaGetSymbolAddress((void**)&qkv2, g_qkv2);
    cudaGetSymbolAddress((void**)&ctx1, g_ctx1);
    cudaGetSymbolAddress((void**)&ctx2, g_ctx2);
    cudaGetSymbolAddress((void**)&s1,   g_s1);
    cudaGetSymbolAddress((void**)&s2,   g_s2);
    cudaGetSymbolAddress((void**)&h1,   g_h1);
    cudaGetSymbolAddress((void**)&wb,   g_wb);
    cudaGetSymbolAddress((void**)&vt1,  g_vt1);
    cudaGetSymbolAddress((void**)&vt2,  g_vt2);
    cudaGetSymbolAddress((void**)&xres, g_x);
    cudaGetSymbolAddress((void**)&bc,   g_bc);

    unsigned* wS1t  = wb;
    unsigned* wS2t  = wb + 393216;
    unsigned* wCQt  = wb + 786432;
    unsigned* wCKVt = wb + 917504;
    unsigned* wWot  = wb + 1179648;
    unsigned* wW1t  = wb + 1310720;
    unsigned* wW2t  = wb + 1572864;

    // 0) merged prep
    Prep p;
    p.ws[0] = Wq1;  p.wd[0] = wS1t;
    p.ws[1] = Wk1;  p.wd[1] = wS1t + 131072;
    p.ws[2] = Wv1;  p.wd[2] = wS1t + 262144;
    p.ws[3] = Wq2;  p.wd[3] = wS2t;
    p.ws[4] = Wk2;  p.wd[4] = wS2t + 131072;
    p.ws[5] = Wv2;  p.wd[5] = wS2t + 262144;
    p.ws[6] = Wq12; p.wd[6] = wCQt;
    p.ws[7] = Wk12; p.wd[7] = wCKVt;
    p.ws[8] = Wv12; p.wd[8] = wCKVt + 131072;
    p.ws[9] = Wo;   p.wd[9] = wWot;
    p.ws[10] = W1;  p.wd[10] = wW1t;
    p.ws[11] = W2;  p.wd[11] = wW2t;
    p.bs[0]=bq1; p.bs[1]=bk1; p.bs[2]=bv1; p.bs[3]=bq2;
    p.bs[4]=bk2; p.bs[5]=bv2; p.bs[6]=bk12; p.bs[7]=bv12;
    p.bdst = bc;
    prep_kernel<<<3586, dim3(32, 8)>>>(p);
    float* bS1 = bc, *bS2 = bc + 1536, *bCKV = bc + 3072;

    // 1) pre-LN, both streams
    ln_kernel<<<dim3(NTOK, 2), 256>>>(x1, ln1_g, ln1_b, x1n,
                                      x2, ln2_g, ln2_b, x2n);

    // 2+3) both self-attentions, z-batched; qkv gemm also emits Vt
    GB q0 = {x1n, wS1t, bS1, nullptr, nullptr, nullptr, qkv1, vt1, 1024};
    GB q1 = {x2n, wS2t, bS2, nullptr, nullptr, nullptr, qkv2, vt2, 1024};
    run_gemm2(q0, q1, 1536, 1536, 512, 0, 2);

    FB fa = {qkv1, qkv1 + 256, vt1, ctx1};
    FB fb = {qkv2, qkv2 + 256, vt2, ctx2};
    run_flash2(fa, fb, 768, 768, 2);

    GB w0 = {ctx1, wWot, bo, nullptr, x1n, nullptr, s1, nullptr, 0};
    GB w1 = {ctx2, wWot, bo, nullptr, x2n, nullptr, s2, nullptr, 0};
    run_gemm2(w0, w1, 512, 512, 512, 0, 2);

    // 4) cross-attention
    GB c0 = {s1, wCQt, bq12, nullptr, nullptr, nullptr, qv, nullptr, 0};
    GB c1 = {s2, wCKVt, bCKV, nullptr, nullptr, nullptr, qkv1, vt1, 512};
    run_gemm2(c0, c1, 512, 1024, 512, 0, 2);

    FB fc = {qv, qkv1, vt1, ctx1};
    run_flash2(fc, fc, 256, 512, 1);

    GB wc = {ctx1, wWot, bo, x1, nullptr, xres, nullptr, nullptr, 0};
    run_gemm2(wc, wc, 512, 512, 512, 0, 1);

    // 5) final LN + MLP
    ln_kernel<<<dim3(NTOK, 1), 256>>>(xres, lnf_g, lnf_b, x1n,
                                      xres, lnf_g, lnf_b, x1n);
    GB m1 = {x1n, wW1t, b1, nullptr, nullptr, nullptr, h1, nullptr, 0};
    run_gemm2(m1, m1, 1024, 1024, 512, 1, 1);
    GB m2 = {h1, wW2t, b2, xres, nullptr, out, nullptr, nullptr, 0};
    run_gemm2(m2, m2, 512, 512, 1024, 0, 1);
    (void)in_sizes; (void)n_in; (void)out_size;
}

// round 15
// speedup vs baseline: 2.8428x; 1.0611x over previous
#include <cuda_runtime.h>
#include <cuda_bf16.h>
#include <math.h>
#include <stdint.h>

// Problem constants
#define BATCH 16
#define SEQ   1024
#define NTOK  (BATCH*SEQ)        // 16384
#define DMODEL 512
#define NHEAD  4
#define HDIM   128
#define DMLP   1024
#define NBH    (BATCH*NHEAD)     // 64

// -------- scratch (no cudaMalloc allowed). bf16 tensors stored as packed u32 pairs.
__device__ unsigned g_x1n[NTOK*256];
__device__ unsigned g_x2n[NTOK*256];
__device__ unsigned g_qv [NTOK*256];
__device__ unsigned g_qkv1[NTOK*768];
__device__ unsigned g_qkv2[NTOK*768];
__device__ unsigned g_ctx1[NTOK*256];
__device__ unsigned g_ctx2[NTOK*256];
__device__ unsigned g_s1 [NTOK*256];
__device__ unsigned g_s2 [NTOK*256];
__device__ float    g_x  [NTOK*DMODEL];
__device__ unsigned g_h1 [NTOK*512];
__device__ unsigned g_wb [1835008];
__device__ float    g_bc [4096];
// pre-transposed V: [bh][token-pair][d] u32 (token-pair packed bf16)
__device__ unsigned g_vt1[NBH*512*128];
__device__ unsigned g_vt2[NBH*512*128];

extern __shared__ unsigned dsm[];

// ---------- helpers ----------
__device__ __forceinline__ unsigned packbf(float a, float b) {
    __nv_bfloat162 h = __floats2bfloat162_rn(a, b);
    return *reinterpret_cast<unsigned*>(&h);
}
__device__ __forceinline__ float2 unpackbf(unsigned u) {
    __nv_bfloat162 h = *reinterpret_cast<__nv_bfloat162*>(&u);
    return __bfloat1622float2(h);
}
__device__ __forceinline__ uint32_t smem_u32(const void* p) {
    uint32_t a;
    asm("{ .reg .u64 t; cvta.to.shared.u64 t, %1; cvt.u32.u64 %0, t; }" : "=r"(a) : "l"(p));
    return a;
}

#define MMA_BF16(acc, a, b) \
    asm volatile("mma.sync.aligned.m16n8k16.row.col.f32.bf16.bf16.f32 " \
        "{%0,%1,%2,%3}, {%4,%5,%6,%7}, {%8,%9}, {%0,%1,%2,%3};\n" \
        : "+f"((acc)[0]), "+f"((acc)[1]), "+f"((acc)[2]), "+f"((acc)[3]) \
        : "r"((a)[0]), "r"((a)[1]), "r"((a)[2]), "r"((a)[3]), "r"((b)[0]), "r"((b)[1]))

#define CP16(daddr, src) \
    asm volatile("cp.async.cg.shared.global [%0], [%1], 16;" :: "r"(daddr), "l"(src))
#define CPCOMMIT() asm volatile("cp.async.commit_group;" ::: "memory")
#define CPWAIT(n)  asm volatile("cp.async.wait_group %0;" :: "n"(n) : "memory")

#define LDSM4(r0, r1, r2, r3, addr) \
    asm volatile("ldmatrix.sync.aligned.m8n8.x4.shared.b16 {%0,%1,%2,%3}, [%4];" \
        : "=r"(r0), "=r"(r1), "=r"(r2), "=r"(r3) : "r"(addr))

// ============================================================
// Merged prep: 12 weight transposes + bias concat (one launch)
// ============================================================
struct Prep {
    const float* ws[12]; unsigned* wd[12];
    const float* bs[8];  float* bdst;
};

__device__ __forceinline__ void tile_transpose(const float* __restrict__ in,
                                               unsigned* __restrict__ out,
                                               int K, int N, int bx, int by) {
    __shared__ float t[32][33];
    int k0 = bx * 32, n0 = by * 32;
    int tx = threadIdx.x, ty = threadIdx.y;
    #pragma unroll
    for (int i = 0; i < 4; i++)
        t[ty + i*8][tx] = in[(size_t)(k0 + ty + i*8) * N + n0 + tx];
    __syncthreads();
    #pragma unroll
    for (int i = 0; i < 2; i++) {
        int kp = ty + 8 * i;
        out[(size_t)(n0 + tx) * (K >> 1) + (k0 >> 1) + kp] =
            packbf(t[2*kp][tx], t[2*kp+1][tx]);
    }
}

__global__ void prep_kernel(Prep p) {
    int id = blockIdx.x;
    if (id < 2560) {
        int m = id >> 8, t = id & 255;
        tile_transpose(p.ws[m], p.wd[m], 512, 512, t & 15, t >> 4);
    } else if (id < 3072) {
        int t = id - 2560;
        tile_transpose(p.ws[10], p.wd[10], 512, 1024, t & 15, t >> 4);
    } else if (id < 3584) {
        int t = id - 3072;
        tile_transpose(p.ws[11], p.wd[11], 1024, 512, t & 31, t >> 5);
    } else {
        int t = threadIdx.y * 32 + threadIdx.x;
        int i0 = (id - 3584) * 2048 + t * 8;
        #pragma unroll
        for (int j = 0; j < 8; j++) {
            int i = i0 + j;
            p.bdst[i] = p.bs[i >> 9][i & 511];
        }
    }
}

// ============================================================
// Batched LayerNorm: fp32 in, bf16 (packed) out.
// ============================================================
__global__ void ln_kernel(const float* __restrict__ xA, const float* __restrict__ gA,
                          const float* __restrict__ bA, unsigned* __restrict__ oA,
                          const float* __restrict__ xB, const float* __restrict__ gB,
                          const float* __restrict__ bB, unsigned* __restrict__ oB) {
    const float* x = blockIdx.y ? xB : xA;
    const float* g = blockIdx.y ? gB : gA;
    const float* b = blockIdx.y ? bB : bA;
    unsigned* out  = blockIdx.y ? oB : oA;

    int row = blockIdx.x;
    const float* xr = x + (size_t)row * DMODEL;
    unsigned* orow = out + (size_t)row * 256;
    int tid = threadIdx.x;
    float v0 = xr[2*tid], v1 = xr[2*tid + 1];

    __shared__ float sm[8];
    float s = v0 + v1;
    #pragma unroll
    for (int o = 16; o; o >>= 1) s += __shfl_xor_sync(0xffffffffu, s, o);
    if ((tid & 31) == 0) sm[tid >> 5] = s;
    __syncthreads();
    if (tid == 0) {
        float t = 0.f;
        #pragma unroll
        for (int i = 0; i < 8; i++) t += sm[i];
        sm[0] = t * (1.0f / DMODEL);
    }
    __syncthreads();
    float mean = sm[0];
    __syncthreads();

    float d0 = v0 - mean, d1 = v1 - mean;
    float q = d0 * d0 + d1 * d1;
    #pragma unroll
    for (int o = 16; o; o >>= 1) q += __shfl_xor_sync(0xffffffffu, q, o);
    if ((tid & 31) == 0) sm[tid >> 5] = q;
    __syncthreads();
    if (tid == 0) {
        float t = 0.f;
        #pragma unroll
        for (int i = 0; i < 8; i++) t += sm[i];
        sm[0] = rsqrtf(t * (1.0f / DMODEL) + 1e-6f);
    }
    __syncthreads();
    float rstd = sm[0];

    float y0 = d0 * rstd * g[2*tid]     + b[2*tid];
    float y1 = d1 * rstd * g[2*tid + 1] + b[2*tid + 1];
    orow[tid] = packbf(y0, y1);
}

// ============================================================
// bf16 GEMM, BK=32, 3-stage cp.async ring, one barrier per chunk,
// ldmatrix.x4 fragment loads (pitch 20 u32, conflict-free).
// ============================================================
#define GM_STAGE 5120
#define GM_SMEM  (3 * GM_STAGE * 4)

struct GB {
    const unsigned* A; const unsigned* BT; const float* bias;
    const float* addf; const unsigned* addb;
    float* Cf; unsigned* Cb;
    unsigned* Vt; int vcol0;
};

__global__ void __launch_bounds__(256, 2)
gemm_bf(GB g0, GB g1, int N0, int N1, int K, int act)
{
    GB G = blockIdx.z ? g1 : g0;
    int N = blockIdx.z ? N1 : N0;
    int bn = blockIdx.x * 128;
    if (bn >= N) return;

    uint32_t sb = smem_u32(dsm);
    int bm = blockIdx.y * 128;
    int tid = threadIdx.x;
    int warp = tid >> 5, lane = tid & 31;
    int wm = warp >> 2, wn = warp & 3;
    int gid = lane >> 2, tig = lane & 3;
    int lda2 = K >> 1;
    int chunks = K >> 5;   // 32-elem chunks (16 u32)

    // ldmatrix lane-address components (u32 offsets within a stage)
    int lmA_row = (lane & 15), lmA_koff = (lane >> 4) * 4;            // A tiles
    int lmB_row = (lane & 7) + ((lane >> 4) * 8), lmB_koff = ((lane >> 3) & 1) * 4;

    // loader: 512 segments of 16B per operand; thread does segs tid, tid+256
    int r0l = tid >> 2, q0l = (tid & 3) * 4;
    int r1l = (tid + 256) >> 2, q1l = ((tid + 256) & 3) * 4;
    const unsigned* Asrc0 = G.A + (size_t)(bm + r0l) * lda2 + q0l;
    const unsigned* Asrc1 = G.A + (size_t)(bm + r1l) * lda2 + q1l;
    const unsigned* Bsrc0 = G.BT + (size_t)(bn + r0l) * lda2 + q0l;
    const unsigned* Bsrc1 = G.BT + (size_t)(bn + r1l) * lda2 + q1l;
    int d0l = r0l * 20 + q0l, d1l = r1l * 20 + q1l;

    float acc[4][4][4];
    #pragma unroll
    for (int i = 0; i < 4; i++)
        #pragma unroll
        for (int j = 0; j < 4; j++)
            #pragma unroll
            for (int c = 0; c < 4; c++) acc[i][j][c] = 0.f;

    // prologue: chunks 0,1 into stages 0,1
    #pragma unroll
    for (int c = 0; c < 2; c++) {
        uint32_t st = sb + c * GM_STAGE * 4;
        CP16(st + d0l * 4, Asrc0 + c * 16);
        CP16(st + d1l * 4, Asrc1 + c * 16);
        CP16(st + (2560 + d0l) * 4, Bsrc0 + c * 16);
        CP16(st + (2560 + d1l) * 4, Bsrc1 + c * 16);
        CPCOMMIT();
    }

    int stc = 0;
    for (int c = 0; c < chunks; c++) {
        CPWAIT(1);
        __syncthreads();
        if (c + 2 < chunks) {
            int stp = stc + 2; if (stp >= 3) stp -= 3;
            uint32_t st = sb + stp * GM_STAGE * 4;
            CP16(st + d0l * 4, Asrc0 + (c + 2) * 16);
            CP16(st + d1l * 4, Asrc1 + (c + 2) * 16);
            CP16(st + (2560 + d0l) * 4, Bsrc0 + (c + 2) * 16);
            CP16(st + (2560 + d1l) * 4, Bsrc1 + (c + 2) * 16);
        }
        CPCOMMIT();

        uint32_t uAs = sb + stc * GM_STAGE * 4;
        uint32_t uBs = uAs + 2560 * 4;
        #pragma unroll
        for (int ks = 0; ks < 2; ks++) {
            int kb = ks * 8;
            unsigned af[4][4], bf2[4][2];
            #pragma unroll
            for (int ma = 0; ma < 4; ma++) {
                uint32_t aaddr = uAs +
                    ((wm * 64 + ma * 16 + lmA_row) * 20 + kb + lmA_koff) * 4;
                LDSM4(af[ma][0], af[ma][1], af[ma][2], af[ma][3], aaddr);
            }
            #pragma unroll
            for (int nbp = 0; nbp < 2; nbp++) {
                uint32_t baddr = uBs +
                    ((wn * 32 + nbp * 16 + lmB_row) * 20 + kb + lmB_koff) * 4;
                LDSM4(bf2[2*nbp][0], bf2[2*nbp][1],
                      bf2[2*nbp+1][0], bf2[2*nbp+1][1], baddr);
            }
            #pragma unroll
            for (int ma = 0; ma < 4; ma++)
                #pragma unroll
                for (int nb = 0; nb < 4; nb++)
                    MMA_BF16(acc[ma][nb], af[ma], bf2[nb]);
        }
        if (++stc >= 3) stc = 0;
    }

    // epilogue
    #pragma unroll
    for (int ma = 0; ma < 4; ma++) {
        #pragma unroll
        for (int nb = 0; nb < 4; nb++) {
            int c = bn + wn * 32 + nb * 8 + tig * 2;
            float bv0 = G.bias ? G.bias[c] : 0.f;
            float bv1 = G.bias ? G.bias[c + 1] : 0.f;
            #pragma unroll
            for (int half = 0; half < 2; half++) {
                int r = bm + wm * 64 + ma * 16 + gid + half * 8;
                float t0 = acc[ma][nb][half * 2 + 0] + bv0;
                float t1 = acc[ma][nb][half * 2 + 1] + bv1;
                if (act) {
                    t0 = 0.5f * t0 * (1.0f + erff(t0 * 0.70710678118654752f));
                    t1 = 0.5f * t1 * (1.0f + erff(t1 * 0.70710678118654752f));
                }
                size_t off = (size_t)r * N + c;
                if (G.addf) { t0 += G.addf[off]; t1 += G.addf[off + 1]; }
                if (G.addb) {
                    float2 av = unpackbf(G.addb[(size_t)r * (N >> 1) + (c >> 1)]);
                    t0 += av.x; t1 += av.y;
                }
                if (G.Cf) *(float2*)&G.Cf[off] = make_float2(t0, t1);
                if (G.Cb) G.Cb[(size_t)r * (N >> 1) + (c >> 1)] = packbf(t0, t1);
                if (G.Vt && c >= G.vcol0) {
                    float u0 = __shfl_xor_sync(0xffffffffu, t0, 4);
                    float u1 = __shfl_xor_sync(0xffffffffu, t1, 4);
                    if (!(gid & 1)) {
                        int d = c - G.vcol0;
                        int h = d >> 7, dh = d & 127;
                        int bb = r >> 10, tp = (r & 1023) >> 1;
                        size_t vo = (((size_t)(bb * 4 + h) * 512) + tp) * 128 + dh;
                        G.Vt[vo]     = packbf(t0, u0);
                        G.Vt[vo + 1] = packbf(t1, u1);
                    }
                }
            }
        }
    }
}

// ============================================================
// Flash v3 (R13, unchanged)
// ============================================================
#define SQ_O 0
#define SK_O 8704
#define SV_O 17408
#define FL_SMEM_BYTES (26112 * 4)
#define NCH 16   // SEQ / 64

struct FB { const unsigned* Qm; const unsigned* Km; const unsigned* Vt; unsigned* Om; };

__global__ void __launch_bounds__(256, 2)
flash_bf(FB f0, FB f1, int qld2, int kvld2)
{
    FB F = blockIdx.z ? f1 : f0;
    unsigned* fsu = dsm;
    uint32_t sb = smem_u32(dsm);

    int tid = threadIdx.x;
    int warp = tid >> 5, lane = tid & 31;
    int gid = lane >> 2, tig = lane & 3;
    int m0 = warp * 16;

    int bh = blockIdx.y, b = bh >> 2, h = bh & 3;
    int q0 = blockIdx.x * 128, base = b * SEQ;
    int hoff2 = h * 64;

    {
        #pragma unroll
        for (int i = 0; i < 8; i++) {
            int seg = tid + 256 * i;
            int r = seg >> 4, sg = seg & 15;
            CP16(sb + (SQ_O + r * 68 + sg * 4) * 4,
                 F.Qm + (size_t)(base + q0 + r) * qld2 + hoff2 + sg * 4);
        }
        #pragma unroll
        for (int i = 0; i < 4; i++) {
            int seg = tid + 256 * i;
            int r = seg >> 4, sg = seg & 15;
            CP16(sb + (SK_O + r * 68 + sg * 4) * 4,
                 F.Km + (size_t)(base + r) * kvld2 + hoff2 + sg * 4);
        }
        #pragma unroll
        for (int i = 0; i < 4; i++) {
            int seg = tid + 256 * i;
            int row = seg >> 5, sg = seg & 31;
            CP16(sb + (SV_O + row * 136 + sg * 4) * 4,
                 F.Vt + (((size_t)bh * 512) + row) * 128 + sg * 4);
        }
        CPCOMMIT();
    }

    float oacc[16][4];
    #pragma unroll
    for (int i = 0; i < 16; i++)
        #pragma unroll
        for (int c = 0; c < 4; c++) oacc[i][c] = 0.f;
    float mrow[2] = {-1e30f, -1e30f}, lrow[2] = {0.f, 0.f};

    const float scale = 0.08838834764831845f;

    for (int ch = 0; ch < NCH; ch++) {
        CPWAIT(0);
        __syncthreads();

        if (ch + 1 < NCH) {
            int nb2f = (ch + 1) & 1;
            #pragma unroll
            for (int i = 0; i < 4; i++) {
                int seg = tid + 256 * i;
                int r = seg >> 4, sg = seg & 15;
                CP16(sb + (SK_O + nb2f * 4352 + r * 68 + sg * 4) * 4,
                     F.Km + (size_t)(base + (ch + 1) * 64 + r) * kvld2 + hoff2 + sg * 4);
            }
            #pragma unroll
            for (int i = 0; i < 4; i++) {
                int seg = tid + 256 * i;
                int row = seg >> 5, sg = seg & 31;
                CP16(sb + (SV_O + nb2f * 4352 + row * 136 + sg * 4) * 4,
                     F.Vt + (((size_t)bh * 512) + (ch + 1) * 32 + row) * 128 + sg * 4);
            }
            CPCOMMIT();
        }

        int kbs = SK_O + (ch & 1) * 4352;
        int vbs = SV_O + (ch & 1) * 4352;

        float s[8][4];
        #pragma unroll
        for (int i = 0; i < 8; i++)
            #pragma unroll
            for (int c = 0; c < 4; c++) s[i][c] = 0.f;

        #pragma unroll
        for (int ks = 0; ks < 8; ks++) {
            int kb = ks * 8;
            unsigned af[4];
            int mb = (m0 + gid) * 68 + kb + tig;
            af[0] = fsu[SQ_O + mb];
            af[1] = fsu[SQ_O + mb + 544];
            af[2] = fsu[SQ_O + mb + 4];
            af[3] = fsu[SQ_O + mb + 548];
            #pragma unroll
            for (int nb = 0; nb < 8; nb++) {
                unsigned bf2[2];
                int nbase = (nb * 8 + gid) * 68 + kb + tig;
                bf2[0] = fsu[kbs + nbase];
                bf2[1] = fsu[kbs + nbase + 4];
                MMA_BF16(s[nb], af, bf2);
            }
        }

        #pragma unroll
        for (int hf = 0; hf < 2; hf++) {
            float mx = -1e30f;
            #pragma unroll
            for (int nb = 0; nb < 8; nb++)
                mx = fmaxf(mx, fmaxf(s[nb][2*hf], s[nb][2*hf+1]));
            mx *= scale;
            mx = fmaxf(mx, __shfl_xor_sync(0xffffffffu, mx, 1));
            mx = fmaxf(mx, __shfl_xor_sync(0xffffffffu, mx, 2));
            float nm = fmaxf(mrow[hf], mx);
            float alpha = __expf(mrow[hf] - nm);
            mrow[hf] = nm;
            float sum = 0.f;
            #pragma unroll
            for (int nb = 0; nb < 8; nb++) {
                float p0 = __expf(s[nb][2*hf]   * scale - nm);
                float p1 = __expf(s[nb][2*hf+1] * scale - nm);
                s[nb][2*hf] = p0; s[nb][2*hf+1] = p1;
                sum += p0 + p1;
            }
            sum += __shfl_xor_sync(0xffffffffu, sum, 1);
            sum += __shfl_xor_sync(0xffffffffu, sum, 2);
            lrow[hf] = lrow[hf] * alpha + sum;
            #pragma unroll
            for (int nb2 = 0; nb2 < 16; nb2++) {
                oacc[nb2][2*hf]   *= alpha;
                oacc[nb2][2*hf+1] *= alpha;
            }
        }

        #pragma unroll
        for (int ks = 0; ks < 4; ks++) {
            unsigned ap[4];
            ap[0] = packbf(s[2*ks][0],   s[2*ks][1]);
            ap[1] = packbf(s[2*ks][2],   s[2*ks][3]);
            ap[2] = packbf(s[2*ks+1][0], s[2*ks+1][1]);
            ap[3] = packbf(s[2*ks+1][2], s[2*ks+1][3]);
            #pragma unroll
            for (int nb2 = 0; nb2 < 16; nb2++) {
                unsigned bv[2];
                int n0 = nb2 * 8 + gid;
                bv[0] = fsu[vbs + (8*ks + tig) * 136 + n0];
                bv[1] = fsu[vbs + (8*ks + tig + 4) * 136 + n0];
                MMA_BF16(oacc[nb2], ap, bv);
            }
        }
    }

    #pragma unroll
    for (int hf = 0; hf < 2; hf++) {
        float inv = 1.0f / lrow[hf];
        int gr = base + q0 + m0 + gid + hf * 8;
        #pragma unroll
        for (int nb2 = 0; nb2 < 16; nb2++) {
            F.Om[(size_t)gr * 256 + hoff2 + nb2 * 4 + tig] =
                packbf(oacc[nb2][2*hf] * inv, oacc[nb2][2*hf+1] * inv);
        }
    }
}

// ============================================================
// Host orchestration
// ============================================================
static inline void run_gemm2(GB g0, GB g1, int N0, int N1, int K, int act, int nz) {
    cudaFuncSetAttribute(gemm_bf, cudaFuncAttributeMaxDynamicSharedMemorySize, GM_SMEM);
    int nmax = N0 > N1 ? N0 : N1;
    dim3 grid(nmax / 128, NTOK / 128, nz);
    gemm_bf<<<grid, 256, GM_SMEM>>>(g0, g1, N0, N1, K, act);
}

static inline void run_flash2(FB f0, FB f1, int qld2, int kvld2, int nz) {
    cudaFuncSetAttribute(flash_bf, cudaFuncAttributeMaxDynamicSharedMemorySize, FL_SMEM_BYTES);
    dim3 grid(SEQ / 128, NBH, nz);
    flash_bf<<<grid, 256, FL_SMEM_BYTES>>>(f0, f1, qld2, kvld2);
}

extern "C" void kernel_launch(void* const* d_in, const int* in_sizes, int n_in,
                              void* d_out, int out_size) {
    const float* x1    = (const float*)d_in[0];
    const float* x2    = (const float*)d_in[1];
    const float* ln1_g = (const float*)d_in[2];
    const float* ln1_b = (const float*)d_in[3];
    const float* ln2_g = (const float*)d_in[4];
    const float* ln2_b = (const float*)d_in[5];
    const float* lnf_g = (const float*)d_in[6];
    const float* lnf_b = (const float*)d_in[7];
    const float* Wq1 = (const float*)d_in[8],  *bq1 = (const float*)d_in[9];
    const float* Wk1 = (const float*)d_in[10], *bk1 = (const float*)d_in[11];
    const float* Wv1 = (const float*)d_in[12], *bv1 = (const float*)d_in[13];
    const float* Wq2 = (const float*)d_in[14], *bq2 = (const float*)d_in[15];
    const float* Wk2 = (const float*)d_in[16], *bk2 = (const float*)d_in[17];
    const float* Wv2 = (const float*)d_in[18], *bv2 = (const float*)d_in[19];
    const float* Wq12 = (const float*)d_in[20], *bq12 = (const float*)d_in[21];
    const float* Wk12 = (const float*)d_in[22], *bk12 = (const float*)d_in[23];
    const float* Wv12 = (const float*)d_in[24], *bv12 = (const float*)d_in[25];
    const float* Wo  = (const float*)d_in[26], *bo = (const float*)d_in[27];
    const float* W1  = (const float*)d_in[28], *b1 = (const float*)d_in[29];
    const float* W2  = (const float*)d_in[30], *b2 = (const float*)d_in[31];
    float* out = (float*)d_out;

    unsigned *x1n, *x2n, *qv, *qkv1, *qkv2, *ctx1, *ctx2, *s1, *s2, *h1, *wb, *vt1, *vt2;
    float *xres, *bc;
    cudaGetSymbolAddress((void**)&x1n,  g_x1n);
    cudaGetSymbolAddress((void**)&x2n,  g_x2n);
    cudaGetSymbolAddress((void**)&qv,   g_qv);
    cudaGetSymbolAddress((void**)&qkv1, g_qkv1);
    cudaGetSymbolAddress((void**)&qkv2, g_qkv2);
    cudaGetSymbolAddress((void**)&ctx1, g_ctx1);
    cudaGetSymbolAddress((void**)&ctx2, g_ctx2);
    cudaGetSymbolAddress((void**)&s1,   g_s1);
    cudaGetSymbolAddress((void**)&s2,   g_s2);
    cudaGetSymbolAddress((void**)&h1,   g_h1);
    cudaGetSymbolAddress((void**)&wb,   g_wb);
    cudaGetSymbolAddress((void**)&vt1,  g_vt1);
    cudaGetSymbolAddress((void**)&vt2,  g_vt2);
    cudaGetSymbolAddress((void**)&xres, g_x);
    cudaGetSymbolAddress((void**)&bc,   g_bc);

    unsigned* wS1t  = wb;
    unsigned* wS2t  = wb + 393216;
    unsigned* wCQt  = wb + 786432;
    unsigned* wCKVt = wb + 917504;
    unsigned* wWot  = wb + 1179648;
    unsigned* wW1t  = wb + 1310720;
    unsigned* wW2t  = wb + 1572864;

    // 0) merged prep
    Prep p;
    p.ws[0] = Wq1;  p.wd[0] = wS1t;
    p.ws[1] = Wk1;  p.wd[1] = wS1t + 131072;
    p.ws[2] = Wv1;  p.wd[2] = wS1t + 262144;
    p.ws[3] = Wq2;  p.wd[3] = wS2t;
    p.ws[4] = Wk2;  p.wd[4] = wS2t + 131072;
    p.ws[5] = Wv2;  p.wd[5] = wS2t + 262144;
    p.ws[6] = Wq12; p.wd[6] = wCQt;
    p.ws[7] = Wk12; p.wd[7] = wCKVt;
    p.ws[8] = Wv12; p.wd[8] = wCKVt + 131072;
    p.ws[9] = Wo;   p.wd[9] = wWot;
    p.ws[10] = W1;  p.wd[10] = wW1t;
    p.ws[11] = W2;  p.wd[11] = wW2t;
    p.bs[0]=bq1; p.bs[1]=bk1; p.bs[2]=bv1; p.bs[3]=bq2;
    p.bs[4]=bk2; p.bs[5]=bv2; p.bs[6]=bk12; p.bs[7]=bv12;
    p.bdst = bc;
    prep_kernel<<<3586, dim3(32, 8)>>>(p);
    float* bS1 = bc, *bS2 = bc + 1536, *bCKV = bc + 3072;

    // 1) pre-LN, both streams
    ln_kernel<<<dim3(NTOK, 2), 256>>>(x1, ln1_g, ln1_b, x1n,
                                      x2, ln2_g, ln2_b, x2n);

    // 2+3) both self-attentions, z-batched; qkv gemm also emits Vt
    GB q0 = {x1n, wS1t, bS1, nullptr, nullptr, nullptr, qkv1, vt1, 1024};
    GB q1 = {x2n, wS2t, bS2, nullptr, nullptr, nullptr, qkv2, vt2, 1024};
    run_gemm2(q0, q1, 1536, 1536, 512, 0, 2);

    FB fa = {qkv1, qkv1 + 256, vt1, ctx1};
    FB fb = {qkv2, qkv2 + 256, vt2, ctx2};
    run_flash2(fa, fb, 768, 768, 2);

    GB w0 = {ctx1, wWot, bo, nullptr, x1n, nullptr, s1, nullptr, 0};
    GB w1 = {ctx2, wWot, bo, nullptr, x2n, nullptr, s2, nullptr, 0};
    run_gemm2(w0, w1, 512, 512, 512, 0, 2);

    // 4) cross-attention
    GB c0 = {s1, wCQt, bq12, nullptr, nullptr, nullptr, qv, nullptr, 0};
    GB c1 = {s2, wCKVt, bCKV, nullptr, nullptr, nullptr, qkv1, vt1, 512};
    run_gemm2(c0, c1, 512, 1024, 512, 0, 2);

    FB fc = {qv, qkv1, vt1, ctx1};
    run_flash2(fc, fc, 256, 512, 1);

    GB wc = {ctx1, wWot, bo, x1, nullptr, xres, nullptr, nullptr, 0};
    run_gemm2(wc, wc, 512, 512, 512, 0, 1);

    // 5) final LN + MLP
    ln_kernel<<<dim3(NTOK, 1), 256>>>(xres, lnf_g, lnf_b, x1n,
                                      xres, lnf_g, lnf_b, x1n);
    GB m1 = {x1n, wW1t, b1, nullptr, nullptr, nullptr, h1, nullptr, 0};
    run_gemm2(m1, m1, 1024, 1024, 512, 1, 1);
    GB m2 = {h1, wW2t, b2, xres, nullptr, out, nullptr, nullptr, 0};
    run_gemm2(m2, m2, 512, 512, 1024, 0, 1);
    (void)in_sizes; (void)n_in; (void)out_size;
}

// round 16
// speedup vs baseline: 2.9881x; 1.0511x over previous
#include <cuda_runtime.h>
#include <cuda_bf16.h>
#include <math.h>
#include <stdint.h>

// Problem constants
#define BATCH 16
#define SEQ   1024
#define NTOK  (BATCH*SEQ)        // 16384
#define DMODEL 512
#define NHEAD  4
#define HDIM   128
#define DMLP   1024
#define NBH    (BATCH*NHEAD)     // 64

// -------- scratch (no cudaMalloc allowed). bf16 tensors stored as packed u32 pairs.
__device__ unsigned g_x1n[NTOK*256];
__device__ unsigned g_x2n[NTOK*256];
__device__ unsigned g_qv [NTOK*256];
__device__ unsigned g_qkv1[NTOK*768];
__device__ unsigned g_qkv2[NTOK*768];
__device__ unsigned g_ctx1[NTOK*256];
__device__ unsigned g_ctx2[NTOK*256];
__device__ unsigned g_s1 [NTOK*256];
__device__ unsigned g_s2 [NTOK*256];
__device__ float    g_x  [NTOK*DMODEL];
__device__ unsigned g_h1 [NTOK*512];
__device__ unsigned g_wb [1835008];
__device__ float    g_bc [4096];
// pre-transposed V: [bh][d][token-pair] u32 (token-pair packed bf16)
__device__ unsigned g_vt1[NBH*128*512];
__device__ unsigned g_vt2[NBH*128*512];

extern __shared__ unsigned dsm[];

// ---------- helpers ----------
__device__ __forceinline__ unsigned packbf(float a, float b) {
    __nv_bfloat162 h = __floats2bfloat162_rn(a, b);
    return *reinterpret_cast<unsigned*>(&h);
}
__device__ __forceinline__ float2 unpackbf(unsigned u) {
    __nv_bfloat162 h = *reinterpret_cast<__nv_bfloat162*>(&u);
    return __bfloat1622float2(h);
}
__device__ __forceinline__ uint32_t smem_u32(const void* p) {
    uint32_t a;
    asm("{ .reg .u64 t; cvta.to.shared.u64 t, %1; cvt.u32.u64 %0, t; }" : "=r"(a) : "l"(p));
    return a;
}

#define MMA_BF16(acc, a, b) \
    asm volatile("mma.sync.aligned.m16n8k16.row.col.f32.bf16.bf16.f32 " \
        "{%0,%1,%2,%3}, {%4,%5,%6,%7}, {%8,%9}, {%0,%1,%2,%3};\n" \
        : "+f"((acc)[0]), "+f"((acc)[1]), "+f"((acc)[2]), "+f"((acc)[3]) \
        : "r"((a)[0]), "r"((a)[1]), "r"((a)[2]), "r"((a)[3]), "r"((b)[0]), "r"((b)[1]))

#define CP16(daddr, src) \
    asm volatile("cp.async.cg.shared.global [%0], [%1], 16;" :: "r"(daddr), "l"(src))
#define CPCOMMIT() asm volatile("cp.async.commit_group;" ::: "memory")
#define CPWAIT(n)  asm volatile("cp.async.wait_group %0;" :: "n"(n) : "memory")

#define LDSM4(r0, r1, r2, r3, addr) \
    asm volatile("ldmatrix.sync.aligned.m8n8.x4.shared.b16 {%0,%1,%2,%3}, [%4];" \
        : "=r"(r0), "=r"(r1), "=r"(r2), "=r"(r3) : "r"(addr))

// ============================================================
// Merged prep: 12 weight transposes + bias concat (one launch)
// ============================================================
struct Prep {
    const float* ws[12]; unsigned* wd[12];
    const float* bs[8];  float* bdst;
};

__device__ __forceinline__ void tile_transpose(const float* __restrict__ in,
                                               unsigned* __restrict__ out,
                                               int K, int N, int bx, int by) {
    __shared__ float t[32][33];
    int k0 = bx * 32, n0 = by * 32;
    int tx = threadIdx.x, ty = threadIdx.y;
    #pragma unroll
    for (int i = 0; i < 4; i++)
        t[ty + i*8][tx] = in[(size_t)(k0 + ty + i*8) * N + n0 + tx];
    __syncthreads();
    #pragma unroll
    for (int i = 0; i < 2; i++) {
        int kp = ty + 8 * i;
        out[(size_t)(n0 + tx) * (K >> 1) + (k0 >> 1) + kp] =
            packbf(t[2*kp][tx], t[2*kp+1][tx]);
    }
}

__global__ void prep_kernel(Prep p) {
    int id = blockIdx.x;
    if (id < 2560) {
        int m = id >> 8, t = id & 255;
        tile_transpose(p.ws[m], p.wd[m], 512, 512, t & 15, t >> 4);
    } else if (id < 3072) {
        int t = id - 2560;
        tile_transpose(p.ws[10], p.wd[10], 512, 1024, t & 15, t >> 4);
    } else if (id < 3584) {
        int t = id - 3072;
        tile_transpose(p.ws[11], p.wd[11], 1024, 512, t & 31, t >> 5);
    } else {
        int t = threadIdx.y * 32 + threadIdx.x;
        int i0 = (id - 3584) * 2048 + t * 8;
        #pragma unroll
        for (int j = 0; j < 8; j++) {
            int i = i0 + j;
            p.bdst[i] = p.bs[i >> 9][i & 511];
        }
    }
}

// ============================================================
// Batched LayerNorm: fp32 in, bf16 (packed) out.
// ============================================================
__global__ void ln_kernel(const float* __restrict__ xA, const float* __restrict__ gA,
                          const float* __restrict__ bA, unsigned* __restrict__ oA,
                          const float* __restrict__ xB, const float* __restrict__ gB,
                          const float* __restrict__ bB, unsigned* __restrict__ oB) {
    const float* x = blockIdx.y ? xB : xA;
    const float* g = blockIdx.y ? gB : gA;
    const float* b = blockIdx.y ? bB : bA;
    unsigned* out  = blockIdx.y ? oB : oA;

    int row = blockIdx.x;
    const float* xr = x + (size_t)row * DMODEL;
    unsigned* orow = out + (size_t)row * 256;
    int tid = threadIdx.x;
    float v0 = xr[2*tid], v1 = xr[2*tid + 1];

    __shared__ float sm[8];
    float s = v0 + v1;
    #pragma unroll
    for (int o = 16; o; o >>= 1) s += __shfl_xor_sync(0xffffffffu, s, o);
    if ((tid & 31) == 0) sm[tid >> 5] = s;
    __syncthreads();
    if (tid == 0) {
        float t = 0.f;
        #pragma unroll
        for (int i = 0; i < 8; i++) t += sm[i];
        sm[0] = t * (1.0f / DMODEL);
    }
    __syncthreads();
    float mean = sm[0];
    __syncthreads();

    float d0 = v0 - mean, d1 = v1 - mean;
    float q = d0 * d0 + d1 * d1;
    #pragma unroll
    for (int o = 16; o; o >>= 1) q += __shfl_xor_sync(0xffffffffu, q, o);
    if ((tid & 31) == 0) sm[tid >> 5] = q;
    __syncthreads();
    if (tid == 0) {
        float t = 0.f;
        #pragma unroll
        for (int i = 0; i < 8; i++) t += sm[i];
        sm[0] = rsqrtf(t * (1.0f / DMODEL) + 1e-6f);
    }
    __syncthreads();
    float rstd = sm[0];

    float y0 = d0 * rstd * g[2*tid]     + b[2*tid];
    float y1 = d1 * rstd * g[2*tid + 1] + b[2*tid + 1];
    orow[tid] = packbf(y0, y1);
}

// ============================================================
// bf16 GEMM, BK=32, 3-stage cp.async ring, one barrier per chunk,
// ldmatrix.x4 fragment loads (pitch 20 u32, conflict-free).
// Vt epilogue now emits [bh][d][token-pair] layout.
// ============================================================
#define GM_STAGE 5120
#define GM_SMEM  (3 * GM_STAGE * 4)

struct GB {
    const unsigned* A; const unsigned* BT; const float* bias;
    const float* addf; const unsigned* addb;
    float* Cf; unsigned* Cb;
    unsigned* Vt; int vcol0;
};

__global__ void __launch_bounds__(256, 2)
gemm_bf(GB g0, GB g1, int N0, int N1, int K, int act)
{
    GB G = blockIdx.z ? g1 : g0;
    int N = blockIdx.z ? N1 : N0;
    int bn = blockIdx.x * 128;
    if (bn >= N) return;

    uint32_t sb = smem_u32(dsm);
    int bm = blockIdx.y * 128;
    int tid = threadIdx.x;
    int warp = tid >> 5, lane = tid & 31;
    int wm = warp >> 2, wn = warp & 3;
    int gid = lane >> 2, tig = lane & 3;
    int lda2 = K >> 1;
    int chunks = K >> 5;

    int lmA_row = (lane & 15), lmA_koff = (lane >> 4) * 4;
    int lmB_row = (lane & 7) + ((lane >> 4) * 8), lmB_koff = ((lane >> 3) & 1) * 4;

    int r0l = tid >> 2, q0l = (tid & 3) * 4;
    int r1l = (tid + 256) >> 2, q1l = ((tid + 256) & 3) * 4;
    const unsigned* Asrc0 = G.A + (size_t)(bm + r0l) * lda2 + q0l;
    const unsigned* Asrc1 = G.A + (size_t)(bm + r1l) * lda2 + q1l;
    const unsigned* Bsrc0 = G.BT + (size_t)(bn + r0l) * lda2 + q0l;
    const unsigned* Bsrc1 = G.BT + (size_t)(bn + r1l) * lda2 + q1l;
    int d0l = r0l * 20 + q0l, d1l = r1l * 20 + q1l;

    float acc[4][4][4];
    #pragma unroll
    for (int i = 0; i < 4; i++)
        #pragma unroll
        for (int j = 0; j < 4; j++)
            #pragma unroll
            for (int c = 0; c < 4; c++) acc[i][j][c] = 0.f;

    #pragma unroll
    for (int c = 0; c < 2; c++) {
        uint32_t st = sb + c * GM_STAGE * 4;
        CP16(st + d0l * 4, Asrc0 + c * 16);
        CP16(st + d1l * 4, Asrc1 + c * 16);
        CP16(st + (2560 + d0l) * 4, Bsrc0 + c * 16);
        CP16(st + (2560 + d1l) * 4, Bsrc1 + c * 16);
        CPCOMMIT();
    }

    int stc = 0;
    for (int c = 0; c < chunks; c++) {
        CPWAIT(1);
        __syncthreads();
        if (c + 2 < chunks) {
            int stp = stc + 2; if (stp >= 3) stp -= 3;
            uint32_t st = sb + stp * GM_STAGE * 4;
            CP16(st + d0l * 4, Asrc0 + (c + 2) * 16);
            CP16(st + d1l * 4, Asrc1 + (c + 2) * 16);
            CP16(st + (2560 + d0l) * 4, Bsrc0 + (c + 2) * 16);
            CP16(st + (2560 + d1l) * 4, Bsrc1 + (c + 2) * 16);
        }
        CPCOMMIT();

        uint32_t uAs = sb + stc * GM_STAGE * 4;
        uint32_t uBs = uAs + 2560 * 4;
        #pragma unroll
        for (int ks = 0; ks < 2; ks++) {
            int kb = ks * 8;
            unsigned af[4][4], bf2[4][2];
            #pragma unroll
            for (int ma = 0; ma < 4; ma++) {
                uint32_t aaddr = uAs +
                    ((wm * 64 + ma * 16 + lmA_row) * 20 + kb + lmA_koff) * 4;
                LDSM4(af[ma][0], af[ma][1], af[ma][2], af[ma][3], aaddr);
            }
            #pragma unroll
            for (int nbp = 0; nbp < 2; nbp++) {
                uint32_t baddr = uBs +
                    ((wn * 32 + nbp * 16 + lmB_row) * 20 + kb + lmB_koff) * 4;
                LDSM4(bf2[2*nbp][0], bf2[2*nbp][1],
                      bf2[2*nbp+1][0], bf2[2*nbp+1][1], baddr);
            }
            #pragma unroll
            for (int ma = 0; ma < 4; ma++)
                #pragma unroll
                for (int nb = 0; nb < 4; nb++)
                    MMA_BF16(acc[ma][nb], af[ma], bf2[nb]);
        }
        if (++stc >= 3) stc = 0;
    }

    // epilogue
    #pragma unroll
    for (int ma = 0; ma < 4; ma++) {
        #pragma unroll
        for (int nb = 0; nb < 4; nb++) {
            int c = bn + wn * 32 + nb * 8 + tig * 2;
            float bv0 = G.bias ? G.bias[c] : 0.f;
            float bv1 = G.bias ? G.bias[c + 1] : 0.f;
            #pragma unroll
            for (int half = 0; half < 2; half++) {
                int r = bm + wm * 64 + ma * 16 + gid + half * 8;
                float t0 = acc[ma][nb][half * 2 + 0] + bv0;
                float t1 = acc[ma][nb][half * 2 + 1] + bv1;
                if (act) {
                    t0 = 0.5f * t0 * (1.0f + erff(t0 * 0.70710678118654752f));
                    t1 = 0.5f * t1 * (1.0f + erff(t1 * 0.70710678118654752f));
                }
                size_t off = (size_t)r * N + c;
                if (G.addf) { t0 += G.addf[off]; t1 += G.addf[off + 1]; }
                if (G.addb) {
                    float2 av = unpackbf(G.addb[(size_t)r * (N >> 1) + (c >> 1)]);
                    t0 += av.x; t1 += av.y;
                }
                if (G.Cf) *(float2*)&G.Cf[off] = make_float2(t0, t1);
                if (G.Cb) G.Cb[(size_t)r * (N >> 1) + (c >> 1)] = packbf(t0, t1);
                // Vt emit, [bh][d][token-pair] layout
                if (G.Vt && c >= G.vcol0) {
                    float u0 = __shfl_xor_sync(0xffffffffu, t0, 4);
                    float u1 = __shfl_xor_sync(0xffffffffu, t1, 4);
                    if (!(gid & 1)) {
                        int d = c - G.vcol0;
                        int h = d >> 7, dh = d & 127;
                        int bb = r >> 10, tp = (r & 1023) >> 1;
                        size_t vo = (((size_t)(bb * 4 + h) * 128) + dh) * 512 + tp;
                        G.Vt[vo]       = packbf(t0, u0);
                        G.Vt[vo + 512] = packbf(t1, u1);
                    }
                }
            }
        }
    }
}

// ============================================================
// Flash v4: warp-owns-rows + ldmatrix fragments everywhere.
// sQ [m][k] pitch 68; sK[2] [n][k] pitch 68; sV[2] [d][kp] pitch 36.
// smem u32: sQ @0 (8704); sK @8704 (2x4352); sV @17408 (2x4608).
// Total 26624 u32 = 106496 B. 2 CTAs/SM.
// ============================================================
#define SQ_O 0
#define SK_O 8704
#define SV_O 17408
#define FL_SMEM_BYTES (26624 * 4)
#define NCH 16   // SEQ / 64

struct FB { const unsigned* Qm; const unsigned* Km; const unsigned* Vt; unsigned* Om; };

__global__ void __launch_bounds__(256, 2)
flash_bf(FB f0, FB f1, int qld2, int kvld2)
{
    FB F = blockIdx.z ? f1 : f0;
    uint32_t sb = smem_u32(dsm);

    int tid = threadIdx.x;
    int warp = tid >> 5, lane = tid & 31;
    int gid = lane >> 2, tig = lane & 3;
    int m0 = warp * 16;

    int lmA_row = (lane & 15), lmA_koff = (lane >> 4) * 4;
    int lmB_row = (lane & 7) + ((lane >> 4) * 8), lmB_koff = ((lane >> 3) & 1) * 4;

    int bh = blockIdx.y, b = bh >> 2, h = bh & 3;
    int q0 = blockIdx.x * 128, base = b * SEQ;
    int hoff2 = h * 64;
    const unsigned* VtB = F.Vt + (size_t)bh * 128 * 512;

    // prologue: Q + K(0) + V(0)
    {
        #pragma unroll
        for (int i = 0; i < 8; i++) {
            int seg = tid + 256 * i;
            int r = seg >> 4, sg = seg & 15;
            CP16(sb + (SQ_O + r * 68 + sg * 4) * 4,
                 F.Qm + (size_t)(base + q0 + r) * qld2 + hoff2 + sg * 4);
        }
        #pragma unroll
        for (int i = 0; i < 4; i++) {
            int seg = tid + 256 * i;
            int r = seg >> 4, sg = seg & 15;
            CP16(sb + (SK_O + r * 68 + sg * 4) * 4,
                 F.Km + (size_t)(base + r) * kvld2 + hoff2 + sg * 4);
        }
        #pragma unroll
        for (int i = 0; i < 4; i++) {
            int seg = tid + 256 * i;
            int row = seg >> 3, sg = seg & 7;       // 128 rows x 8 segs
            CP16(sb + (SV_O + row * 36 + sg * 4) * 4,
                 VtB + (size_t)row * 512 + sg * 4);
        }
        CPCOMMIT();
    }

    float oacc[16][4];
    #pragma unroll
    for (int i = 0; i < 16; i++)
        #pragma unroll
        for (int c = 0; c < 4; c++) oacc[i][c] = 0.f;
    float mrow[2] = {-1e30f, -1e30f}, lrow[2] = {0.f, 0.f};

    const float scale = 0.08838834764831845f;

    for (int ch = 0; ch < NCH; ch++) {
        CPWAIT(0);
        __syncthreads();

        if (ch + 1 < NCH) {
            int nb2f = (ch + 1) & 1;
            #pragma unroll
            for (int i = 0; i < 4; i++) {
                int seg = tid + 256 * i;
                int r = seg >> 4, sg = seg & 15;
                CP16(sb + (SK_O + nb2f * 4352 + r * 68 + sg * 4) * 4,
                     F.Km + (size_t)(base + (ch + 1) * 64 + r) * kvld2 + hoff2 + sg * 4);
            }
            #pragma unroll
            for (int i = 0; i < 4; i++) {
                int seg = tid + 256 * i;
                int row = seg >> 3, sg = seg & 7;
                CP16(sb + (SV_O + nb2f * 4608 + row * 36 + sg * 4) * 4,
                     VtB + (size_t)row * 512 + (ch + 1) * 32 + sg * 4);
            }
            CPCOMMIT();
        }

        uint32_t ukb = sb + (SK_O + (ch & 1) * 4352) * 4;
        uint32_t uvb = sb + (SV_O + (ch & 1) * 4608) * 4;
        uint32_t uqb = sb + SQ_O * 4;

        // S = Q @ K^T : warp tile 16x64 (nb 0..7), 8 k16 steps, ldmatrix frags
        float s[8][4];
        #pragma unroll
        for (int i = 0; i < 8; i++)
            #pragma unroll
            for (int c = 0; c < 4; c++) s[i][c] = 0.f;

        #pragma unroll
        for (int ks = 0; ks < 8; ks++) {
            int kb = ks * 8;
            unsigned af[4];
            LDSM4(af[0], af[1], af[2], af[3],
                  uqb + ((m0 + lmA_row) * 68 + kb + lmA_koff) * 4);
            unsigned bf2[8][2];
            #pragma unroll
            for (int nbp = 0; nbp < 4; nbp++) {
                LDSM4(bf2[2*nbp][0], bf2[2*nbp][1],
                      bf2[2*nbp+1][0], bf2[2*nbp+1][1],
                      ukb + ((nbp * 16 + lmB_row) * 68 + kb + lmB_koff) * 4);
            }
            #pragma unroll
            for (int nb = 0; nb < 8; nb++)
                MMA_BF16(s[nb], af, bf2[nb]);
        }

        // register-only online softmax
        #pragma unroll
        for (int hf = 0; hf < 2; hf++) {
            float mx = -1e30f;
            #pragma unroll
            for (int nb = 0; nb < 8; nb++)
                mx = fmaxf(mx, fmaxf(s[nb][2*hf], s[nb][2*hf+1]));
            mx *= scale;
            mx = fmaxf(mx, __shfl_xor_sync(0xffffffffu, mx, 1));
            mx = fmaxf(mx, __shfl_xor_sync(0xffffffffu, mx, 2));
            float nm = fmaxf(mrow[hf], mx);
            float alpha = __expf(mrow[hf] - nm);
            mrow[hf] = nm;
            float sum = 0.f;
            #pragma unroll
            for (int nb = 0; nb < 8; nb++) {
                float p0 = __expf(s[nb][2*hf]   * scale - nm);
                float p1 = __expf(s[nb][2*hf+1] * scale - nm);
                s[nb][2*hf] = p0; s[nb][2*hf+1] = p1;
                sum += p0 + p1;
            }
            sum += __shfl_xor_sync(0xffffffffu, sum, 1);
            sum += __shfl_xor_sync(0xffffffffu, sum, 2);
            lrow[hf] = lrow[hf] * alpha + sum;
            #pragma unroll
            for (int nb2 = 0; nb2 < 16; nb2++) {
                oacc[nb2][2*hf]   *= alpha;
                oacc[nb2][2*hf+1] *= alpha;
            }
        }

        // O += P @ V : in-register P A-frags; V B-frags via ldmatrix on [d][kp]
        #pragma unroll
        for (int ks = 0; ks < 4; ks++) {
            unsigned ap[4];
            ap[0] = packbf(s[2*ks][0],   s[2*ks][1]);
            ap[1] = packbf(s[2*ks][2],   s[2*ks][3]);
            ap[2] = packbf(s[2*ks+1][0], s[2*ks+1][1]);
            ap[3] = packbf(s[2*ks+1][2], s[2*ks+1][3]);
            #pragma unroll
            for (int nbp = 0; nbp < 8; nbp++) {
                unsigned bv[2][2];
                LDSM4(bv[0][0], bv[0][1], bv[1][0], bv[1][1],
                      uvb + ((nbp * 16 + lmB_row) * 36 + ks * 8 + lmB_koff) * 4);
                MMA_BF16(oacc[2*nbp],   ap, bv[0]);
                MMA_BF16(oacc[2*nbp+1], ap, bv[1]);
            }
        }
    }

    // epilogue
    #pragma unroll
    for (int hf = 0; hf < 2; hf++) {
        float inv = 1.0f / lrow[hf];
        int gr = base + q0 + m0 + gid + hf * 8;
        #pragma unroll
        for (int nb2 = 0; nb2 < 16; nb2++) {
            F.Om[(size_t)gr * 256 + hoff2 + nb2 * 4 + tig] =
                packbf(oacc[nb2][2*hf] * inv, oacc[nb2][2*hf+1] * inv);
        }
    }
}

// ============================================================
// Host orchestration
// ============================================================
static inline void run_gemm2(GB g0, GB g1, int N0, int N1, int K, int act, int nz) {
    cudaFuncSetAttribute(gemm_bf, cudaFuncAttributeMaxDynamicSharedMemorySize, GM_SMEM);
    int nmax = N0 > N1 ? N0 : N1;
    dim3 grid(nmax / 128, NTOK / 128, nz);
    gemm_bf<<<grid, 256, GM_SMEM>>>(g0, g1, N0, N1, K, act);
}

static inline void run_flash2(FB f0, FB f1, int qld2, int kvld2, int nz) {
    cudaFuncSetAttribute(flash_bf, cudaFuncAttributeMaxDynamicSharedMemorySize, FL_SMEM_BYTES);
    dim3 grid(SEQ / 128, NBH, nz);
    flash_bf<<<grid, 256, FL_SMEM_BYTES>>>(f0, f1, qld2, kvld2);
}

extern "C" void kernel_launch(void* const* d_in, const int* in_sizes, int n_in,
                              void* d_out, int out_size) {
    const float* x1    = (const float*)d_in[0];
    const float* x2    = (const float*)d_in[1];
    const float* ln1_g = (const float*)d_in[2];
    const float* ln1_b = (const float*)d_in[3];
    const float* ln2_g = (const float*)d_in[4];
    const float* ln2_b = (const float*)d_in[5];
    const float* lnf_g = (const float*)d_in[6];
    const float* lnf_b = (const float*)d_in[7];
    const float* Wq1 = (const float*)d_in[8],  *bq1 = (const float*)d_in[9];
    const float* Wk1 = (const float*)d_in[10], *bk1 = (const float*)d_in[11];
    const float* Wv1 = (const float*)d_in[12], *bv1 = (const float*)d_in[13];
    const float* Wq2 = (const float*)d_in[14], *bq2 = (const float*)d_in[15];
    const float* Wk2 = (const float*)d_in[16], *bk2 = (const float*)d_in[17];
    const float* Wv2 = (const float*)d_in[18], *bv2 = (const float*)d_in[19];
    const float* Wq12 = (const float*)d_in[20], *bq12 = (const float*)d_in[21];
    const float* Wk12 = (const float*)d_in[22], *bk12 = (const float*)d_in[23];
    const float* Wv12 = (const float*)d_in[24], *bv12 = (const float*)d_in[25];
    const float* Wo  = (const float*)d_in[26], *bo = (const float*)d_in[27];
    const float* W1  = (const float*)d_in[28], *b1 = (const float*)d_in[29];
    const float* W2  = (const float*)d_in[30], *b2 = (const float*)d_in[31];
    float* out = (float*)d_out;

    unsigned *x1n, *x2n, *qv, *qkv1, *qkv2, *ctx1, *ctx2, *s1, *s2, *h1, *wb, *vt1, *vt2;
    float *xres, *bc;
    cudaGetSymbolAddress((void**)&x1n,  g_x1n);
    cudaGetSymbolAddress((void**)&x2n,  g_x2n);
    cudaGetSymbolAddress((void**)&qv,   g_qv);
    cudaGetSymbolAddress((void**)&qkv1, g_qkv1);
    cudaGetSymbolAddress((void**)&qkv2, g_qkv2);
    cudaGetSymbolAddress((void**)&ctx1, g_ctx1);
    cudaGetSymbolAddress((void**)&ctx2, g_ctx2);
    cudaGetSymbolAddress((void**)&s1,   g_s1);
    cudaGetSymbolAddress((void**)&s2,   g_s2);
    cudaGetSymbolAddress((void**)&h1,   g_h1);
    cudaGetSymbolAddress((void**)&wb,   g_wb);
    cudaGetSymbolAddress((void**)&vt1,  g_vt1);
    cudaGetSymbolAddress((void**)&vt2,  g_vt2);
    cudaGetSymbolAddress((void**)&xres, g_x);
    cudaGetSymbolAddress((void**)&bc,   g_bc);

    unsigned* wS1t  = wb;
    unsigned* wS2t  = wb + 393216;
    unsigned* wCQt  = wb + 786432;
    unsigned* wCKVt = wb + 917504;
    unsigned* wWot  = wb + 1179648;
    unsigned* wW1t  = wb + 1310720;
    unsigned* wW2t  = wb + 1572864;

    // 0) merged prep
    Prep p;
    p.ws[0] = Wq1;  p.wd[0] = wS1t;
    p.ws[1] = Wk1;  p.wd[1] = wS1t + 131072;
    p.ws[2] = Wv1;  p.wd[2] = wS1t + 262144;
    p.ws[3] = Wq2;  p.wd[3] = wS2t;
    p.ws[4] = Wk2;  p.wd[4] = wS2t + 131072;
    p.ws[5] = Wv2;  p.wd[5] = wS2t + 262144;
    p.ws[6] = Wq12; p.wd[6] = wCQt;
    p.ws[7] = Wk12; p.wd[7] = wCKVt;
    p.ws[8] = Wv12; p.wd[8] = wCKVt + 131072;
    p.ws[9] = Wo;   p.wd[9] = wWot;
    p.ws[10] = W1;  p.wd[10] = wW1t;
    p.ws[11] = W2;  p.wd[11] = wW2t;
    p.bs[0]=bq1; p.bs[1]=bk1; p.bs[2]=bv1; p.bs[3]=bq2;
    p.bs[4]=bk2; p.bs[5]=bv2; p.bs[6]=bk12; p.bs[7]=bv12;
    p.bdst = bc;
    prep_kernel<<<3586, dim3(32, 8)>>>(p);
    float* bS1 = bc, *bS2 = bc + 1536, *bCKV = bc + 3072;

    // 1) pre-LN, both streams
    ln_kernel<<<dim3(NTOK, 2), 256>>>(x1, ln1_g, ln1_b, x1n,
                                      x2, ln2_g, ln2_b, x2n);

    // 2+3) both self-attentions, z-batched; qkv gemm also emits Vt
    GB q0 = {x1n, wS1t, bS1, nullptr, nullptr, nullptr, qkv1, vt1, 1024};
    GB q1 = {x2n, wS2t, bS2, nullptr, nullptr, nullptr, qkv2, vt2, 1024};
    run_gemm2(q0, q1, 1536, 1536, 512, 0, 2);

    FB fa = {qkv1, qkv1 + 256, vt1, ctx1};
    FB fb = {qkv2, qkv2 + 256, vt2, ctx2};
    run_flash2(fa, fb, 768, 768, 2);

    GB w0 = {ctx1, wWot, bo, nullptr, x1n, nullptr, s1, nullptr, 0};
    GB w1 = {ctx2, wWot, bo, nullptr, x2n, nullptr, s2, nullptr, 0};
    run_gemm2(w0, w1, 512, 512, 512, 0, 2);

    // 4) cross-attention
    GB c0 = {s1, wCQt, bq12, nullptr, nullptr, nullptr, qv, nullptr, 0};
    GB c1 = {s2, wCKVt, bCKV, nullptr, nullptr, nullptr, qkv1, vt1, 512};
    run_gemm2(c0, c1, 512, 1024, 512, 0, 2);

    FB fc = {qv, qkv1, vt1, ctx1};
    run_flash2(fc, fc, 256, 512, 1);

    GB wc = {ctx1, wWot, bo, x1, nullptr, xres, nullptr, nullptr, 0};
    run_gemm2(wc, wc, 512, 512, 512, 0, 1);

    // 5) final LN + MLP
    ln_kernel<<<dim3(NTOK, 1), 256>>>(xres, lnf_g, lnf_b, x1n,
                                      xres, lnf_g, lnf_b, x1n);
    GB m1 = {x1n, wW1t, b1, nullptr, nullptr, nullptr, h1, nullptr, 0};
    run_gemm2(m1, m1, 1024, 1024, 512, 1, 1);
    GB m2 = {h1, wW2t, b2, xres, nullptr, out, nullptr, nullptr, 0};
    run_gemm2(m2, m2, 512, 512, 1024, 0, 1);
    (void)in_sizes; (void)n_in; (void)out_size;
}